// round 9
// baseline (speedup 1.0000x reference)
#include <cuda_runtime.h>
#include <cuda_bf16.h>
#include <math.h>
#include <cstdint>

// Problem constants
#define B_   4
#define T_   2048
#define NH   16
#define NKV  4
#define HD_  128
#define DQ   (NH * HD_)    // 2048
#define DKV  (NKV * HD_)   // 512
#define MROWS (B_ * T_)    // 8192

// ---------------------------------------------------------------------------
// Scratch (device globals; allocations banned)
// ---------------------------------------------------------------------------
__device__ float g_Q[(size_t)MROWS * DQ];    // fp32 Q projection
__device__ float g_K[(size_t)MROWS * DKV];   // fp32 K projection

__device__ __nv_bfloat16 g_xh[(size_t)MROWS * DQ];
__device__ __nv_bfloat16 g_xl[(size_t)MROWS * DQ];
__device__ __nv_bfloat16 g_yh[(size_t)MROWS * DQ];
__device__ __nv_bfloat16 g_yl[(size_t)MROWS * DQ];
__device__ __nv_bfloat16 g_wqh[(size_t)DQ * DQ];
__device__ __nv_bfloat16 g_wql[(size_t)DQ * DQ];
__device__ __nv_bfloat16 g_wkh[(size_t)DKV * DQ];
__device__ __nv_bfloat16 g_wkl[(size_t)DKV * DQ];
__device__ __nv_bfloat16 g_wvh[(size_t)DKV * DQ];
__device__ __nv_bfloat16 g_wvl[(size_t)DKV * DQ];
__device__ __nv_bfloat16 g_wph[(size_t)DQ * DQ];
__device__ __nv_bfloat16 g_wpl[(size_t)DQ * DQ];

// attention operands (hi/lo bf16)
__device__ __nv_bfloat16 g_aqh[(size_t)MROWS * DQ];
__device__ __nv_bfloat16 g_aql[(size_t)MROWS * DQ];
__device__ __nv_bfloat16 g_akh[(size_t)MROWS * DKV];
__device__ __nv_bfloat16 g_akl[(size_t)MROWS * DKV];
__device__ __nv_bfloat16 g_avh[(size_t)MROWS * DKV];
__device__ __nv_bfloat16 g_avl[(size_t)MROWS * DKV];

// ---------------------------------------------------------------------------
// Warp-level MMA helpers (sm_80+ PTX; safe for sm_103 base target)
// ---------------------------------------------------------------------------
__device__ __forceinline__ uint32_t smem_to_u32(const void* smem_ptr) {
    uint32_t addr;
    asm("{ .reg .u64 tmp; cvta.to.shared.u64 tmp, %1; cvt.u32.u64 %0, tmp; }"
        : "=r"(addr) : "l"(smem_ptr));
    return addr;
}

__device__ __forceinline__ void ldsm_x4(uint32_t* r, uint32_t addr) {
    asm volatile("ldmatrix.sync.aligned.m8n8.x4.shared.b16 {%0,%1,%2,%3}, [%4];"
        : "=r"(r[0]), "=r"(r[1]), "=r"(r[2]), "=r"(r[3]) : "r"(addr));
}

__device__ __forceinline__ void ldsm_x4_t(uint32_t* r, uint32_t addr) {
    asm volatile("ldmatrix.sync.aligned.m8n8.x4.trans.shared.b16 {%0,%1,%2,%3}, [%4];"
        : "=r"(r[0]), "=r"(r[1]), "=r"(r[2]), "=r"(r[3]) : "r"(addr));
}

__device__ __forceinline__ void mma_bf16(float* d, const uint32_t* a, const uint32_t* b) {
    asm volatile(
        "mma.sync.aligned.m16n8k16.row.col.f32.bf16.bf16.f32 "
        "{%0,%1,%2,%3}, {%4,%5,%6,%7}, {%8,%9}, {%0,%1,%2,%3};"
        : "+f"(d[0]), "+f"(d[1]), "+f"(d[2]), "+f"(d[3])
        : "r"(a[0]), "r"(a[1]), "r"(a[2]), "r"(a[3]), "r"(b[0]), "r"(b[1]));
}

__device__ __forceinline__ void cp_async16(uint32_t dst, const void* src) {
    asm volatile("cp.async.cg.shared.global [%0], [%1], 16;"
                 :: "r"(dst), "l"(src) : "memory");
}

// split x,y into packed bf16 hi + lo pairs
__device__ __forceinline__ void split_pack(float x, float y, uint32_t& hi, uint32_t& lo) {
    __nv_bfloat16 hx = __float2bfloat16(x);
    __nv_bfloat16 hy = __float2bfloat16(y);
    __nv_bfloat16 lx = __float2bfloat16(x - __bfloat162float(hx));
    __nv_bfloat16 ly = __float2bfloat16(y - __bfloat162float(hy));
    __nv_bfloat162 h2 = __halves2bfloat162(hx, hy);
    __nv_bfloat162 l2 = __halves2bfloat162(lx, ly);
    hi = *(uint32_t*)&h2; lo = *(uint32_t*)&l2;
}

// ---------------------------------------------------------------------------
// fp32 -> bf16 hi/lo split
// ---------------------------------------------------------------------------
__global__ void __launch_bounds__(256) cvt_hilo_kernel(
    const float* __restrict__ x,
    __nv_bfloat16* __restrict__ hi, __nv_bfloat16* __restrict__ lo, int n4)
{
    int i = blockIdx.x * 256 + threadIdx.x;
    if (i >= n4) return;
    float4 v = ((const float4*)x)[i];
    __nv_bfloat16 h[4], l[4];
    h[0] = __float2bfloat16(v.x); l[0] = __float2bfloat16(v.x - __bfloat162float(h[0]));
    h[1] = __float2bfloat16(v.y); l[1] = __float2bfloat16(v.y - __bfloat162float(h[1]));
    h[2] = __float2bfloat16(v.z); l[2] = __float2bfloat16(v.z - __bfloat162float(h[2]));
    h[3] = __float2bfloat16(v.w); l[3] = __float2bfloat16(v.w - __bfloat162float(h[3]));
    *(uint2*)(hi + 4 * (size_t)i) = *(uint2*)h;
    *(uint2*)(lo + 4 * (size_t)i) = *(uint2*)l;
}

// ---------------------------------------------------------------------------
// HMMA 3xBF16 GEMM (NT): C[M,N] = A[M,K] * B[N,K]^T, fp32 accumulate.
// BM=128, BN=128, BK=64. 8 warps (2x4). 3-stage cp.async pipeline, one
// __syncthreads per chunk. OUT_MODE 0: fp32 C; OUT_MODE 1: bf16 hi/lo.
// ---------------------------------------------------------------------------
#define GTILE_BYTES  16384
#define GSTAGE_BYTES (4 * GTILE_BYTES)      // 65536
#define GSMEM_SIZE   (3 * GSTAGE_BYTES)     // 196608

template<int OUT_MODE>
__global__ void __launch_bounds__(256, 1)
gemm_mma3_kernel(const __nv_bfloat16* __restrict__ Ah,
                 const __nv_bfloat16* __restrict__ Al,
                 const __nv_bfloat16* __restrict__ Bh,
                 const __nv_bfloat16* __restrict__ Bl,
                 float* __restrict__ C,
                 __nv_bfloat16* __restrict__ Ch, __nv_bfloat16* __restrict__ Cl,
                 int M, int N, int Kd)
{
    extern __shared__ char smem[];
    const uint32_t sbase = smem_to_u32(smem);
    const int tid = threadIdx.x;
    const int wid = tid >> 5, lane = tid & 31;
    const int wm = wid >> 2, wn = wid & 3;
    const int m0 = blockIdx.y * 128, n0 = blockIdx.x * 128;
    const int nchunk = Kd >> 6;

    const char* gsrc[16];
    uint32_t    soff[16];
#pragma unroll
    for (int i = 0; i < 16; ++i) {
        int gid  = tid + i * 256;
        int tile = gid >> 10;
        int rem  = gid & 1023;
        int row  = rem >> 3;
        int seg  = rem & 7;
        uint32_t off = (uint32_t)(row * 128 + seg * 16);
        soff[i] = (uint32_t)tile * GTILE_BYTES + (off ^ ((off >> 3) & 0x70));
        const char* base =
            (tile == 0) ? (const char*)Ah :
            (tile == 1) ? (const char*)Al :
            (tile == 2) ? (const char*)Bh : (const char*)Bl;
        int r0 = (tile < 2) ? m0 : n0;
        gsrc[i] = base + ((size_t)(r0 + row) * Kd + (size_t)seg * 8) * 2;
    }

    // Prologue: chunks 0 and 1 into stages 0, 1
#pragma unroll
    for (int i = 0; i < 16; ++i) cp_async16(sbase + soff[i], gsrc[i]);
    asm volatile("cp.async.commit_group;" ::: "memory");
#pragma unroll
    for (int i = 0; i < 16; ++i)
        cp_async16(sbase + GSTAGE_BYTES + soff[i], gsrc[i] + 128);
    asm volatile("cp.async.commit_group;" ::: "memory");

    const int a_row_l = (lane & 15);
    const uint32_t a_cb = (uint32_t)((lane >> 4) * 16);
    const int b_row_l = ((lane >> 4) << 3) + (lane & 7);
    const uint32_t b_cb = (uint32_t)(((lane >> 3) & 1) * 16);

    uint32_t aRow[4], aXor[4];
#pragma unroll
    for (int mi = 0; mi < 4; ++mi) {
        int r = wm * 64 + mi * 16 + a_row_l;
        aRow[mi] = (uint32_t)(r * 128);
        aXor[mi] = (uint32_t)((r << 4) & 0x70);
    }
    uint32_t bRow[2], bXor[2];
#pragma unroll
    for (int p = 0; p < 2; ++p) {
        int r = wn * 32 + p * 16 + b_row_l;
        bRow[p] = (uint32_t)(r * 128);
        bXor[p] = (uint32_t)((r << 4) & 0x70);
    }

    float acc[4][4][4];
#pragma unroll
    for (int mi = 0; mi < 4; ++mi)
#pragma unroll
        for (int ni = 0; ni < 4; ++ni)
#pragma unroll
            for (int q = 0; q < 4; ++q) acc[mi][ni][q] = 0.0f;

    int sidx = 0;                 // stage of chunk c
    for (int c = 0; c < nchunk; ++c) {
        if (c + 1 < nchunk) {
            asm volatile("cp.async.wait_group 1;" ::: "memory");
        } else {
            asm volatile("cp.async.wait_group 0;" ::: "memory");
        }
        __syncthreads();

        if (c + 2 < nchunk) {
            int pidx = sidx + 2; if (pidx >= 3) pidx -= 3;
            const uint32_t stn = sbase + (uint32_t)pidx * GSTAGE_BYTES;
            const size_t kb = (size_t)(c + 2) * 128;
#pragma unroll
            for (int i = 0; i < 16; ++i) cp_async16(stn + soff[i], gsrc[i] + kb);
            asm volatile("cp.async.commit_group;" ::: "memory");
        }

        const uint32_t st = sbase + (uint32_t)sidx * GSTAGE_BYTES;
#pragma unroll
        for (int ks = 0; ks < 4; ++ks) {
            const uint32_t kcb = (uint32_t)(ks * 32);
            uint32_t ah[4][4], al[4][4], bh[2][4], bl[2][4];
#pragma unroll
            for (int mi = 0; mi < 4; ++mi) {
                uint32_t col = (kcb + a_cb);
                uint32_t addr = st + aRow[mi] + (col ^ aXor[mi]);
                ldsm_x4(ah[mi], addr);
                ldsm_x4(al[mi], addr + GTILE_BYTES);
            }
#pragma unroll
            for (int p = 0; p < 2; ++p) {
                uint32_t col = (kcb + b_cb);
                uint32_t addr = st + 2 * GTILE_BYTES + bRow[p] + (col ^ bXor[p]);
                ldsm_x4(bh[p], addr);
                ldsm_x4(bl[p], addr + GTILE_BYTES);
            }
#pragma unroll
            for (int mi = 0; mi < 4; ++mi)
#pragma unroll
                for (int ni = 0; ni < 4; ++ni) {
                    const uint32_t* bhf = &bh[ni >> 1][(ni & 1) * 2];
                    const uint32_t* blf = &bl[ni >> 1][(ni & 1) * 2];
                    mma_bf16(acc[mi][ni], ah[mi], bhf);
                    mma_bf16(acc[mi][ni], ah[mi], blf);
                    mma_bf16(acc[mi][ni], al[mi], bhf);
                }
        }
        if (++sidx == 3) sidx = 0;
    }

#pragma unroll
    for (int mi = 0; mi < 4; ++mi) {
        const int gm = m0 + wm * 64 + mi * 16 + (lane >> 2);
#pragma unroll
        for (int ni = 0; ni < 4; ++ni) {
            const int gn = n0 + wn * 32 + ni * 8 + (lane & 3) * 2;
            if (OUT_MODE == 0) {
                float2 v0 = make_float2(acc[mi][ni][0], acc[mi][ni][1]);
                float2 v1 = make_float2(acc[mi][ni][2], acc[mi][ni][3]);
                *(float2*)(C + (size_t)gm * N + gn) = v0;
                *(float2*)(C + (size_t)(gm + 8) * N + gn) = v1;
            } else {
                uint32_t hi, lo;
                split_pack(acc[mi][ni][0], acc[mi][ni][1], hi, lo);
                *(uint32_t*)(Ch + (size_t)gm * N + gn) = hi;
                *(uint32_t*)(Cl + (size_t)gm * N + gn) = lo;
                split_pack(acc[mi][ni][2], acc[mi][ni][3], hi, lo);
                *(uint32_t*)(Ch + (size_t)(gm + 8) * N + gn) = hi;
                *(uint32_t*)(Cl + (size_t)(gm + 8) * N + gn) = lo;
            }
        }
    }
}

// ---------------------------------------------------------------------------
// Fused QK RMSNorm + RoPE (+gain) -> bf16 hi/lo outputs.
// ---------------------------------------------------------------------------
__global__ void __launch_bounds__(256) rms_rope_split_kernel(
    const float* __restrict__ X, int nheads, const float* __restrict__ gain,
    __nv_bfloat16* __restrict__ H, __nv_bfloat16* __restrict__ L)
{
    const int wid = threadIdx.x >> 5, lane = threadIdx.x & 31;
    const long long gid = (long long)blockIdx.x * 8 + wid;
    const int h = (int)(gid % nheads);
    const long long bt = gid / nheads;
    const int t = (int)(bt % T_);

    const long long base = bt * (long long)(nheads * HD_) + (long long)h * HD_;
    const float* p = X + base;
    float x0 = p[lane], x1 = p[lane + 32], x2 = p[lane + 64], x3 = p[lane + 96];

    float ss = x0 * x0 + x1 * x1 + x2 * x2 + x3 * x3;
#pragma unroll
    for (int o = 16; o; o >>= 1) ss += __shfl_xor_sync(0xffffffffu, ss, o);
    const float r = rsqrtf(ss * (1.0f / 128.0f) + 1.1920928955078125e-07f);
    x0 *= r; x1 *= r; x2 *= r; x3 *= r;

    const float Lc = 13.287712379549449f / 64.0f;
    const float tf = (float)t;
    const float a0 = tf * exp2f(-(float)lane * Lc);
    const float a1 = tf * exp2f(-(float)(lane + 32) * Lc);
    const float c0 = cosf(a0), s0 = sinf(a0);
    const float c1 = cosf(a1), s1 = sinf(a1);
    const float g = gain ? gain[h] : 1.0f;

    float y0 = (x0 * c0 - x2 * s0) * g;
    float y2 = (x2 * c0 + x0 * s0) * g;
    float y1 = (x1 * c1 - x3 * s1) * g;
    float y3 = (x3 * c1 + x1 * s1) * g;

    __nv_bfloat16 h0 = __float2bfloat16(y0), h1 = __float2bfloat16(y1);
    __nv_bfloat16 h2 = __float2bfloat16(y2), h3 = __float2bfloat16(y3);
    H[base + lane]      = h0;  L[base + lane]      = __float2bfloat16(y0 - __bfloat162float(h0));
    H[base + lane + 32] = h1;  L[base + lane + 32] = __float2bfloat16(y1 - __bfloat162float(h1));
    H[base + lane + 64] = h2;  L[base + lane + 64] = __float2bfloat16(y2 - __bfloat162float(h2));
    H[base + lane + 96] = h3;  L[base + lane + 96] = __float2bfloat16(y3 - __bfloat162float(h3));
}

// ---------------------------------------------------------------------------
// Flash attention, HMMA 3xBF16, causal, GQA group=4.
// Br=128, Bc=64, 8 warps. 3-stage KV cp.async pipeline; Q staged through
// stage 0 then held in registers. smem = 3 x 64KB stages.
// Stage layout: Kh,Kl,Vh,Vl each 16KB; each tensor: 2 panels x (64 rows x 128B).
// ---------------------------------------------------------------------------
#define FA_STSZ 65536u
#define FA_SMEM (3 * 65536)   // 196608

__global__ void __launch_bounds__(256, 1) flash_attn_mma_kernel(
    const __nv_bfloat16* __restrict__ Qh, const __nv_bfloat16* __restrict__ Ql,
    const __nv_bfloat16* __restrict__ Kh, const __nv_bfloat16* __restrict__ Kl,
    const __nv_bfloat16* __restrict__ Vh, const __nv_bfloat16* __restrict__ Vl,
    __nv_bfloat16* __restrict__ Yh, __nv_bfloat16* __restrict__ Yl)
{
    extern __shared__ char smem[];
    const uint32_t sb = smem_to_u32(smem);
    const int qt = blockIdx.x, h = blockIdx.y, b = blockIdx.z;
    const int kvh = h >> 2;
    const int tid = threadIdx.x, wid = tid >> 5, lane = tid & 31;

    // ---- Q tile via stage 0 (Qh at +0, Ql at +32768), 16 x 16B per thread ----
#pragma unroll
    for (int i = 0; i < 16; ++i) {
        int gid = tid + i * 256;           // 0..4095
        int tensor = gid >> 11;            // 0:Qh 1:Ql
        int rem = gid & 2047;
        int row = rem >> 4;                // 0..127
        int seg = rem & 15;                // 16B seg within 256B row
        int panel = seg >> 3, segp = seg & 7;
        uint32_t off = (uint32_t)(row * 128 + segp * 16);
        uint32_t dst = sb + (uint32_t)tensor * 32768u + (uint32_t)panel * 16384u
                     + (off ^ ((off >> 3) & 0x70));
        const __nv_bfloat16* g = (tensor ? Ql : Qh)
            + ((size_t)(b * T_ + qt * 128 + row) * DQ + h * HD_ + seg * 8);
        cp_async16(dst, g);
    }
    asm volatile("cp.async.commit_group;" ::: "memory");
    asm volatile("cp.async.wait_group 0;" ::: "memory");
    __syncthreads();

    // lane addressing constants
    const int a_row_l = lane & 15;
    const uint32_t a_cb = (uint32_t)((lane >> 4) * 16);
    const int b_row_l = ((lane >> 4) << 3) + (lane & 7);
    const uint32_t b_cb = (uint32_t)(((lane >> 3) & 1) * 16);
    const int v_row_l = lane & 15;
    const uint32_t v_cb = (uint32_t)((lane >> 4) * 16);

    // ---- extract Q fragments (A operand) for 8 k-steps, hi+lo ----
    uint32_t qhf[8][4], qlf[8][4];
    {
        const int arow = wid * 16 + a_row_l;
        const uint32_t axor = (uint32_t)((arow << 4) & 0x70);
        const uint32_t abase = sb + (uint32_t)(arow * 128);
#pragma unroll
        for (int ks = 0; ks < 8; ++ks) {
            uint32_t colb = (uint32_t)((ks & 3) * 32) + a_cb;
            uint32_t ad = abase + (uint32_t)(ks >> 2) * 16384u + (colb ^ axor);
            ldsm_x4(qhf[ks], ad);
            ldsm_x4(qlf[ks], ad + 32768u);
        }
    }
    __syncthreads();   // everyone done reading Q from stage 0

    // ---- KV stage loader ----
    auto issue_kv = [&](int kt, uint32_t stagebase) {
#pragma unroll
        for (int i = 0; i < 16; ++i) {
            int gid = tid + i * 256;           // 0..4095
            int tensor = gid >> 10;            // 0:Kh 1:Kl 2:Vh 3:Vl
            int rem = gid & 1023;
            int row = rem >> 4;                // 0..63
            int seg = rem & 15;
            int panel = seg >> 3, segp = seg & 7;
            uint32_t off = (uint32_t)(row * 128 + segp * 16);
            uint32_t dst = stagebase + (uint32_t)tensor * 16384u + (uint32_t)panel * 8192u
                         + (off ^ ((off >> 3) & 0x70));
            const __nv_bfloat16* base =
                (tensor == 0) ? Kh : (tensor == 1) ? Kl : (tensor == 2) ? Vh : Vl;
            const __nv_bfloat16* g = base
                + ((size_t)(b * T_ + kt * 64 + row) * DKV + kvh * HD_ + seg * 8);
            cp_async16(dst, g);
        }
        asm volatile("cp.async.commit_group;" ::: "memory");
    };

    const int ktmax = 2 * qt + 1;
    issue_kv(0, sb);
    issue_kv(1, sb + FA_STSZ);

    float m0 = -1e30f, m1 = -1e30f, l0 = 0.0f, l1 = 0.0f;
    float O[16][4];
#pragma unroll
    for (int nt = 0; nt < 16; ++nt)
#pragma unroll
        for (int q = 0; q < 4; ++q) O[nt][q] = 0.0f;

    const int r0g = qt * 128 + wid * 16 + (lane >> 2);
    const float scale = 0.08838834764831845f;

    int sidx = 0;
    for (int kt = 0; kt <= ktmax; ++kt) {
        if (kt + 1 <= ktmax) {
            asm volatile("cp.async.wait_group 1;" ::: "memory");
        } else {
            asm volatile("cp.async.wait_group 0;" ::: "memory");
        }
        __syncthreads();

        if (kt + 2 <= ktmax) {
            int pidx = sidx + 2; if (pidx >= 3) pidx -= 3;
            issue_kv(kt + 2, sb + (uint32_t)pidx * FA_STSZ);
        }

        const uint32_t stg = sb + (uint32_t)sidx * FA_STSZ;

        // ---- S = Q K^T (3 terms) ----
        float sacc[8][4];
#pragma unroll
        for (int nt = 0; nt < 8; ++nt)
#pragma unroll
            for (int q = 0; q < 4; ++q) sacc[nt][q] = 0.0f;

#pragma unroll
        for (int ks = 0; ks < 8; ++ks) {
            const uint32_t pbase = stg + (uint32_t)(ks >> 2) * 8192u;
            const uint32_t colb = (uint32_t)((ks & 3) * 32) + b_cb;
#pragma unroll
            for (int p = 0; p < 4; ++p) {
                const int row = p * 16 + b_row_l;
                const uint32_t ad = pbase + (uint32_t)(row * 128)
                                  + (colb ^ (uint32_t)((row << 4) & 0x70));
                uint32_t kh4[4], kl4[4];
                ldsm_x4(kh4, ad);
                ldsm_x4(kl4, ad + 16384u);
                mma_bf16(sacc[2 * p],     qhf[ks], kh4);
                mma_bf16(sacc[2 * p],     qhf[ks], kl4);
                mma_bf16(sacc[2 * p],     qlf[ks], kh4);
                mma_bf16(sacc[2 * p + 1], qhf[ks], kh4 + 2);
                mma_bf16(sacc[2 * p + 1], qhf[ks], kl4 + 2);
                mma_bf16(sacc[2 * p + 1], qlf[ks], kh4 + 2);
            }
        }

        // ---- scale + causal mask ----
        const int cbase = kt * 64 + (lane & 3) * 2;
        const bool need_mask = (kt >= 2 * qt);
#pragma unroll
        for (int nt = 0; nt < 8; ++nt) {
#pragma unroll
            for (int c = 0; c < 2; ++c) {
                const int col = cbase + nt * 8 + c;
                float v0 = sacc[nt][c] * scale;
                float v1 = sacc[nt][2 + c] * scale;
                if (need_mask) {
                    if (col > r0g)     v0 = -1e30f;
                    if (col > r0g + 8) v1 = -1e30f;
                }
                sacc[nt][c] = v0;
                sacc[nt][2 + c] = v1;
            }
        }

        // ---- online softmax ----
        float mx0 = -1e30f, mx1 = -1e30f;
#pragma unroll
        for (int nt = 0; nt < 8; ++nt) {
            mx0 = fmaxf(mx0, fmaxf(sacc[nt][0], sacc[nt][1]));
            mx1 = fmaxf(mx1, fmaxf(sacc[nt][2], sacc[nt][3]));
        }
        mx0 = fmaxf(mx0, __shfl_xor_sync(0xffffffffu, mx0, 1));
        mx0 = fmaxf(mx0, __shfl_xor_sync(0xffffffffu, mx0, 2));
        mx1 = fmaxf(mx1, __shfl_xor_sync(0xffffffffu, mx1, 1));
        mx1 = fmaxf(mx1, __shfl_xor_sync(0xffffffffu, mx1, 2));
        const float mn0 = fmaxf(m0, mx0), mn1 = fmaxf(m1, mx1);
        const float al0 = __expf(m0 - mn0), al1 = __expf(m1 - mn1);
        m0 = mn0; m1 = mn1;

        float rs0 = 0.0f, rs1 = 0.0f;
#pragma unroll
        for (int nt = 0; nt < 8; ++nt) {
            float p0 = __expf(sacc[nt][0] - mn0);
            float p1 = __expf(sacc[nt][1] - mn0);
            float p2 = __expf(sacc[nt][2] - mn1);
            float p3 = __expf(sacc[nt][3] - mn1);
            sacc[nt][0] = p0; sacc[nt][1] = p1; sacc[nt][2] = p2; sacc[nt][3] = p3;
            rs0 += p0 + p1; rs1 += p2 + p3;
        }
        rs0 += __shfl_xor_sync(0xffffffffu, rs0, 1);
        rs0 += __shfl_xor_sync(0xffffffffu, rs0, 2);
        rs1 += __shfl_xor_sync(0xffffffffu, rs1, 1);
        rs1 += __shfl_xor_sync(0xffffffffu, rs1, 2);
        l0 = l0 * al0 + rs0;
        l1 = l1 * al1 + rs1;

#pragma unroll
        for (int nt = 0; nt < 16; ++nt) {
            O[nt][0] *= al0; O[nt][1] *= al0;
            O[nt][2] *= al1; O[nt][3] *= al1;
        }

        // ---- P fragments (hi/lo bf16), A-operand layout ----
        uint32_t pah[4][4], pal[4][4];
#pragma unroll
        for (int kk = 0; kk < 4; ++kk) {
            const int t0 = 2 * kk, t1 = 2 * kk + 1;
            split_pack(sacc[t0][0], sacc[t0][1], pah[kk][0], pal[kk][0]);
            split_pack(sacc[t0][2], sacc[t0][3], pah[kk][1], pal[kk][1]);
            split_pack(sacc[t1][0], sacc[t1][1], pah[kk][2], pal[kk][2]);
            split_pack(sacc[t1][2], sacc[t1][3], pah[kk][3], pal[kk][3]);
        }

        // ---- O += P V (3 terms) ----
#pragma unroll
        for (int kk = 0; kk < 4; ++kk) {
            const int rowl = kk * 16 + v_row_l;
            const uint32_t rbase = stg + 32768u + (uint32_t)(rowl * 128);
            const uint32_t rxor = (uint32_t)((rowl << 4) & 0x70);
#pragma unroll
            for (int j = 0; j < 8; ++j) {
                const uint32_t colb = (uint32_t)((j & 3) * 32) + v_cb;
                const uint32_t ad = rbase + (uint32_t)(j >> 2) * 8192u + (colb ^ rxor);
                uint32_t vh4[4], vl4[4];
                ldsm_x4_t(vh4, ad);
                ldsm_x4_t(vl4, ad + 16384u);
                mma_bf16(O[2 * j],     pah[kk], vh4);
                mma_bf16(O[2 * j],     pah[kk], vl4);
                mma_bf16(O[2 * j],     pal[kk], vh4);
                mma_bf16(O[2 * j + 1], pah[kk], vh4 + 2);
                mma_bf16(O[2 * j + 1], pah[kk], vl4 + 2);
                mma_bf16(O[2 * j + 1], pal[kk], vh4 + 2);
            }
        }
        if (++sidx == 3) sidx = 0;
    }

    // ---- epilogue: normalize, split hi/lo, write bf16 ----
    const float inv0 = 1.0f / l0, inv1 = 1.0f / l1;
    const size_t tok0 = (size_t)(b * T_ + qt * 128 + wid * 16 + (lane >> 2));
    const int colb = h * HD_ + (lane & 3) * 2;
#pragma unroll
    for (int nt = 0; nt < 16; ++nt) {
        uint32_t hi, lo;
        const size_t idx0 = tok0 * DQ + colb + nt * 8;
        split_pack(O[nt][0] * inv0, O[nt][1] * inv0, hi, lo);
        *(uint32_t*)(Yh + idx0) = hi;
        *(uint32_t*)(Yl + idx0) = lo;
        const size_t idx1 = idx0 + (size_t)8 * DQ;
        split_pack(O[nt][2] * inv1, O[nt][3] * inv1, hi, lo);
        *(uint32_t*)(Yh + idx1) = hi;
        *(uint32_t*)(Yl + idx1) = lo;
    }
}

// ---------------------------------------------------------------------------
// Launch
// ---------------------------------------------------------------------------
extern "C" void kernel_launch(void* const* d_in, const int* in_sizes, int n_in,
                              void* d_out, int out_size)
{
    const float* x     = (const float*)d_in[0];
    const float* Wq    = (const float*)d_in[1];
    const float* Wk    = (const float*)d_in[2];
    const float* Wv    = (const float*)d_in[3];
    const float* Wproj = (const float*)d_in[4];
    const float* qgain = (const float*)d_in[5];
    float* out = (float*)d_out;

    float *Qb, *Kb;
    cudaGetSymbolAddress((void**)&Qb, g_Q);
    cudaGetSymbolAddress((void**)&Kb, g_K);
    __nv_bfloat16 *xh, *xl, *yh, *yl, *wqh, *wql, *wkh, *wkl, *wvh, *wvl, *wph, *wpl;
    __nv_bfloat16 *aqh, *aql, *akh, *akl, *avh, *avl;
    cudaGetSymbolAddress((void**)&xh,  g_xh);
    cudaGetSymbolAddress((void**)&xl,  g_xl);
    cudaGetSymbolAddress((void**)&yh,  g_yh);
    cudaGetSymbolAddress((void**)&yl,  g_yl);
    cudaGetSymbolAddress((void**)&wqh, g_wqh);
    cudaGetSymbolAddress((void**)&wql, g_wql);
    cudaGetSymbolAddress((void**)&wkh, g_wkh);
    cudaGetSymbolAddress((void**)&wkl, g_wkl);
    cudaGetSymbolAddress((void**)&wvh, g_wvh);
    cudaGetSymbolAddress((void**)&wvl, g_wvl);
    cudaGetSymbolAddress((void**)&wph, g_wph);
    cudaGetSymbolAddress((void**)&wpl, g_wpl);
    cudaGetSymbolAddress((void**)&aqh, g_aqh);
    cudaGetSymbolAddress((void**)&aql, g_aql);
    cudaGetSymbolAddress((void**)&akh, g_akh);
    cudaGetSymbolAddress((void**)&akl, g_akl);
    cudaGetSymbolAddress((void**)&avh, g_avh);
    cudaGetSymbolAddress((void**)&avl, g_avl);

    cudaFuncSetAttribute(gemm_mma3_kernel<0>,
                         cudaFuncAttributeMaxDynamicSharedMemorySize, GSMEM_SIZE);
    cudaFuncSetAttribute(gemm_mma3_kernel<1>,
                         cudaFuncAttributeMaxDynamicSharedMemorySize, GSMEM_SIZE);
    cudaFuncSetAttribute(flash_attn_mma_kernel,
                         cudaFuncAttributeMaxDynamicSharedMemorySize, FA_SMEM);

    // Convert inputs to bf16 hi/lo
    cvt_hilo_kernel<<<(MROWS * DQ / 4 + 255) / 256, 256>>>(x, xh, xl, MROWS * DQ / 4);
    cvt_hilo_kernel<<<(DQ * DQ / 4 + 255) / 256, 256>>>(Wq, wqh, wql, DQ * DQ / 4);
    cvt_hilo_kernel<<<(DKV * DQ / 4 + 255) / 256, 256>>>(Wk, wkh, wkl, DKV * DQ / 4);
    cvt_hilo_kernel<<<(DKV * DQ / 4 + 255) / 256, 256>>>(Wv, wvh, wvl, DKV * DQ / 4);
    cvt_hilo_kernel<<<(DQ * DQ / 4 + 255) / 256, 256>>>(Wproj, wph, wpl, DQ * DQ / 4);

    // QKV projections on HMMA tensor cores (3xBF16)
    gemm_mma3_kernel<0><<<dim3(DQ / 128,  MROWS / 128), 256, GSMEM_SIZE>>>(
        xh, xl, wqh, wql, Qb, nullptr, nullptr, MROWS, DQ, DQ);
    gemm_mma3_kernel<0><<<dim3(DKV / 128, MROWS / 128), 256, GSMEM_SIZE>>>(
        xh, xl, wkh, wkl, Kb, nullptr, nullptr, MROWS, DKV, DQ);
    // V projection writes bf16 hi/lo directly (no fp32 round-trip)
    gemm_mma3_kernel<1><<<dim3(DKV / 128, MROWS / 128), 256, GSMEM_SIZE>>>(
        xh, xl, wvh, wvl, nullptr, avh, avl, MROWS, DKV, DQ);

    // RMSNorm + RoPE (+gain on Q) -> bf16 hi/lo
    rms_rope_split_kernel<<<(MROWS * NH) / 8, 256>>>(Qb, NH, qgain, aqh, aql);
    rms_rope_split_kernel<<<(MROWS * NKV) / 8, 256>>>(Kb, NKV, nullptr, akh, akl);

    // Flash attention (HMMA 3xBF16) -> yh/yl bf16
    flash_attn_mma_kernel<<<dim3(T_ / 128, NH, B_), 256, FA_SMEM>>>(
        aqh, aql, akh, akl, avh, avl, yh, yl);

    // Output projection
    gemm_mma3_kernel<0><<<dim3(DQ / 128, MROWS / 128), 256, GSMEM_SIZE>>>(
        yh, yl, wph, wpl, out, nullptr, nullptr, MROWS, DQ, DQ);
}

// round 10
// speedup vs baseline: 1.0008x; 1.0008x over previous
#include <cuda_runtime.h>
#include <cuda_bf16.h>
#include <math.h>
#include <cstdint>

// Problem constants
#define B_   4
#define T_   2048
#define NH   16
#define NKV  4
#define HD_  128
#define DQ   (NH * HD_)    // 2048
#define DKV  (NKV * HD_)   // 512
#define MROWS (B_ * T_)    // 8192

// ---------------------------------------------------------------------------
// Scratch (device globals; allocations banned)
// ---------------------------------------------------------------------------
__device__ float g_Q[(size_t)MROWS * DQ];    // fp32 Q projection
__device__ float g_K[(size_t)MROWS * DKV];   // fp32 K projection

__device__ __nv_bfloat16 g_xh[(size_t)MROWS * DQ];
__device__ __nv_bfloat16 g_xl[(size_t)MROWS * DQ];
__device__ __nv_bfloat16 g_yh[(size_t)MROWS * DQ];
__device__ __nv_bfloat16 g_yl[(size_t)MROWS * DQ];
__device__ __nv_bfloat16 g_wqh[(size_t)DQ * DQ];
__device__ __nv_bfloat16 g_wql[(size_t)DQ * DQ];
__device__ __nv_bfloat16 g_wkh[(size_t)DKV * DQ];
__device__ __nv_bfloat16 g_wkl[(size_t)DKV * DQ];
__device__ __nv_bfloat16 g_wvh[(size_t)DKV * DQ];
__device__ __nv_bfloat16 g_wvl[(size_t)DKV * DQ];
__device__ __nv_bfloat16 g_wph[(size_t)DQ * DQ];
__device__ __nv_bfloat16 g_wpl[(size_t)DQ * DQ];

// attention operands (hi/lo bf16)
__device__ __nv_bfloat16 g_aqh[(size_t)MROWS * DQ];
__device__ __nv_bfloat16 g_aql[(size_t)MROWS * DQ];
__device__ __nv_bfloat16 g_akh[(size_t)MROWS * DKV];
__device__ __nv_bfloat16 g_akl[(size_t)MROWS * DKV];
__device__ __nv_bfloat16 g_avh[(size_t)MROWS * DKV];
__device__ __nv_bfloat16 g_avl[(size_t)MROWS * DKV];

// ---------------------------------------------------------------------------
// Warp-level MMA helpers (sm_80+ PTX; safe for sm_103 base target)
// ---------------------------------------------------------------------------
__device__ __forceinline__ uint32_t smem_to_u32(const void* smem_ptr) {
    uint32_t addr;
    asm("{ .reg .u64 tmp; cvta.to.shared.u64 tmp, %1; cvt.u32.u64 %0, tmp; }"
        : "=r"(addr) : "l"(smem_ptr));
    return addr;
}

__device__ __forceinline__ void ldsm_x4(uint32_t* r, uint32_t addr) {
    asm volatile("ldmatrix.sync.aligned.m8n8.x4.shared.b16 {%0,%1,%2,%3}, [%4];"
        : "=r"(r[0]), "=r"(r[1]), "=r"(r[2]), "=r"(r[3]) : "r"(addr));
}

__device__ __forceinline__ void ldsm_x4_t(uint32_t* r, uint32_t addr) {
    asm volatile("ldmatrix.sync.aligned.m8n8.x4.trans.shared.b16 {%0,%1,%2,%3}, [%4];"
        : "=r"(r[0]), "=r"(r[1]), "=r"(r[2]), "=r"(r[3]) : "r"(addr));
}

__device__ __forceinline__ void mma_bf16(float* d, const uint32_t* a, const uint32_t* b) {
    asm volatile(
        "mma.sync.aligned.m16n8k16.row.col.f32.bf16.bf16.f32 "
        "{%0,%1,%2,%3}, {%4,%5,%6,%7}, {%8,%9}, {%0,%1,%2,%3};"
        : "+f"(d[0]), "+f"(d[1]), "+f"(d[2]), "+f"(d[3])
        : "r"(a[0]), "r"(a[1]), "r"(a[2]), "r"(a[3]), "r"(b[0]), "r"(b[1]));
}

__device__ __forceinline__ void cp_async16(uint32_t dst, const void* src) {
    asm volatile("cp.async.cg.shared.global [%0], [%1], 16;"
                 :: "r"(dst), "l"(src) : "memory");
}

// split x,y into packed bf16 hi + lo pairs
__device__ __forceinline__ void split_pack(float x, float y, uint32_t& hi, uint32_t& lo) {
    __nv_bfloat16 hx = __float2bfloat16(x);
    __nv_bfloat16 hy = __float2bfloat16(y);
    __nv_bfloat16 lx = __float2bfloat16(x - __bfloat162float(hx));
    __nv_bfloat16 ly = __float2bfloat16(y - __bfloat162float(hy));
    __nv_bfloat162 h2 = __halves2bfloat162(hx, hy);
    __nv_bfloat162 l2 = __halves2bfloat162(lx, ly);
    hi = *(uint32_t*)&h2; lo = *(uint32_t*)&l2;
}

// ---------------------------------------------------------------------------
// fp32 -> bf16 hi/lo split
// ---------------------------------------------------------------------------
__global__ void __launch_bounds__(256) cvt_hilo_kernel(
    const float* __restrict__ x,
    __nv_bfloat16* __restrict__ hi, __nv_bfloat16* __restrict__ lo, int n4)
{
    int i = blockIdx.x * 256 + threadIdx.x;
    if (i >= n4) return;
    float4 v = ((const float4*)x)[i];
    __nv_bfloat16 h[4], l[4];
    h[0] = __float2bfloat16(v.x); l[0] = __float2bfloat16(v.x - __bfloat162float(h[0]));
    h[1] = __float2bfloat16(v.y); l[1] = __float2bfloat16(v.y - __bfloat162float(h[1]));
    h[2] = __float2bfloat16(v.z); l[2] = __float2bfloat16(v.z - __bfloat162float(h[2]));
    h[3] = __float2bfloat16(v.w); l[3] = __float2bfloat16(v.w - __bfloat162float(h[3]));
    *(uint2*)(hi + 4 * (size_t)i) = *(uint2*)h;
    *(uint2*)(lo + 4 * (size_t)i) = *(uint2*)l;
}

// ---------------------------------------------------------------------------
// HMMA 3xBF16 GEMM (NT): C[M,N] = A[M,K] * B[N,K]^T, fp32 accumulate.
// BM=128, BN=128, BK=64. 8 warps (2x4). 3-stage cp.async pipeline, one
// __syncthreads per chunk. OUT_MODE 0: fp32 C; OUT_MODE 1: bf16 hi/lo.
// ---------------------------------------------------------------------------
#define GTILE_BYTES  16384
#define GSTAGE_BYTES (4 * GTILE_BYTES)      // 65536
#define GSMEM_SIZE   (3 * GSTAGE_BYTES)     // 196608

template<int OUT_MODE>
__global__ void __launch_bounds__(256, 1)
gemm_mma3_kernel(const __nv_bfloat16* __restrict__ Ah,
                 const __nv_bfloat16* __restrict__ Al,
                 const __nv_bfloat16* __restrict__ Bh,
                 const __nv_bfloat16* __restrict__ Bl,
                 float* __restrict__ C,
                 __nv_bfloat16* __restrict__ Ch, __nv_bfloat16* __restrict__ Cl,
                 int M, int N, int Kd)
{
    extern __shared__ char smem[];
    const uint32_t sbase = smem_to_u32(smem);
    const int tid = threadIdx.x;
    const int wid = tid >> 5, lane = tid & 31;
    const int wm = wid >> 2, wn = wid & 3;
    const int m0 = blockIdx.y * 128, n0 = blockIdx.x * 128;
    const int nchunk = Kd >> 6;

    const char* gsrc[16];
    uint32_t    soff[16];
#pragma unroll
    for (int i = 0; i < 16; ++i) {
        int gid  = tid + i * 256;
        int tile = gid >> 10;
        int rem  = gid & 1023;
        int row  = rem >> 3;
        int seg  = rem & 7;
        uint32_t off = (uint32_t)(row * 128 + seg * 16);
        soff[i] = (uint32_t)tile * GTILE_BYTES + (off ^ ((off >> 3) & 0x70));
        const char* base =
            (tile == 0) ? (const char*)Ah :
            (tile == 1) ? (const char*)Al :
            (tile == 2) ? (const char*)Bh : (const char*)Bl;
        int r0 = (tile < 2) ? m0 : n0;
        gsrc[i] = base + ((size_t)(r0 + row) * Kd + (size_t)seg * 8) * 2;
    }

    // Prologue: chunks 0 and 1 into stages 0, 1
#pragma unroll
    for (int i = 0; i < 16; ++i) cp_async16(sbase + soff[i], gsrc[i]);
    asm volatile("cp.async.commit_group;" ::: "memory");
#pragma unroll
    for (int i = 0; i < 16; ++i)
        cp_async16(sbase + GSTAGE_BYTES + soff[i], gsrc[i] + 128);
    asm volatile("cp.async.commit_group;" ::: "memory");

    const int a_row_l = (lane & 15);
    const uint32_t a_cb = (uint32_t)((lane >> 4) * 16);
    const int b_row_l = ((lane >> 4) << 3) + (lane & 7);
    const uint32_t b_cb = (uint32_t)(((lane >> 3) & 1) * 16);

    uint32_t aRow[4], aXor[4];
#pragma unroll
    for (int mi = 0; mi < 4; ++mi) {
        int r = wm * 64 + mi * 16 + a_row_l;
        aRow[mi] = (uint32_t)(r * 128);
        aXor[mi] = (uint32_t)((r << 4) & 0x70);
    }
    uint32_t bRow[2], bXor[2];
#pragma unroll
    for (int p = 0; p < 2; ++p) {
        int r = wn * 32 + p * 16 + b_row_l;
        bRow[p] = (uint32_t)(r * 128);
        bXor[p] = (uint32_t)((r << 4) & 0x70);
    }

    float acc[4][4][4];
#pragma unroll
    for (int mi = 0; mi < 4; ++mi)
#pragma unroll
        for (int ni = 0; ni < 4; ++ni)
#pragma unroll
            for (int q = 0; q < 4; ++q) acc[mi][ni][q] = 0.0f;

    int sidx = 0;                 // stage of chunk c
    for (int c = 0; c < nchunk; ++c) {
        if (c + 1 < nchunk) {
            asm volatile("cp.async.wait_group 1;" ::: "memory");
        } else {
            asm volatile("cp.async.wait_group 0;" ::: "memory");
        }
        __syncthreads();

        if (c + 2 < nchunk) {
            int pidx = sidx + 2; if (pidx >= 3) pidx -= 3;
            const uint32_t stn = sbase + (uint32_t)pidx * GSTAGE_BYTES;
            const size_t kb = (size_t)(c + 2) * 128;
#pragma unroll
            for (int i = 0; i < 16; ++i) cp_async16(stn + soff[i], gsrc[i] + kb);
            asm volatile("cp.async.commit_group;" ::: "memory");
        }

        const uint32_t st = sbase + (uint32_t)sidx * GSTAGE_BYTES;
#pragma unroll
        for (int ks = 0; ks < 4; ++ks) {
            const uint32_t kcb = (uint32_t)(ks * 32);
            uint32_t ah[4][4], al[4][4], bh[2][4], bl[2][4];
#pragma unroll
            for (int mi = 0; mi < 4; ++mi) {
                uint32_t col = (kcb + a_cb);
                uint32_t addr = st + aRow[mi] + (col ^ aXor[mi]);
                ldsm_x4(ah[mi], addr);
                ldsm_x4(al[mi], addr + GTILE_BYTES);
            }
#pragma unroll
            for (int p = 0; p < 2; ++p) {
                uint32_t col = (kcb + b_cb);
                uint32_t addr = st + 2 * GTILE_BYTES + bRow[p] + (col ^ bXor[p]);
                ldsm_x4(bh[p], addr);
                ldsm_x4(bl[p], addr + GTILE_BYTES);
            }
#pragma unroll
            for (int mi = 0; mi < 4; ++mi)
#pragma unroll
                for (int ni = 0; ni < 4; ++ni) {
                    const uint32_t* bhf = &bh[ni >> 1][(ni & 1) * 2];
                    const uint32_t* blf = &bl[ni >> 1][(ni & 1) * 2];
                    mma_bf16(acc[mi][ni], ah[mi], bhf);
                    mma_bf16(acc[mi][ni], ah[mi], blf);
                    mma_bf16(acc[mi][ni], al[mi], bhf);
                }
        }
        if (++sidx == 3) sidx = 0;
    }

#pragma unroll
    for (int mi = 0; mi < 4; ++mi) {
        const int gm = m0 + wm * 64 + mi * 16 + (lane >> 2);
#pragma unroll
        for (int ni = 0; ni < 4; ++ni) {
            const int gn = n0 + wn * 32 + ni * 8 + (lane & 3) * 2;
            if (OUT_MODE == 0) {
                float2 v0 = make_float2(acc[mi][ni][0], acc[mi][ni][1]);
                float2 v1 = make_float2(acc[mi][ni][2], acc[mi][ni][3]);
                *(float2*)(C + (size_t)gm * N + gn) = v0;
                *(float2*)(C + (size_t)(gm + 8) * N + gn) = v1;
            } else {
                uint32_t hi, lo;
                split_pack(acc[mi][ni][0], acc[mi][ni][1], hi, lo);
                *(uint32_t*)(Ch + (size_t)gm * N + gn) = hi;
                *(uint32_t*)(Cl + (size_t)gm * N + gn) = lo;
                split_pack(acc[mi][ni][2], acc[mi][ni][3], hi, lo);
                *(uint32_t*)(Ch + (size_t)(gm + 8) * N + gn) = hi;
                *(uint32_t*)(Cl + (size_t)(gm + 8) * N + gn) = lo;
            }
        }
    }
}

// ---------------------------------------------------------------------------
// Fused QK RMSNorm + RoPE (+gain) -> bf16 hi/lo outputs.
// ---------------------------------------------------------------------------
__global__ void __launch_bounds__(256) rms_rope_split_kernel(
    const float* __restrict__ X, int nheads, const float* __restrict__ gain,
    __nv_bfloat16* __restrict__ H, __nv_bfloat16* __restrict__ L)
{
    const int wid = threadIdx.x >> 5, lane = threadIdx.x & 31;
    const long long gid = (long long)blockIdx.x * 8 + wid;
    const int h = (int)(gid % nheads);
    const long long bt = gid / nheads;
    const int t = (int)(bt % T_);

    const long long base = bt * (long long)(nheads * HD_) + (long long)h * HD_;
    const float* p = X + base;
    float x0 = p[lane], x1 = p[lane + 32], x2 = p[lane + 64], x3 = p[lane + 96];

    float ss = x0 * x0 + x1 * x1 + x2 * x2 + x3 * x3;
#pragma unroll
    for (int o = 16; o; o >>= 1) ss += __shfl_xor_sync(0xffffffffu, ss, o);
    const float r = rsqrtf(ss * (1.0f / 128.0f) + 1.1920928955078125e-07f);
    x0 *= r; x1 *= r; x2 *= r; x3 *= r;

    const float Lc = 13.287712379549449f / 64.0f;
    const float tf = (float)t;
    const float a0 = tf * exp2f(-(float)lane * Lc);
    const float a1 = tf * exp2f(-(float)(lane + 32) * Lc);
    const float c0 = cosf(a0), s0 = sinf(a0);
    const float c1 = cosf(a1), s1 = sinf(a1);
    const float g = gain ? gain[h] : 1.0f;

    float y0 = (x0 * c0 - x2 * s0) * g;
    float y2 = (x2 * c0 + x0 * s0) * g;
    float y1 = (x1 * c1 - x3 * s1) * g;
    float y3 = (x3 * c1 + x1 * s1) * g;

    __nv_bfloat16 h0 = __float2bfloat16(y0), h1 = __float2bfloat16(y1);
    __nv_bfloat16 h2 = __float2bfloat16(y2), h3 = __float2bfloat16(y3);
    H[base + lane]      = h0;  L[base + lane]      = __float2bfloat16(y0 - __bfloat162float(h0));
    H[base + lane + 32] = h1;  L[base + lane + 32] = __float2bfloat16(y1 - __bfloat162float(h1));
    H[base + lane + 64] = h2;  L[base + lane + 64] = __float2bfloat16(y2 - __bfloat162float(h2));
    H[base + lane + 96] = h3;  L[base + lane + 96] = __float2bfloat16(y3 - __bfloat162float(h3));
}

// ---------------------------------------------------------------------------
// Flash attention, HMMA 3xBF16, causal, GQA group=4.
// Br=128, Bc=64, 8 warps. 3-stage KV cp.async pipeline; Q staged through
// stage 0 then held in registers. smem = 3 x 64KB stages.
// Stage layout: Kh,Kl,Vh,Vl each 16KB; each tensor: 2 panels x (64 rows x 128B).
// ---------------------------------------------------------------------------
#define FA_STSZ 65536u
#define FA_SMEM (3 * 65536)   // 196608

__global__ void __launch_bounds__(256, 1) flash_attn_mma_kernel(
    const __nv_bfloat16* __restrict__ Qh, const __nv_bfloat16* __restrict__ Ql,
    const __nv_bfloat16* __restrict__ Kh, const __nv_bfloat16* __restrict__ Kl,
    const __nv_bfloat16* __restrict__ Vh, const __nv_bfloat16* __restrict__ Vl,
    __nv_bfloat16* __restrict__ Yh, __nv_bfloat16* __restrict__ Yl)
{
    extern __shared__ char smem[];
    const uint32_t sb = smem_to_u32(smem);
    const int qt = blockIdx.x, h = blockIdx.y, b = blockIdx.z;
    const int kvh = h >> 2;
    const int tid = threadIdx.x, wid = tid >> 5, lane = tid & 31;

    // ---- Q tile via stage 0 (Qh at +0, Ql at +32768), 16 x 16B per thread ----
#pragma unroll
    for (int i = 0; i < 16; ++i) {
        int gid = tid + i * 256;           // 0..4095
        int tensor = gid >> 11;            // 0:Qh 1:Ql
        int rem = gid & 2047;
        int row = rem >> 4;                // 0..127
        int seg = rem & 15;                // 16B seg within 256B row
        int panel = seg >> 3, segp = seg & 7;
        uint32_t off = (uint32_t)(row * 128 + segp * 16);
        uint32_t dst = sb + (uint32_t)tensor * 32768u + (uint32_t)panel * 16384u
                     + (off ^ ((off >> 3) & 0x70));
        const __nv_bfloat16* g = (tensor ? Ql : Qh)
            + ((size_t)(b * T_ + qt * 128 + row) * DQ + h * HD_ + seg * 8);
        cp_async16(dst, g);
    }
    asm volatile("cp.async.commit_group;" ::: "memory");
    asm volatile("cp.async.wait_group 0;" ::: "memory");
    __syncthreads();

    // lane addressing constants
    const int a_row_l = lane & 15;
    const uint32_t a_cb = (uint32_t)((lane >> 4) * 16);
    const int b_row_l = ((lane >> 4) << 3) + (lane & 7);
    const uint32_t b_cb = (uint32_t)(((lane >> 3) & 1) * 16);
    const int v_row_l = lane & 15;
    const uint32_t v_cb = (uint32_t)((lane >> 4) * 16);

    // ---- extract Q fragments (A operand) for 8 k-steps, hi+lo ----
    uint32_t qhf[8][4], qlf[8][4];
    {
        const int arow = wid * 16 + a_row_l;
        const uint32_t axor = (uint32_t)((arow << 4) & 0x70);
        const uint32_t abase = sb + (uint32_t)(arow * 128);
#pragma unroll
        for (int ks = 0; ks < 8; ++ks) {
            uint32_t colb = (uint32_t)((ks & 3) * 32) + a_cb;
            uint32_t ad = abase + (uint32_t)(ks >> 2) * 16384u + (colb ^ axor);
            ldsm_x4(qhf[ks], ad);
            ldsm_x4(qlf[ks], ad + 32768u);
        }
    }
    __syncthreads();   // everyone done reading Q from stage 0

    // ---- KV stage loader ----
    auto issue_kv = [&](int kt, uint32_t stagebase) {
#pragma unroll
        for (int i = 0; i < 16; ++i) {
            int gid = tid + i * 256;           // 0..4095
            int tensor = gid >> 10;            // 0:Kh 1:Kl 2:Vh 3:Vl
            int rem = gid & 1023;
            int row = rem >> 4;                // 0..63
            int seg = rem & 15;
            int panel = seg >> 3, segp = seg & 7;
            uint32_t off = (uint32_t)(row * 128 + segp * 16);
            uint32_t dst = stagebase + (uint32_t)tensor * 16384u + (uint32_t)panel * 8192u
                         + (off ^ ((off >> 3) & 0x70));
            const __nv_bfloat16* base =
                (tensor == 0) ? Kh : (tensor == 1) ? Kl : (tensor == 2) ? Vh : Vl;
            const __nv_bfloat16* g = base
                + ((size_t)(b * T_ + kt * 64 + row) * DKV + kvh * HD_ + seg * 8);
            cp_async16(dst, g);
        }
        asm volatile("cp.async.commit_group;" ::: "memory");
    };

    const int ktmax = 2 * qt + 1;
    issue_kv(0, sb);
    issue_kv(1, sb + FA_STSZ);

    float m0 = -1e30f, m1 = -1e30f, l0 = 0.0f, l1 = 0.0f;
    float O[16][4];
#pragma unroll
    for (int nt = 0; nt < 16; ++nt)
#pragma unroll
        for (int q = 0; q < 4; ++q) O[nt][q] = 0.0f;

    const int r0g = qt * 128 + wid * 16 + (lane >> 2);
    const float scale = 0.08838834764831845f;

    int sidx = 0;
    for (int kt = 0; kt <= ktmax; ++kt) {
        if (kt + 1 <= ktmax) {
            asm volatile("cp.async.wait_group 1;" ::: "memory");
        } else {
            asm volatile("cp.async.wait_group 0;" ::: "memory");
        }
        __syncthreads();

        if (kt + 2 <= ktmax) {
            int pidx = sidx + 2; if (pidx >= 3) pidx -= 3;
            issue_kv(kt + 2, sb + (uint32_t)pidx * FA_STSZ);
        }

        const uint32_t stg = sb + (uint32_t)sidx * FA_STSZ;

        // ---- S = Q K^T (3 terms) ----
        float sacc[8][4];
#pragma unroll
        for (int nt = 0; nt < 8; ++nt)
#pragma unroll
            for (int q = 0; q < 4; ++q) sacc[nt][q] = 0.0f;

#pragma unroll
        for (int ks = 0; ks < 8; ++ks) {
            const uint32_t pbase = stg + (uint32_t)(ks >> 2) * 8192u;
            const uint32_t colb = (uint32_t)((ks & 3) * 32) + b_cb;
#pragma unroll
            for (int p = 0; p < 4; ++p) {
                const int row = p * 16 + b_row_l;
                const uint32_t ad = pbase + (uint32_t)(row * 128)
                                  + (colb ^ (uint32_t)((row << 4) & 0x70));
                uint32_t kh4[4], kl4[4];
                ldsm_x4(kh4, ad);
                ldsm_x4(kl4, ad + 16384u);
                mma_bf16(sacc[2 * p],     qhf[ks], kh4);
                mma_bf16(sacc[2 * p],     qhf[ks], kl4);
                mma_bf16(sacc[2 * p],     qlf[ks], kh4);
                mma_bf16(sacc[2 * p + 1], qhf[ks], kh4 + 2);
                mma_bf16(sacc[2 * p + 1], qhf[ks], kl4 + 2);
                mma_bf16(sacc[2 * p + 1], qlf[ks], kh4 + 2);
            }
        }

        // ---- scale + causal mask ----
        const int cbase = kt * 64 + (lane & 3) * 2;
        const bool need_mask = (kt >= 2 * qt);
#pragma unroll
        for (int nt = 0; nt < 8; ++nt) {
#pragma unroll
            for (int c = 0; c < 2; ++c) {
                const int col = cbase + nt * 8 + c;
                float v0 = sacc[nt][c] * scale;
                float v1 = sacc[nt][2 + c] * scale;
                if (need_mask) {
                    if (col > r0g)     v0 = -1e30f;
                    if (col > r0g + 8) v1 = -1e30f;
                }
                sacc[nt][c] = v0;
                sacc[nt][2 + c] = v1;
            }
        }

        // ---- online softmax ----
        float mx0 = -1e30f, mx1 = -1e30f;
#pragma unroll
        for (int nt = 0; nt < 8; ++nt) {
            mx0 = fmaxf(mx0, fmaxf(sacc[nt][0], sacc[nt][1]));
            mx1 = fmaxf(mx1, fmaxf(sacc[nt][2], sacc[nt][3]));
        }
        mx0 = fmaxf(mx0, __shfl_xor_sync(0xffffffffu, mx0, 1));
        mx0 = fmaxf(mx0, __shfl_xor_sync(0xffffffffu, mx0, 2));
        mx1 = fmaxf(mx1, __shfl_xor_sync(0xffffffffu, mx1, 1));
        mx1 = fmaxf(mx1, __shfl_xor_sync(0xffffffffu, mx1, 2));
        const float mn0 = fmaxf(m0, mx0), mn1 = fmaxf(m1, mx1);
        const float al0 = __expf(m0 - mn0), al1 = __expf(m1 - mn1);
        m0 = mn0; m1 = mn1;

        float rs0 = 0.0f, rs1 = 0.0f;
#pragma unroll
        for (int nt = 0; nt < 8; ++nt) {
            float p0 = __expf(sacc[nt][0] - mn0);
            float p1 = __expf(sacc[nt][1] - mn0);
            float p2 = __expf(sacc[nt][2] - mn1);
            float p3 = __expf(sacc[nt][3] - mn1);
            sacc[nt][0] = p0; sacc[nt][1] = p1; sacc[nt][2] = p2; sacc[nt][3] = p3;
            rs0 += p0 + p1; rs1 += p2 + p3;
        }
        rs0 += __shfl_xor_sync(0xffffffffu, rs0, 1);
        rs0 += __shfl_xor_sync(0xffffffffu, rs0, 2);
        rs1 += __shfl_xor_sync(0xffffffffu, rs1, 1);
        rs1 += __shfl_xor_sync(0xffffffffu, rs1, 2);
        l0 = l0 * al0 + rs0;
        l1 = l1 * al1 + rs1;

#pragma unroll
        for (int nt = 0; nt < 16; ++nt) {
            O[nt][0] *= al0; O[nt][1] *= al0;
            O[nt][2] *= al1; O[nt][3] *= al1;
        }

        // ---- P fragments (hi/lo bf16), A-operand layout ----
        uint32_t pah[4][4], pal[4][4];
#pragma unroll
        for (int kk = 0; kk < 4; ++kk) {
            const int t0 = 2 * kk, t1 = 2 * kk + 1;
            split_pack(sacc[t0][0], sacc[t0][1], pah[kk][0], pal[kk][0]);
            split_pack(sacc[t0][2], sacc[t0][3], pah[kk][1], pal[kk][1]);
            split_pack(sacc[t1][0], sacc[t1][1], pah[kk][2], pal[kk][2]);
            split_pack(sacc[t1][2], sacc[t1][3], pah[kk][3], pal[kk][3]);
        }

        // ---- O += P V (3 terms) ----
#pragma unroll
        for (int kk = 0; kk < 4; ++kk) {
            const int rowl = kk * 16 + v_row_l;
            const uint32_t rbase = stg + 32768u + (uint32_t)(rowl * 128);
            const uint32_t rxor = (uint32_t)((rowl << 4) & 0x70);
#pragma unroll
            for (int j = 0; j < 8; ++j) {
                const uint32_t colb = (uint32_t)((j & 3) * 32) + v_cb;
                const uint32_t ad = rbase + (uint32_t)(j >> 2) * 8192u + (colb ^ rxor);
                uint32_t vh4[4], vl4[4];
                ldsm_x4_t(vh4, ad);
                ldsm_x4_t(vl4, ad + 16384u);
                mma_bf16(O[2 * j],     pah[kk], vh4);
                mma_bf16(O[2 * j],     pah[kk], vl4);
                mma_bf16(O[2 * j],     pal[kk], vh4);
                mma_bf16(O[2 * j + 1], pah[kk], vh4 + 2);
                mma_bf16(O[2 * j + 1], pah[kk], vl4 + 2);
                mma_bf16(O[2 * j + 1], pal[kk], vh4 + 2);
            }
        }
        if (++sidx == 3) sidx = 0;
    }

    // ---- epilogue: normalize, split hi/lo, write bf16 ----
    const float inv0 = 1.0f / l0, inv1 = 1.0f / l1;
    const size_t tok0 = (size_t)(b * T_ + qt * 128 + wid * 16 + (lane >> 2));
    const int colb = h * HD_ + (lane & 3) * 2;
#pragma unroll
    for (int nt = 0; nt < 16; ++nt) {
        uint32_t hi, lo;
        const size_t idx0 = tok0 * DQ + colb + nt * 8;
        split_pack(O[nt][0] * inv0, O[nt][1] * inv0, hi, lo);
        *(uint32_t*)(Yh + idx0) = hi;
        *(uint32_t*)(Yl + idx0) = lo;
        const size_t idx1 = idx0 + (size_t)8 * DQ;
        split_pack(O[nt][2] * inv1, O[nt][3] * inv1, hi, lo);
        *(uint32_t*)(Yh + idx1) = hi;
        *(uint32_t*)(Yl + idx1) = lo;
    }
}

// ---------------------------------------------------------------------------
// Launch
// ---------------------------------------------------------------------------
extern "C" void kernel_launch(void* const* d_in, const int* in_sizes, int n_in,
                              void* d_out, int out_size)
{
    const float* x     = (const float*)d_in[0];
    const float* Wq    = (const float*)d_in[1];
    const float* Wk    = (const float*)d_in[2];
    const float* Wv    = (const float*)d_in[3];
    const float* Wproj = (const float*)d_in[4];
    const float* qgain = (const float*)d_in[5];
    float* out = (float*)d_out;

    float *Qb, *Kb;
    cudaGetSymbolAddress((void**)&Qb, g_Q);
    cudaGetSymbolAddress((void**)&Kb, g_K);
    __nv_bfloat16 *xh, *xl, *yh, *yl, *wqh, *wql, *wkh, *wkl, *wvh, *wvl, *wph, *wpl;
    __nv_bfloat16 *aqh, *aql, *akh, *akl, *avh, *avl;
    cudaGetSymbolAddress((void**)&xh,  g_xh);
    cudaGetSymbolAddress((void**)&xl,  g_xl);
    cudaGetSymbolAddress((void**)&yh,  g_yh);
    cudaGetSymbolAddress((void**)&yl,  g_yl);
    cudaGetSymbolAddress((void**)&wqh, g_wqh);
    cudaGetSymbolAddress((void**)&wql, g_wql);
    cudaGetSymbolAddress((void**)&wkh, g_wkh);
    cudaGetSymbolAddress((void**)&wkl, g_wkl);
    cudaGetSymbolAddress((void**)&wvh, g_wvh);
    cudaGetSymbolAddress((void**)&wvl, g_wvl);
    cudaGetSymbolAddress((void**)&wph, g_wph);
    cudaGetSymbolAddress((void**)&wpl, g_wpl);
    cudaGetSymbolAddress((void**)&aqh, g_aqh);
    cudaGetSymbolAddress((void**)&aql, g_aql);
    cudaGetSymbolAddress((void**)&akh, g_akh);
    cudaGetSymbolAddress((void**)&akl, g_akl);
    cudaGetSymbolAddress((void**)&avh, g_avh);
    cudaGetSymbolAddress((void**)&avl, g_avl);

    cudaFuncSetAttribute(gemm_mma3_kernel<0>,
                         cudaFuncAttributeMaxDynamicSharedMemorySize, GSMEM_SIZE);
    cudaFuncSetAttribute(gemm_mma3_kernel<1>,
                         cudaFuncAttributeMaxDynamicSharedMemorySize, GSMEM_SIZE);
    cudaFuncSetAttribute(flash_attn_mma_kernel,
                         cudaFuncAttributeMaxDynamicSharedMemorySize, FA_SMEM);

    // Convert inputs to bf16 hi/lo
    cvt_hilo_kernel<<<(MROWS * DQ / 4 + 255) / 256, 256>>>(x, xh, xl, MROWS * DQ / 4);
    cvt_hilo_kernel<<<(DQ * DQ / 4 + 255) / 256, 256>>>(Wq, wqh, wql, DQ * DQ / 4);
    cvt_hilo_kernel<<<(DKV * DQ / 4 + 255) / 256, 256>>>(Wk, wkh, wkl, DKV * DQ / 4);
    cvt_hilo_kernel<<<(DKV * DQ / 4 + 255) / 256, 256>>>(Wv, wvh, wvl, DKV * DQ / 4);
    cvt_hilo_kernel<<<(DQ * DQ / 4 + 255) / 256, 256>>>(Wproj, wph, wpl, DQ * DQ / 4);

    // QKV projections on HMMA tensor cores (3xBF16)
    gemm_mma3_kernel<0><<<dim3(DQ / 128,  MROWS / 128), 256, GSMEM_SIZE>>>(
        xh, xl, wqh, wql, Qb, nullptr, nullptr, MROWS, DQ, DQ);
    gemm_mma3_kernel<0><<<dim3(DKV / 128, MROWS / 128), 256, GSMEM_SIZE>>>(
        xh, xl, wkh, wkl, Kb, nullptr, nullptr, MROWS, DKV, DQ);
    // V projection writes bf16 hi/lo directly (no fp32 round-trip)
    gemm_mma3_kernel<1><<<dim3(DKV / 128, MROWS / 128), 256, GSMEM_SIZE>>>(
        xh, xl, wvh, wvl, nullptr, avh, avl, MROWS, DKV, DQ);

    // RMSNorm + RoPE (+gain on Q) -> bf16 hi/lo
    rms_rope_split_kernel<<<(MROWS * NH) / 8, 256>>>(Qb, NH, qgain, aqh, aql);
    rms_rope_split_kernel<<<(MROWS * NKV) / 8, 256>>>(Kb, NKV, nullptr, akh, akl);

    // Flash attention (HMMA 3xBF16) -> yh/yl bf16
    flash_attn_mma_kernel<<<dim3(T_ / 128, NH, B_), 256, FA_SMEM>>>(
        aqh, aql, akh, akl, avh, avl, yh, yl);

    // Output projection
    gemm_mma3_kernel<0><<<dim3(DQ / 128, MROWS / 128), 256, GSMEM_SIZE>>>(
        yh, yl, wph, wpl, out, nullptr, nullptr, MROWS, DQ, DQ);
}

// round 11
// speedup vs baseline: 1.0013x; 1.0005x over previous
#include <cuda_runtime.h>
#include <cuda_bf16.h>
#include <math.h>
#include <cstdint>

// Problem constants
#define B_   4
#define T_   2048
#define NH   16
#define NKV  4
#define HD_  128
#define DQ   (NH * HD_)    // 2048
#define DKV  (NKV * HD_)   // 512
#define MROWS (B_ * T_)    // 8192

// ---------------------------------------------------------------------------
// Scratch (device globals; allocations banned)
// ---------------------------------------------------------------------------
__device__ float g_Q[(size_t)MROWS * DQ];    // fp32 Q projection
__device__ float g_K[(size_t)MROWS * DKV];   // fp32 K projection

__device__ __nv_bfloat16 g_xh[(size_t)MROWS * DQ];
__device__ __nv_bfloat16 g_xl[(size_t)MROWS * DQ];
__device__ __nv_bfloat16 g_yh[(size_t)MROWS * DQ];
__device__ __nv_bfloat16 g_yl[(size_t)MROWS * DQ];
__device__ __nv_bfloat16 g_wqh[(size_t)DQ * DQ];
__device__ __nv_bfloat16 g_wql[(size_t)DQ * DQ];
__device__ __nv_bfloat16 g_wkh[(size_t)DKV * DQ];
__device__ __nv_bfloat16 g_wkl[(size_t)DKV * DQ];
__device__ __nv_bfloat16 g_wvh[(size_t)DKV * DQ];
__device__ __nv_bfloat16 g_wvl[(size_t)DKV * DQ];
__device__ __nv_bfloat16 g_wph[(size_t)DQ * DQ];
__device__ __nv_bfloat16 g_wpl[(size_t)DQ * DQ];

// attention operands (hi/lo bf16)
__device__ __nv_bfloat16 g_aqh[(size_t)MROWS * DQ];
__device__ __nv_bfloat16 g_aql[(size_t)MROWS * DQ];
__device__ __nv_bfloat16 g_akh[(size_t)MROWS * DKV];
__device__ __nv_bfloat16 g_akl[(size_t)MROWS * DKV];
__device__ __nv_bfloat16 g_avh[(size_t)MROWS * DKV];
__device__ __nv_bfloat16 g_avl[(size_t)MROWS * DKV];

// ---------------------------------------------------------------------------
// Warp-level MMA helpers (sm_80+ PTX; safe for sm_103 base target)
// ---------------------------------------------------------------------------
__device__ __forceinline__ uint32_t smem_to_u32(const void* smem_ptr) {
    uint32_t addr;
    asm("{ .reg .u64 tmp; cvta.to.shared.u64 tmp, %1; cvt.u32.u64 %0, tmp; }"
        : "=r"(addr) : "l"(smem_ptr));
    return addr;
}

__device__ __forceinline__ void ldsm_x4(uint32_t* r, uint32_t addr) {
    asm volatile("ldmatrix.sync.aligned.m8n8.x4.shared.b16 {%0,%1,%2,%3}, [%4];"
        : "=r"(r[0]), "=r"(r[1]), "=r"(r[2]), "=r"(r[3]) : "r"(addr));
}

__device__ __forceinline__ void ldsm_x4_t(uint32_t* r, uint32_t addr) {
    asm volatile("ldmatrix.sync.aligned.m8n8.x4.trans.shared.b16 {%0,%1,%2,%3}, [%4];"
        : "=r"(r[0]), "=r"(r[1]), "=r"(r[2]), "=r"(r[3]) : "r"(addr));
}

__device__ __forceinline__ void mma_bf16(float* d, const uint32_t* a, const uint32_t* b) {
    asm volatile(
        "mma.sync.aligned.m16n8k16.row.col.f32.bf16.bf16.f32 "
        "{%0,%1,%2,%3}, {%4,%5,%6,%7}, {%8,%9}, {%0,%1,%2,%3};"
        : "+f"(d[0]), "+f"(d[1]), "+f"(d[2]), "+f"(d[3])
        : "r"(a[0]), "r"(a[1]), "r"(a[2]), "r"(a[3]), "r"(b[0]), "r"(b[1]));
}

__device__ __forceinline__ void cp_async16(uint32_t dst, const void* src) {
    asm volatile("cp.async.cg.shared.global [%0], [%1], 16;"
                 :: "r"(dst), "l"(src) : "memory");
}

// split x,y into packed bf16 hi + lo pairs
__device__ __forceinline__ void split_pack(float x, float y, uint32_t& hi, uint32_t& lo) {
    __nv_bfloat16 hx = __float2bfloat16(x);
    __nv_bfloat16 hy = __float2bfloat16(y);
    __nv_bfloat16 lx = __float2bfloat16(x - __bfloat162float(hx));
    __nv_bfloat16 ly = __float2bfloat16(y - __bfloat162float(hy));
    __nv_bfloat162 h2 = __halves2bfloat162(hx, hy);
    __nv_bfloat162 l2 = __halves2bfloat162(lx, ly);
    hi = *(uint32_t*)&h2; lo = *(uint32_t*)&l2;
}

// ---------------------------------------------------------------------------
// fp32 -> bf16 hi/lo split
// ---------------------------------------------------------------------------
__global__ void __launch_bounds__(256) cvt_hilo_kernel(
    const float* __restrict__ x,
    __nv_bfloat16* __restrict__ hi, __nv_bfloat16* __restrict__ lo, int n4)
{
    int i = blockIdx.x * 256 + threadIdx.x;
    if (i >= n4) return;
    float4 v = ((const float4*)x)[i];
    __nv_bfloat16 h[4], l[4];
    h[0] = __float2bfloat16(v.x); l[0] = __float2bfloat16(v.x - __bfloat162float(h[0]));
    h[1] = __float2bfloat16(v.y); l[1] = __float2bfloat16(v.y - __bfloat162float(h[1]));
    h[2] = __float2bfloat16(v.z); l[2] = __float2bfloat16(v.z - __bfloat162float(h[2]));
    h[3] = __float2bfloat16(v.w); l[3] = __float2bfloat16(v.w - __bfloat162float(h[3]));
    *(uint2*)(hi + 4 * (size_t)i) = *(uint2*)h;
    *(uint2*)(lo + 4 * (size_t)i) = *(uint2*)l;
}

// ---------------------------------------------------------------------------
// HMMA 3xBF16 GEMM (NT): C[M,N] = A[M,K] * B[N,K]^T, fp32 accumulate.
// BM=128, BN=128, BK=64. 8 warps (2x4). 3-stage cp.async pipeline, one
// __syncthreads per chunk. OUT_MODE 0: fp32 C; OUT_MODE 1: bf16 hi/lo.
// ---------------------------------------------------------------------------
#define GTILE_BYTES  16384
#define GSTAGE_BYTES (4 * GTILE_BYTES)      // 65536
#define GSMEM_SIZE   (3 * GSTAGE_BYTES)     // 196608

template<int OUT_MODE>
__global__ void __launch_bounds__(256, 1)
gemm_mma3_kernel(const __nv_bfloat16* __restrict__ Ah,
                 const __nv_bfloat16* __restrict__ Al,
                 const __nv_bfloat16* __restrict__ Bh,
                 const __nv_bfloat16* __restrict__ Bl,
                 float* __restrict__ C,
                 __nv_bfloat16* __restrict__ Ch, __nv_bfloat16* __restrict__ Cl,
                 int M, int N, int Kd)
{
    extern __shared__ char smem[];
    const uint32_t sbase = smem_to_u32(smem);
    const int tid = threadIdx.x;
    const int wid = tid >> 5, lane = tid & 31;
    const int wm = wid >> 2, wn = wid & 3;
    const int m0 = blockIdx.y * 128, n0 = blockIdx.x * 128;
    const int nchunk = Kd >> 6;

    const char* gsrc[16];
    uint32_t    soff[16];
#pragma unroll
    for (int i = 0; i < 16; ++i) {
        int gid  = tid + i * 256;
        int tile = gid >> 10;
        int rem  = gid & 1023;
        int row  = rem >> 3;
        int seg  = rem & 7;
        uint32_t off = (uint32_t)(row * 128 + seg * 16);
        soff[i] = (uint32_t)tile * GTILE_BYTES + (off ^ ((off >> 3) & 0x70));
        const char* base =
            (tile == 0) ? (const char*)Ah :
            (tile == 1) ? (const char*)Al :
            (tile == 2) ? (const char*)Bh : (const char*)Bl;
        int r0 = (tile < 2) ? m0 : n0;
        gsrc[i] = base + ((size_t)(r0 + row) * Kd + (size_t)seg * 8) * 2;
    }

    // Prologue: chunks 0 and 1 into stages 0, 1
#pragma unroll
    for (int i = 0; i < 16; ++i) cp_async16(sbase + soff[i], gsrc[i]);
    asm volatile("cp.async.commit_group;" ::: "memory");
#pragma unroll
    for (int i = 0; i < 16; ++i)
        cp_async16(sbase + GSTAGE_BYTES + soff[i], gsrc[i] + 128);
    asm volatile("cp.async.commit_group;" ::: "memory");

    const int a_row_l = (lane & 15);
    const uint32_t a_cb = (uint32_t)((lane >> 4) * 16);
    const int b_row_l = ((lane >> 4) << 3) + (lane & 7);
    const uint32_t b_cb = (uint32_t)(((lane >> 3) & 1) * 16);

    uint32_t aRow[4], aXor[4];
#pragma unroll
    for (int mi = 0; mi < 4; ++mi) {
        int r = wm * 64 + mi * 16 + a_row_l;
        aRow[mi] = (uint32_t)(r * 128);
        aXor[mi] = (uint32_t)((r << 4) & 0x70);
    }
    uint32_t bRow[2], bXor[2];
#pragma unroll
    for (int p = 0; p < 2; ++p) {
        int r = wn * 32 + p * 16 + b_row_l;
        bRow[p] = (uint32_t)(r * 128);
        bXor[p] = (uint32_t)((r << 4) & 0x70);
    }

    float acc[4][4][4];
#pragma unroll
    for (int mi = 0; mi < 4; ++mi)
#pragma unroll
        for (int ni = 0; ni < 4; ++ni)
#pragma unroll
            for (int q = 0; q < 4; ++q) acc[mi][ni][q] = 0.0f;

    int sidx = 0;                 // stage of chunk c
    for (int c = 0; c < nchunk; ++c) {
        if (c + 1 < nchunk) {
            asm volatile("cp.async.wait_group 1;" ::: "memory");
        } else {
            asm volatile("cp.async.wait_group 0;" ::: "memory");
        }
        __syncthreads();

        if (c + 2 < nchunk) {
            int pidx = sidx + 2; if (pidx >= 3) pidx -= 3;
            const uint32_t stn = sbase + (uint32_t)pidx * GSTAGE_BYTES;
            const size_t kb = (size_t)(c + 2) * 128;
#pragma unroll
            for (int i = 0; i < 16; ++i) cp_async16(stn + soff[i], gsrc[i] + kb);
            asm volatile("cp.async.commit_group;" ::: "memory");
        }

        const uint32_t st = sbase + (uint32_t)sidx * GSTAGE_BYTES;
#pragma unroll
        for (int ks = 0; ks < 4; ++ks) {
            const uint32_t kcb = (uint32_t)(ks * 32);
            uint32_t ah[4][4], al[4][4], bh[2][4], bl[2][4];
#pragma unroll
            for (int mi = 0; mi < 4; ++mi) {
                uint32_t col = (kcb + a_cb);
                uint32_t addr = st + aRow[mi] + (col ^ aXor[mi]);
                ldsm_x4(ah[mi], addr);
                ldsm_x4(al[mi], addr + GTILE_BYTES);
            }
#pragma unroll
            for (int p = 0; p < 2; ++p) {
                uint32_t col = (kcb + b_cb);
                uint32_t addr = st + 2 * GTILE_BYTES + bRow[p] + (col ^ bXor[p]);
                ldsm_x4(bh[p], addr);
                ldsm_x4(bl[p], addr + GTILE_BYTES);
            }
#pragma unroll
            for (int mi = 0; mi < 4; ++mi)
#pragma unroll
                for (int ni = 0; ni < 4; ++ni) {
                    const uint32_t* bhf = &bh[ni >> 1][(ni & 1) * 2];
                    const uint32_t* blf = &bl[ni >> 1][(ni & 1) * 2];
                    mma_bf16(acc[mi][ni], ah[mi], bhf);
                    mma_bf16(acc[mi][ni], ah[mi], blf);
                    mma_bf16(acc[mi][ni], al[mi], bhf);
                }
        }
        if (++sidx == 3) sidx = 0;
    }

#pragma unroll
    for (int mi = 0; mi < 4; ++mi) {
        const int gm = m0 + wm * 64 + mi * 16 + (lane >> 2);
#pragma unroll
        for (int ni = 0; ni < 4; ++ni) {
            const int gn = n0 + wn * 32 + ni * 8 + (lane & 3) * 2;
            if (OUT_MODE == 0) {
                float2 v0 = make_float2(acc[mi][ni][0], acc[mi][ni][1]);
                float2 v1 = make_float2(acc[mi][ni][2], acc[mi][ni][3]);
                *(float2*)(C + (size_t)gm * N + gn) = v0;
                *(float2*)(C + (size_t)(gm + 8) * N + gn) = v1;
            } else {
                uint32_t hi, lo;
                split_pack(acc[mi][ni][0], acc[mi][ni][1], hi, lo);
                *(uint32_t*)(Ch + (size_t)gm * N + gn) = hi;
                *(uint32_t*)(Cl + (size_t)gm * N + gn) = lo;
                split_pack(acc[mi][ni][2], acc[mi][ni][3], hi, lo);
                *(uint32_t*)(Ch + (size_t)(gm + 8) * N + gn) = hi;
                *(uint32_t*)(Cl + (size_t)(gm + 8) * N + gn) = lo;
            }
        }
    }
}

// ---------------------------------------------------------------------------
// Fused QK RMSNorm + RoPE (+gain) -> bf16 hi/lo outputs.
// ---------------------------------------------------------------------------
__global__ void __launch_bounds__(256) rms_rope_split_kernel(
    const float* __restrict__ X, int nheads, const float* __restrict__ gain,
    __nv_bfloat16* __restrict__ H, __nv_bfloat16* __restrict__ L)
{
    const int wid = threadIdx.x >> 5, lane = threadIdx.x & 31;
    const long long gid = (long long)blockIdx.x * 8 + wid;
    const int h = (int)(gid % nheads);
    const long long bt = gid / nheads;
    const int t = (int)(bt % T_);

    const long long base = bt * (long long)(nheads * HD_) + (long long)h * HD_;
    const float* p = X + base;
    float x0 = p[lane], x1 = p[lane + 32], x2 = p[lane + 64], x3 = p[lane + 96];

    float ss = x0 * x0 + x1 * x1 + x2 * x2 + x3 * x3;
#pragma unroll
    for (int o = 16; o; o >>= 1) ss += __shfl_xor_sync(0xffffffffu, ss, o);
    const float r = rsqrtf(ss * (1.0f / 128.0f) + 1.1920928955078125e-07f);
    x0 *= r; x1 *= r; x2 *= r; x3 *= r;

    const float Lc = 13.287712379549449f / 64.0f;
    const float tf = (float)t;
    const float a0 = tf * exp2f(-(float)lane * Lc);
    const float a1 = tf * exp2f(-(float)(lane + 32) * Lc);
    const float c0 = cosf(a0), s0 = sinf(a0);
    const float c1 = cosf(a1), s1 = sinf(a1);
    const float g = gain ? gain[h] : 1.0f;

    float y0 = (x0 * c0 - x2 * s0) * g;
    float y2 = (x2 * c0 + x0 * s0) * g;
    float y1 = (x1 * c1 - x3 * s1) * g;
    float y3 = (x3 * c1 + x1 * s1) * g;

    __nv_bfloat16 h0 = __float2bfloat16(y0), h1 = __float2bfloat16(y1);
    __nv_bfloat16 h2 = __float2bfloat16(y2), h3 = __float2bfloat16(y3);
    H[base + lane]      = h0;  L[base + lane]      = __float2bfloat16(y0 - __bfloat162float(h0));
    H[base + lane + 32] = h1;  L[base + lane + 32] = __float2bfloat16(y1 - __bfloat162float(h1));
    H[base + lane + 64] = h2;  L[base + lane + 64] = __float2bfloat16(y2 - __bfloat162float(h2));
    H[base + lane + 96] = h3;  L[base + lane + 96] = __float2bfloat16(y3 - __bfloat162float(h3));
}

// ---------------------------------------------------------------------------
// Flash attention, HMMA 3xBF16, causal, GQA group=4.
// Br=128, Bc=64, 8 warps. 3-stage KV cp.async pipeline; Q staged through
// stage 0 then held in registers. smem = 3 x 64KB stages.
// Stage layout: Kh,Kl,Vh,Vl each 16KB; each tensor: 2 panels x (64 rows x 128B).
// ---------------------------------------------------------------------------
#define FA_STSZ 65536u
#define FA_SMEM (3 * 65536)   // 196608

__global__ void __launch_bounds__(256, 1) flash_attn_mma_kernel(
    const __nv_bfloat16* __restrict__ Qh, const __nv_bfloat16* __restrict__ Ql,
    const __nv_bfloat16* __restrict__ Kh, const __nv_bfloat16* __restrict__ Kl,
    const __nv_bfloat16* __restrict__ Vh, const __nv_bfloat16* __restrict__ Vl,
    __nv_bfloat16* __restrict__ Yh, __nv_bfloat16* __restrict__ Yl)
{
    extern __shared__ char smem[];
    const uint32_t sb = smem_to_u32(smem);
    const int qt = blockIdx.x, h = blockIdx.y, b = blockIdx.z;
    const int kvh = h >> 2;
    const int tid = threadIdx.x, wid = tid >> 5, lane = tid & 31;

    // ---- Q tile via stage 0 (Qh at +0, Ql at +32768), 16 x 16B per thread ----
#pragma unroll
    for (int i = 0; i < 16; ++i) {
        int gid = tid + i * 256;           // 0..4095
        int tensor = gid >> 11;            // 0:Qh 1:Ql
        int rem = gid & 2047;
        int row = rem >> 4;                // 0..127
        int seg = rem & 15;                // 16B seg within 256B row
        int panel = seg >> 3, segp = seg & 7;
        uint32_t off = (uint32_t)(row * 128 + segp * 16);
        uint32_t dst = sb + (uint32_t)tensor * 32768u + (uint32_t)panel * 16384u
                     + (off ^ ((off >> 3) & 0x70));
        const __nv_bfloat16* g = (tensor ? Ql : Qh)
            + ((size_t)(b * T_ + qt * 128 + row) * DQ + h * HD_ + seg * 8);
        cp_async16(dst, g);
    }
    asm volatile("cp.async.commit_group;" ::: "memory");
    asm volatile("cp.async.wait_group 0;" ::: "memory");
    __syncthreads();

    // lane addressing constants
    const int a_row_l = lane & 15;
    const uint32_t a_cb = (uint32_t)((lane >> 4) * 16);
    const int b_row_l = ((lane >> 4) << 3) + (lane & 7);
    const uint32_t b_cb = (uint32_t)(((lane >> 3) & 1) * 16);
    const int v_row_l = lane & 15;
    const uint32_t v_cb = (uint32_t)((lane >> 4) * 16);

    // ---- extract Q fragments (A operand) for 8 k-steps, hi+lo ----
    uint32_t qhf[8][4], qlf[8][4];
    {
        const int arow = wid * 16 + a_row_l;
        const uint32_t axor = (uint32_t)((arow << 4) & 0x70);
        const uint32_t abase = sb + (uint32_t)(arow * 128);
#pragma unroll
        for (int ks = 0; ks < 8; ++ks) {
            uint32_t colb = (uint32_t)((ks & 3) * 32) + a_cb;
            uint32_t ad = abase + (uint32_t)(ks >> 2) * 16384u + (colb ^ axor);
            ldsm_x4(qhf[ks], ad);
            ldsm_x4(qlf[ks], ad + 32768u);
        }
    }
    __syncthreads();   // everyone done reading Q from stage 0

    // ---- KV stage loader ----
    auto issue_kv = [&](int kt, uint32_t stagebase) {
#pragma unroll
        for (int i = 0; i < 16; ++i) {
            int gid = tid + i * 256;           // 0..4095
            int tensor = gid >> 10;            // 0:Kh 1:Kl 2:Vh 3:Vl
            int rem = gid & 1023;
            int row = rem >> 4;                // 0..63
            int seg = rem & 15;
            int panel = seg >> 3, segp = seg & 7;
            uint32_t off = (uint32_t)(row * 128 + segp * 16);
            uint32_t dst = stagebase + (uint32_t)tensor * 16384u + (uint32_t)panel * 8192u
                         + (off ^ ((off >> 3) & 0x70));
            const __nv_bfloat16* base =
                (tensor == 0) ? Kh : (tensor == 1) ? Kl : (tensor == 2) ? Vh : Vl;
            const __nv_bfloat16* g = base
                + ((size_t)(b * T_ + kt * 64 + row) * DKV + kvh * HD_ + seg * 8);
            cp_async16(dst, g);
        }
        asm volatile("cp.async.commit_group;" ::: "memory");
    };

    const int ktmax = 2 * qt + 1;
    issue_kv(0, sb);
    issue_kv(1, sb + FA_STSZ);

    float m0 = -1e30f, m1 = -1e30f, l0 = 0.0f, l1 = 0.0f;
    float O[16][4];
#pragma unroll
    for (int nt = 0; nt < 16; ++nt)
#pragma unroll
        for (int q = 0; q < 4; ++q) O[nt][q] = 0.0f;

    const int r0g = qt * 128 + wid * 16 + (lane >> 2);
    const float scale = 0.08838834764831845f;

    int sidx = 0;
    for (int kt = 0; kt <= ktmax; ++kt) {
        if (kt + 1 <= ktmax) {
            asm volatile("cp.async.wait_group 1;" ::: "memory");
        } else {
            asm volatile("cp.async.wait_group 0;" ::: "memory");
        }
        __syncthreads();

        if (kt + 2 <= ktmax) {
            int pidx = sidx + 2; if (pidx >= 3) pidx -= 3;
            issue_kv(kt + 2, sb + (uint32_t)pidx * FA_STSZ);
        }

        const uint32_t stg = sb + (uint32_t)sidx * FA_STSZ;

        // ---- S = Q K^T (3 terms) ----
        float sacc[8][4];
#pragma unroll
        for (int nt = 0; nt < 8; ++nt)
#pragma unroll
            for (int q = 0; q < 4; ++q) sacc[nt][q] = 0.0f;

#pragma unroll
        for (int ks = 0; ks < 8; ++ks) {
            const uint32_t pbase = stg + (uint32_t)(ks >> 2) * 8192u;
            const uint32_t colb = (uint32_t)((ks & 3) * 32) + b_cb;
#pragma unroll
            for (int p = 0; p < 4; ++p) {
                const int row = p * 16 + b_row_l;
                const uint32_t ad = pbase + (uint32_t)(row * 128)
                                  + (colb ^ (uint32_t)((row << 4) & 0x70));
                uint32_t kh4[4], kl4[4];
                ldsm_x4(kh4, ad);
                ldsm_x4(kl4, ad + 16384u);
                mma_bf16(sacc[2 * p],     qhf[ks], kh4);
                mma_bf16(sacc[2 * p],     qhf[ks], kl4);
                mma_bf16(sacc[2 * p],     qlf[ks], kh4);
                mma_bf16(sacc[2 * p + 1], qhf[ks], kh4 + 2);
                mma_bf16(sacc[2 * p + 1], qhf[ks], kl4 + 2);
                mma_bf16(sacc[2 * p + 1], qlf[ks], kh4 + 2);
            }
        }

        // ---- scale + causal mask ----
        const int cbase = kt * 64 + (lane & 3) * 2;
        const bool need_mask = (kt >= 2 * qt);
#pragma unroll
        for (int nt = 0; nt < 8; ++nt) {
#pragma unroll
            for (int c = 0; c < 2; ++c) {
                const int col = cbase + nt * 8 + c;
                float v0 = sacc[nt][c] * scale;
                float v1 = sacc[nt][2 + c] * scale;
                if (need_mask) {
                    if (col > r0g)     v0 = -1e30f;
                    if (col > r0g + 8) v1 = -1e30f;
                }
                sacc[nt][c] = v0;
                sacc[nt][2 + c] = v1;
            }
        }

        // ---- online softmax ----
        float mx0 = -1e30f, mx1 = -1e30f;
#pragma unroll
        for (int nt = 0; nt < 8; ++nt) {
            mx0 = fmaxf(mx0, fmaxf(sacc[nt][0], sacc[nt][1]));
            mx1 = fmaxf(mx1, fmaxf(sacc[nt][2], sacc[nt][3]));
        }
        mx0 = fmaxf(mx0, __shfl_xor_sync(0xffffffffu, mx0, 1));
        mx0 = fmaxf(mx0, __shfl_xor_sync(0xffffffffu, mx0, 2));
        mx1 = fmaxf(mx1, __shfl_xor_sync(0xffffffffu, mx1, 1));
        mx1 = fmaxf(mx1, __shfl_xor_sync(0xffffffffu, mx1, 2));
        const float mn0 = fmaxf(m0, mx0), mn1 = fmaxf(m1, mx1);
        const float al0 = __expf(m0 - mn0), al1 = __expf(m1 - mn1);
        m0 = mn0; m1 = mn1;

        float rs0 = 0.0f, rs1 = 0.0f;
#pragma unroll
        for (int nt = 0; nt < 8; ++nt) {
            float p0 = __expf(sacc[nt][0] - mn0);
            float p1 = __expf(sacc[nt][1] - mn0);
            float p2 = __expf(sacc[nt][2] - mn1);
            float p3 = __expf(sacc[nt][3] - mn1);
            sacc[nt][0] = p0; sacc[nt][1] = p1; sacc[nt][2] = p2; sacc[nt][3] = p3;
            rs0 += p0 + p1; rs1 += p2 + p3;
        }
        rs0 += __shfl_xor_sync(0xffffffffu, rs0, 1);
        rs0 += __shfl_xor_sync(0xffffffffu, rs0, 2);
        rs1 += __shfl_xor_sync(0xffffffffu, rs1, 1);
        rs1 += __shfl_xor_sync(0xffffffffu, rs1, 2);
        l0 = l0 * al0 + rs0;
        l1 = l1 * al1 + rs1;

#pragma unroll
        for (int nt = 0; nt < 16; ++nt) {
            O[nt][0] *= al0; O[nt][1] *= al0;
            O[nt][2] *= al1; O[nt][3] *= al1;
        }

        // ---- P fragments (hi/lo bf16), A-operand layout ----
        uint32_t pah[4][4], pal[4][4];
#pragma unroll
        for (int kk = 0; kk < 4; ++kk) {
            const int t0 = 2 * kk, t1 = 2 * kk + 1;
            split_pack(sacc[t0][0], sacc[t0][1], pah[kk][0], pal[kk][0]);
            split_pack(sacc[t0][2], sacc[t0][3], pah[kk][1], pal[kk][1]);
            split_pack(sacc[t1][0], sacc[t1][1], pah[kk][2], pal[kk][2]);
            split_pack(sacc[t1][2], sacc[t1][3], pah[kk][3], pal[kk][3]);
        }

        // ---- O += P V (3 terms) ----
#pragma unroll
        for (int kk = 0; kk < 4; ++kk) {
            const int rowl = kk * 16 + v_row_l;
            const uint32_t rbase = stg + 32768u + (uint32_t)(rowl * 128);
            const uint32_t rxor = (uint32_t)((rowl << 4) & 0x70);
#pragma unroll
            for (int j = 0; j < 8; ++j) {
                const uint32_t colb = (uint32_t)((j & 3) * 32) + v_cb;
                const uint32_t ad = rbase + (uint32_t)(j >> 2) * 8192u + (colb ^ rxor);
                uint32_t vh4[4], vl4[4];
                ldsm_x4_t(vh4, ad);
                ldsm_x4_t(vl4, ad + 16384u);
                mma_bf16(O[2 * j],     pah[kk], vh4);
                mma_bf16(O[2 * j],     pah[kk], vl4);
                mma_bf16(O[2 * j],     pal[kk], vh4);
                mma_bf16(O[2 * j + 1], pah[kk], vh4 + 2);
                mma_bf16(O[2 * j + 1], pah[kk], vl4 + 2);
                mma_bf16(O[2 * j + 1], pal[kk], vh4 + 2);
            }
        }
        if (++sidx == 3) sidx = 0;
    }

    // ---- epilogue: normalize, split hi/lo, write bf16 ----
    const float inv0 = 1.0f / l0, inv1 = 1.0f / l1;
    const size_t tok0 = (size_t)(b * T_ + qt * 128 + wid * 16 + (lane >> 2));
    const int colb = h * HD_ + (lane & 3) * 2;
#pragma unroll
    for (int nt = 0; nt < 16; ++nt) {
        uint32_t hi, lo;
        const size_t idx0 = tok0 * DQ + colb + nt * 8;
        split_pack(O[nt][0] * inv0, O[nt][1] * inv0, hi, lo);
        *(uint32_t*)(Yh + idx0) = hi;
        *(uint32_t*)(Yl + idx0) = lo;
        const size_t idx1 = idx0 + (size_t)8 * DQ;
        split_pack(O[nt][2] * inv1, O[nt][3] * inv1, hi, lo);
        *(uint32_t*)(Yh + idx1) = hi;
        *(uint32_t*)(Yl + idx1) = lo;
    }
}

// ---------------------------------------------------------------------------
// Launch
// ---------------------------------------------------------------------------
extern "C" void kernel_launch(void* const* d_in, const int* in_sizes, int n_in,
                              void* d_out, int out_size)
{
    const float* x     = (const float*)d_in[0];
    const float* Wq    = (const float*)d_in[1];
    const float* Wk    = (const float*)d_in[2];
    const float* Wv    = (const float*)d_in[3];
    const float* Wproj = (const float*)d_in[4];
    const float* qgain = (const float*)d_in[5];
    float* out = (float*)d_out;

    float *Qb, *Kb;
    cudaGetSymbolAddress((void**)&Qb, g_Q);
    cudaGetSymbolAddress((void**)&Kb, g_K);
    __nv_bfloat16 *xh, *xl, *yh, *yl, *wqh, *wql, *wkh, *wkl, *wvh, *wvl, *wph, *wpl;
    __nv_bfloat16 *aqh, *aql, *akh, *akl, *avh, *avl;
    cudaGetSymbolAddress((void**)&xh,  g_xh);
    cudaGetSymbolAddress((void**)&xl,  g_xl);
    cudaGetSymbolAddress((void**)&yh,  g_yh);
    cudaGetSymbolAddress((void**)&yl,  g_yl);
    cudaGetSymbolAddress((void**)&wqh, g_wqh);
    cudaGetSymbolAddress((void**)&wql, g_wql);
    cudaGetSymbolAddress((void**)&wkh, g_wkh);
    cudaGetSymbolAddress((void**)&wkl, g_wkl);
    cudaGetSymbolAddress((void**)&wvh, g_wvh);
    cudaGetSymbolAddress((void**)&wvl, g_wvl);
    cudaGetSymbolAddress((void**)&wph, g_wph);
    cudaGetSymbolAddress((void**)&wpl, g_wpl);
    cudaGetSymbolAddress((void**)&aqh, g_aqh);
    cudaGetSymbolAddress((void**)&aql, g_aql);
    cudaGetSymbolAddress((void**)&akh, g_akh);
    cudaGetSymbolAddress((void**)&akl, g_akl);
    cudaGetSymbolAddress((void**)&avh, g_avh);
    cudaGetSymbolAddress((void**)&avl, g_avl);

    cudaFuncSetAttribute(gemm_mma3_kernel<0>,
                         cudaFuncAttributeMaxDynamicSharedMemorySize, GSMEM_SIZE);
    cudaFuncSetAttribute(gemm_mma3_kernel<1>,
                         cudaFuncAttributeMaxDynamicSharedMemorySize, GSMEM_SIZE);
    cudaFuncSetAttribute(flash_attn_mma_kernel,
                         cudaFuncAttributeMaxDynamicSharedMemorySize, FA_SMEM);

    // Convert inputs to bf16 hi/lo
    cvt_hilo_kernel<<<(MROWS * DQ / 4 + 255) / 256, 256>>>(x, xh, xl, MROWS * DQ / 4);
    cvt_hilo_kernel<<<(DQ * DQ / 4 + 255) / 256, 256>>>(Wq, wqh, wql, DQ * DQ / 4);
    cvt_hilo_kernel<<<(DKV * DQ / 4 + 255) / 256, 256>>>(Wk, wkh, wkl, DKV * DQ / 4);
    cvt_hilo_kernel<<<(DKV * DQ / 4 + 255) / 256, 256>>>(Wv, wvh, wvl, DKV * DQ / 4);
    cvt_hilo_kernel<<<(DQ * DQ / 4 + 255) / 256, 256>>>(Wproj, wph, wpl, DQ * DQ / 4);

    // QKV projections on HMMA tensor cores (3xBF16)
    gemm_mma3_kernel<0><<<dim3(DQ / 128,  MROWS / 128), 256, GSMEM_SIZE>>>(
        xh, xl, wqh, wql, Qb, nullptr, nullptr, MROWS, DQ, DQ);
    gemm_mma3_kernel<0><<<dim3(DKV / 128, MROWS / 128), 256, GSMEM_SIZE>>>(
        xh, xl, wkh, wkl, Kb, nullptr, nullptr, MROWS, DKV, DQ);
    // V projection writes bf16 hi/lo directly (no fp32 round-trip)
    gemm_mma3_kernel<1><<<dim3(DKV / 128, MROWS / 128), 256, GSMEM_SIZE>>>(
        xh, xl, wvh, wvl, nullptr, avh, avl, MROWS, DKV, DQ);

    // RMSNorm + RoPE (+gain on Q) -> bf16 hi/lo
    rms_rope_split_kernel<<<(MROWS * NH) / 8, 256>>>(Qb, NH, qgain, aqh, aql);
    rms_rope_split_kernel<<<(MROWS * NKV) / 8, 256>>>(Kb, NKV, nullptr, akh, akl);

    // Flash attention (HMMA 3xBF16) -> yh/yl bf16
    flash_attn_mma_kernel<<<dim3(T_ / 128, NH, B_), 256, FA_SMEM>>>(
        aqh, aql, akh, akl, avh, avl, yh, yl);

    // Output projection
    gemm_mma3_kernel<0><<<dim3(DQ / 128, MROWS / 128), 256, GSMEM_SIZE>>>(
        yh, yl, wph, wpl, out, nullptr, nullptr, MROWS, DQ, DQ);
}

// round 13
// speedup vs baseline: 1.0016x; 1.0003x over previous
#include <cuda_runtime.h>
#include <cuda_bf16.h>
#include <math.h>
#include <cstdint>

// Problem constants
#define B_   4
#define T_   2048
#define NH   16
#define NKV  4
#define HD_  128
#define DQ   (NH * HD_)    // 2048
#define DKV  (NKV * HD_)   // 512
#define MROWS (B_ * T_)    // 8192

// ---------------------------------------------------------------------------
// Scratch (device globals; allocations banned)
// ---------------------------------------------------------------------------
__device__ float g_Q[(size_t)MROWS * DQ];    // fp32 Q projection
__device__ float g_K[(size_t)MROWS * DKV];   // fp32 K projection

__device__ __nv_bfloat16 g_xh[(size_t)MROWS * DQ];
__device__ __nv_bfloat16 g_xl[(size_t)MROWS * DQ];
__device__ __nv_bfloat16 g_yh[(size_t)MROWS * DQ];
__device__ __nv_bfloat16 g_yl[(size_t)MROWS * DQ];
__device__ __nv_bfloat16 g_wqh[(size_t)DQ * DQ];
__device__ __nv_bfloat16 g_wql[(size_t)DQ * DQ];
__device__ __nv_bfloat16 g_wkh[(size_t)DKV * DQ];
__device__ __nv_bfloat16 g_wkl[(size_t)DKV * DQ];
__device__ __nv_bfloat16 g_wvh[(size_t)DKV * DQ];
__device__ __nv_bfloat16 g_wvl[(size_t)DKV * DQ];
__device__ __nv_bfloat16 g_wph[(size_t)DQ * DQ];
__device__ __nv_bfloat16 g_wpl[(size_t)DQ * DQ];

// attention operands (hi/lo bf16)
__device__ __nv_bfloat16 g_aqh[(size_t)MROWS * DQ];
__device__ __nv_bfloat16 g_aql[(size_t)MROWS * DQ];
__device__ __nv_bfloat16 g_akh[(size_t)MROWS * DKV];
__device__ __nv_bfloat16 g_akl[(size_t)MROWS * DKV];
__device__ __nv_bfloat16 g_avh[(size_t)MROWS * DKV];
__device__ __nv_bfloat16 g_avl[(size_t)MROWS * DKV];

// ---------------------------------------------------------------------------
// Warp-level MMA helpers (sm_80+ PTX; safe for sm_103 base target)
// ---------------------------------------------------------------------------
__device__ __forceinline__ uint32_t smem_to_u32(const void* smem_ptr) {
    uint32_t addr;
    asm("{ .reg .u64 tmp; cvta.to.shared.u64 tmp, %1; cvt.u32.u64 %0, tmp; }"
        : "=r"(addr) : "l"(smem_ptr));
    return addr;
}

__device__ __forceinline__ void ldsm_x4(uint32_t* r, uint32_t addr) {
    asm volatile("ldmatrix.sync.aligned.m8n8.x4.shared.b16 {%0,%1,%2,%3}, [%4];"
        : "=r"(r[0]), "=r"(r[1]), "=r"(r[2]), "=r"(r[3]) : "r"(addr));
}

__device__ __forceinline__ void ldsm_x4_t(uint32_t* r, uint32_t addr) {
    asm volatile("ldmatrix.sync.aligned.m8n8.x4.trans.shared.b16 {%0,%1,%2,%3}, [%4];"
        : "=r"(r[0]), "=r"(r[1]), "=r"(r[2]), "=r"(r[3]) : "r"(addr));
}

__device__ __forceinline__ void mma_bf16(float* d, const uint32_t* a, const uint32_t* b) {
    asm volatile(
        "mma.sync.aligned.m16n8k16.row.col.f32.bf16.bf16.f32 "
        "{%0,%1,%2,%3}, {%4,%5,%6,%7}, {%8,%9}, {%0,%1,%2,%3};"
        : "+f"(d[0]), "+f"(d[1]), "+f"(d[2]), "+f"(d[3])
        : "r"(a[0]), "r"(a[1]), "r"(a[2]), "r"(a[3]), "r"(b[0]), "r"(b[1]));
}

__device__ __forceinline__ void cp_async16(uint32_t dst, const void* src) {
    asm volatile("cp.async.cg.shared.global [%0], [%1], 16;"
                 :: "r"(dst), "l"(src) : "memory");
}

// split x,y into packed bf16 hi + lo pairs
__device__ __forceinline__ void split_pack(float x, float y, uint32_t& hi, uint32_t& lo) {
    __nv_bfloat16 hx = __float2bfloat16(x);
    __nv_bfloat16 hy = __float2bfloat16(y);
    __nv_bfloat16 lx = __float2bfloat16(x - __bfloat162float(hx));
    __nv_bfloat16 ly = __float2bfloat16(y - __bfloat162float(hy));
    __nv_bfloat162 h2 = __halves2bfloat162(hx, hy);
    __nv_bfloat162 l2 = __halves2bfloat162(lx, ly);
    hi = *(uint32_t*)&h2; lo = *(uint32_t*)&l2;
}

// ---------------------------------------------------------------------------
// fp32 -> bf16 hi/lo split
// ---------------------------------------------------------------------------
__global__ void __launch_bounds__(256) cvt_hilo_kernel(
    const float* __restrict__ x,
    __nv_bfloat16* __restrict__ hi, __nv_bfloat16* __restrict__ lo, int n4)
{
    int i = blockIdx.x * 256 + threadIdx.x;
    if (i >= n4) return;
    float4 v = ((const float4*)x)[i];
    __nv_bfloat16 h[4], l[4];
    h[0] = __float2bfloat16(v.x); l[0] = __float2bfloat16(v.x - __bfloat162float(h[0]));
    h[1] = __float2bfloat16(v.y); l[1] = __float2bfloat16(v.y - __bfloat162float(h[1]));
    h[2] = __float2bfloat16(v.z); l[2] = __float2bfloat16(v.z - __bfloat162float(h[2]));
    h[3] = __float2bfloat16(v.w); l[3] = __float2bfloat16(v.w - __bfloat162float(h[3]));
    *(uint2*)(hi + 4 * (size_t)i) = *(uint2*)h;
    *(uint2*)(lo + 4 * (size_t)i) = *(uint2*)l;
}

// ---------------------------------------------------------------------------
// HMMA 3xBF16 GEMM (NT): C[M,N] = A[M,K] * B[N,K]^T, fp32 accumulate.
// BM=128, BN=128, BK=64. 8 warps (2x4). 3-stage cp.async pipeline, one
// __syncthreads per chunk. OUT_MODE 0: fp32 C; OUT_MODE 1: bf16 hi/lo.
// ---------------------------------------------------------------------------
#define GTILE_BYTES  16384
#define GSTAGE_BYTES (4 * GTILE_BYTES)      // 65536
#define GSMEM_SIZE   (3 * GSTAGE_BYTES)     // 196608

template<int OUT_MODE>
__global__ void __launch_bounds__(256, 1)
gemm_mma3_kernel(const __nv_bfloat16* __restrict__ Ah,
                 const __nv_bfloat16* __restrict__ Al,
                 const __nv_bfloat16* __restrict__ Bh,
                 const __nv_bfloat16* __restrict__ Bl,
                 float* __restrict__ C,
                 __nv_bfloat16* __restrict__ Ch, __nv_bfloat16* __restrict__ Cl,
                 int M, int N, int Kd)
{
    extern __shared__ char smem[];
    const uint32_t sbase = smem_to_u32(smem);
    const int tid = threadIdx.x;
    const int wid = tid >> 5, lane = tid & 31;
    const int wm = wid >> 2, wn = wid & 3;
    const int m0 = blockIdx.y * 128, n0 = blockIdx.x * 128;
    const int nchunk = Kd >> 6;

    const char* gsrc[16];
    uint32_t    soff[16];
#pragma unroll
    for (int i = 0; i < 16; ++i) {
        int gid  = tid + i * 256;
        int tile = gid >> 10;
        int rem  = gid & 1023;
        int row  = rem >> 3;
        int seg  = rem & 7;
        uint32_t off = (uint32_t)(row * 128 + seg * 16);
        soff[i] = (uint32_t)tile * GTILE_BYTES + (off ^ ((off >> 3) & 0x70));
        const char* base =
            (tile == 0) ? (const char*)Ah :
            (tile == 1) ? (const char*)Al :
            (tile == 2) ? (const char*)Bh : (const char*)Bl;
        int r0 = (tile < 2) ? m0 : n0;
        gsrc[i] = base + ((size_t)(r0 + row) * Kd + (size_t)seg * 8) * 2;
    }

    // Prologue: chunks 0 and 1 into stages 0, 1
#pragma unroll
    for (int i = 0; i < 16; ++i) cp_async16(sbase + soff[i], gsrc[i]);
    asm volatile("cp.async.commit_group;" ::: "memory");
#pragma unroll
    for (int i = 0; i < 16; ++i)
        cp_async16(sbase + GSTAGE_BYTES + soff[i], gsrc[i] + 128);
    asm volatile("cp.async.commit_group;" ::: "memory");

    const int a_row_l = (lane & 15);
    const uint32_t a_cb = (uint32_t)((lane >> 4) * 16);
    const int b_row_l = ((lane >> 4) << 3) + (lane & 7);
    const uint32_t b_cb = (uint32_t)(((lane >> 3) & 1) * 16);

    uint32_t aRow[4], aXor[4];
#pragma unroll
    for (int mi = 0; mi < 4; ++mi) {
        int r = wm * 64 + mi * 16 + a_row_l;
        aRow[mi] = (uint32_t)(r * 128);
        aXor[mi] = (uint32_t)((r << 4) & 0x70);
    }
    uint32_t bRow[2], bXor[2];
#pragma unroll
    for (int p = 0; p < 2; ++p) {
        int r = wn * 32 + p * 16 + b_row_l;
        bRow[p] = (uint32_t)(r * 128);
        bXor[p] = (uint32_t)((r << 4) & 0x70);
    }

    float acc[4][4][4];
#pragma unroll
    for (int mi = 0; mi < 4; ++mi)
#pragma unroll
        for (int ni = 0; ni < 4; ++ni)
#pragma unroll
            for (int q = 0; q < 4; ++q) acc[mi][ni][q] = 0.0f;

    int sidx = 0;                 // stage of chunk c
    for (int c = 0; c < nchunk; ++c) {
        if (c + 1 < nchunk) {
            asm volatile("cp.async.wait_group 1;" ::: "memory");
        } else {
            asm volatile("cp.async.wait_group 0;" ::: "memory");
        }
        __syncthreads();

        if (c + 2 < nchunk) {
            int pidx = sidx + 2; if (pidx >= 3) pidx -= 3;
            const uint32_t stn = sbase + (uint32_t)pidx * GSTAGE_BYTES;
            const size_t kb = (size_t)(c + 2) * 128;
#pragma unroll
            for (int i = 0; i < 16; ++i) cp_async16(stn + soff[i], gsrc[i] + kb);
            asm volatile("cp.async.commit_group;" ::: "memory");
        }

        const uint32_t st = sbase + (uint32_t)sidx * GSTAGE_BYTES;
#pragma unroll
        for (int ks = 0; ks < 4; ++ks) {
            const uint32_t kcb = (uint32_t)(ks * 32);
            uint32_t ah[4][4], al[4][4], bh[2][4], bl[2][4];
#pragma unroll
            for (int mi = 0; mi < 4; ++mi) {
                uint32_t col = (kcb + a_cb);
                uint32_t addr = st + aRow[mi] + (col ^ aXor[mi]);
                ldsm_x4(ah[mi], addr);
                ldsm_x4(al[mi], addr + GTILE_BYTES);
            }
#pragma unroll
            for (int p = 0; p < 2; ++p) {
                uint32_t col = (kcb + b_cb);
                uint32_t addr = st + 2 * GTILE_BYTES + bRow[p] + (col ^ bXor[p]);
                ldsm_x4(bh[p], addr);
                ldsm_x4(bl[p], addr + GTILE_BYTES);
            }
#pragma unroll
            for (int mi = 0; mi < 4; ++mi)
#pragma unroll
                for (int ni = 0; ni < 4; ++ni) {
                    const uint32_t* bhf = &bh[ni >> 1][(ni & 1) * 2];
                    const uint32_t* blf = &bl[ni >> 1][(ni & 1) * 2];
                    mma_bf16(acc[mi][ni], ah[mi], bhf);
                    mma_bf16(acc[mi][ni], ah[mi], blf);
                    mma_bf16(acc[mi][ni], al[mi], bhf);
                }
        }
        if (++sidx == 3) sidx = 0;
    }

#pragma unroll
    for (int mi = 0; mi < 4; ++mi) {
        const int gm = m0 + wm * 64 + mi * 16 + (lane >> 2);
#pragma unroll
        for (int ni = 0; ni < 4; ++ni) {
            const int gn = n0 + wn * 32 + ni * 8 + (lane & 3) * 2;
            if (OUT_MODE == 0) {
                float2 v0 = make_float2(acc[mi][ni][0], acc[mi][ni][1]);
                float2 v1 = make_float2(acc[mi][ni][2], acc[mi][ni][3]);
                *(float2*)(C + (size_t)gm * N + gn) = v0;
                *(float2*)(C + (size_t)(gm + 8) * N + gn) = v1;
            } else {
                uint32_t hi, lo;
                split_pack(acc[mi][ni][0], acc[mi][ni][1], hi, lo);
                *(uint32_t*)(Ch + (size_t)gm * N + gn) = hi;
                *(uint32_t*)(Cl + (size_t)gm * N + gn) = lo;
                split_pack(acc[mi][ni][2], acc[mi][ni][3], hi, lo);
                *(uint32_t*)(Ch + (size_t)(gm + 8) * N + gn) = hi;
                *(uint32_t*)(Cl + (size_t)(gm + 8) * N + gn) = lo;
            }
        }
    }
}

// ---------------------------------------------------------------------------
// Fused QK RMSNorm + RoPE (+gain) -> bf16 hi/lo outputs.
// ---------------------------------------------------------------------------
__global__ void __launch_bounds__(256) rms_rope_split_kernel(
    const float* __restrict__ X, int nheads, const float* __restrict__ gain,
    __nv_bfloat16* __restrict__ H, __nv_bfloat16* __restrict__ L)
{
    const int wid = threadIdx.x >> 5, lane = threadIdx.x & 31;
    const long long gid = (long long)blockIdx.x * 8 + wid;
    const int h = (int)(gid % nheads);
    const long long bt = gid / nheads;
    const int t = (int)(bt % T_);

    const long long base = bt * (long long)(nheads * HD_) + (long long)h * HD_;
    const float* p = X + base;
    float x0 = p[lane], x1 = p[lane + 32], x2 = p[lane + 64], x3 = p[lane + 96];

    float ss = x0 * x0 + x1 * x1 + x2 * x2 + x3 * x3;
#pragma unroll
    for (int o = 16; o; o >>= 1) ss += __shfl_xor_sync(0xffffffffu, ss, o);
    const float r = rsqrtf(ss * (1.0f / 128.0f) + 1.1920928955078125e-07f);
    x0 *= r; x1 *= r; x2 *= r; x3 *= r;

    const float Lc = 13.287712379549449f / 64.0f;
    const float tf = (float)t;
    const float a0 = tf * exp2f(-(float)lane * Lc);
    const float a1 = tf * exp2f(-(float)(lane + 32) * Lc);
    const float c0 = cosf(a0), s0 = sinf(a0);
    const float c1 = cosf(a1), s1 = sinf(a1);
    const float g = gain ? gain[h] : 1.0f;

    float y0 = (x0 * c0 - x2 * s0) * g;
    float y2 = (x2 * c0 + x0 * s0) * g;
    float y1 = (x1 * c1 - x3 * s1) * g;
    float y3 = (x3 * c1 + x1 * s1) * g;

    __nv_bfloat16 h0 = __float2bfloat16(y0), h1 = __float2bfloat16(y1);
    __nv_bfloat16 h2 = __float2bfloat16(y2), h3 = __float2bfloat16(y3);
    H[base + lane]      = h0;  L[base + lane]      = __float2bfloat16(y0 - __bfloat162float(h0));
    H[base + lane + 32] = h1;  L[base + lane + 32] = __float2bfloat16(y1 - __bfloat162float(h1));
    H[base + lane + 64] = h2;  L[base + lane + 64] = __float2bfloat16(y2 - __bfloat162float(h2));
    H[base + lane + 96] = h3;  L[base + lane + 96] = __float2bfloat16(y3 - __bfloat162float(h3));
}

// ---------------------------------------------------------------------------
// Flash attention, HMMA 3xBF16, causal, GQA group=4.
// Br=128, Bc=64, 8 warps. 3-stage KV cp.async pipeline; Q staged through
// stage 0 then held in registers. smem = 3 x 64KB stages.
// Stage layout: Kh,Kl,Vh,Vl each 16KB; each tensor: 2 panels x (64 rows x 128B).
// ---------------------------------------------------------------------------
#define FA_STSZ 65536u
#define FA_SMEM (3 * 65536)   // 196608

__global__ void __launch_bounds__(256, 1) flash_attn_mma_kernel(
    const __nv_bfloat16* __restrict__ Qh, const __nv_bfloat16* __restrict__ Ql,
    const __nv_bfloat16* __restrict__ Kh, const __nv_bfloat16* __restrict__ Kl,
    const __nv_bfloat16* __restrict__ Vh, const __nv_bfloat16* __restrict__ Vl,
    __nv_bfloat16* __restrict__ Yh, __nv_bfloat16* __restrict__ Yl)
{
    extern __shared__ char smem[];
    const uint32_t sb = smem_to_u32(smem);
    const int qt = blockIdx.x, h = blockIdx.y, b = blockIdx.z;
    const int kvh = h >> 2;
    const int tid = threadIdx.x, wid = tid >> 5, lane = tid & 31;

    // ---- Q tile via stage 0 (Qh at +0, Ql at +32768), 16 x 16B per thread ----
#pragma unroll
    for (int i = 0; i < 16; ++i) {
        int gid = tid + i * 256;           // 0..4095
        int tensor = gid >> 11;            // 0:Qh 1:Ql
        int rem = gid & 2047;
        int row = rem >> 4;                // 0..127
        int seg = rem & 15;                // 16B seg within 256B row
        int panel = seg >> 3, segp = seg & 7;
        uint32_t off = (uint32_t)(row * 128 + segp * 16);
        uint32_t dst = sb + (uint32_t)tensor * 32768u + (uint32_t)panel * 16384u
                     + (off ^ ((off >> 3) & 0x70));
        const __nv_bfloat16* g = (tensor ? Ql : Qh)
            + ((size_t)(b * T_ + qt * 128 + row) * DQ + h * HD_ + seg * 8);
        cp_async16(dst, g);
    }
    asm volatile("cp.async.commit_group;" ::: "memory");
    asm volatile("cp.async.wait_group 0;" ::: "memory");
    __syncthreads();

    // lane addressing constants
    const int a_row_l = lane & 15;
    const uint32_t a_cb = (uint32_t)((lane >> 4) * 16);
    const int b_row_l = ((lane >> 4) << 3) + (lane & 7);
    const uint32_t b_cb = (uint32_t)(((lane >> 3) & 1) * 16);
    const int v_row_l = lane & 15;
    const uint32_t v_cb = (uint32_t)((lane >> 4) * 16);

    // ---- extract Q fragments (A operand) for 8 k-steps, hi+lo ----
    uint32_t qhf[8][4], qlf[8][4];
    {
        const int arow = wid * 16 + a_row_l;
        const uint32_t axor = (uint32_t)((arow << 4) & 0x70);
        const uint32_t abase = sb + (uint32_t)(arow * 128);
#pragma unroll
        for (int ks = 0; ks < 8; ++ks) {
            uint32_t colb = (uint32_t)((ks & 3) * 32) + a_cb;
            uint32_t ad = abase + (uint32_t)(ks >> 2) * 16384u + (colb ^ axor);
            ldsm_x4(qhf[ks], ad);
            ldsm_x4(qlf[ks], ad + 32768u);
        }
    }
    __syncthreads();   // everyone done reading Q from stage 0

    // ---- KV stage loader ----
    auto issue_kv = [&](int kt, uint32_t stagebase) {
#pragma unroll
        for (int i = 0; i < 16; ++i) {
            int gid = tid + i * 256;           // 0..4095
            int tensor = gid >> 10;            // 0:Kh 1:Kl 2:Vh 3:Vl
            int rem = gid & 1023;
            int row = rem >> 4;                // 0..63
            int seg = rem & 15;
            int panel = seg >> 3, segp = seg & 7;
            uint32_t off = (uint32_t)(row * 128 + segp * 16);
            uint32_t dst = stagebase + (uint32_t)tensor * 16384u + (uint32_t)panel * 8192u
                         + (off ^ ((off >> 3) & 0x70));
            const __nv_bfloat16* base =
                (tensor == 0) ? Kh : (tensor == 1) ? Kl : (tensor == 2) ? Vh : Vl;
            const __nv_bfloat16* g = base
                + ((size_t)(b * T_ + kt * 64 + row) * DKV + kvh * HD_ + seg * 8);
            cp_async16(dst, g);
        }
        asm volatile("cp.async.commit_group;" ::: "memory");
    };

    const int ktmax = 2 * qt + 1;
    issue_kv(0, sb);
    issue_kv(1, sb + FA_STSZ);

    float m0 = -1e30f, m1 = -1e30f, l0 = 0.0f, l1 = 0.0f;
    float O[16][4];
#pragma unroll
    for (int nt = 0; nt < 16; ++nt)
#pragma unroll
        for (int q = 0; q < 4; ++q) O[nt][q] = 0.0f;

    const int r0g = qt * 128 + wid * 16 + (lane >> 2);
    const float scale = 0.08838834764831845f;

    int sidx = 0;
    for (int kt = 0; kt <= ktmax; ++kt) {
        if (kt + 1 <= ktmax) {
            asm volatile("cp.async.wait_group 1;" ::: "memory");
        } else {
            asm volatile("cp.async.wait_group 0;" ::: "memory");
        }
        __syncthreads();

        if (kt + 2 <= ktmax) {
            int pidx = sidx + 2; if (pidx >= 3) pidx -= 3;
            issue_kv(kt + 2, sb + (uint32_t)pidx * FA_STSZ);
        }

        const uint32_t stg = sb + (uint32_t)sidx * FA_STSZ;

        // ---- S = Q K^T (3 terms) ----
        float sacc[8][4];
#pragma unroll
        for (int nt = 0; nt < 8; ++nt)
#pragma unroll
            for (int q = 0; q < 4; ++q) sacc[nt][q] = 0.0f;

#pragma unroll
        for (int ks = 0; ks < 8; ++ks) {
            const uint32_t pbase = stg + (uint32_t)(ks >> 2) * 8192u;
            const uint32_t colb = (uint32_t)((ks & 3) * 32) + b_cb;
#pragma unroll
            for (int p = 0; p < 4; ++p) {
                const int row = p * 16 + b_row_l;
                const uint32_t ad = pbase + (uint32_t)(row * 128)
                                  + (colb ^ (uint32_t)((row << 4) & 0x70));
                uint32_t kh4[4], kl4[4];
                ldsm_x4(kh4, ad);
                ldsm_x4(kl4, ad + 16384u);
                mma_bf16(sacc[2 * p],     qhf[ks], kh4);
                mma_bf16(sacc[2 * p],     qhf[ks], kl4);
                mma_bf16(sacc[2 * p],     qlf[ks], kh4);
                mma_bf16(sacc[2 * p + 1], qhf[ks], kh4 + 2);
                mma_bf16(sacc[2 * p + 1], qhf[ks], kl4 + 2);
                mma_bf16(sacc[2 * p + 1], qlf[ks], kh4 + 2);
            }
        }

        // ---- scale + causal mask ----
        const int cbase = kt * 64 + (lane & 3) * 2;
        const bool need_mask = (kt >= 2 * qt);
#pragma unroll
        for (int nt = 0; nt < 8; ++nt) {
#pragma unroll
            for (int c = 0; c < 2; ++c) {
                const int col = cbase + nt * 8 + c;
                float v0 = sacc[nt][c] * scale;
                float v1 = sacc[nt][2 + c] * scale;
                if (need_mask) {
                    if (col > r0g)     v0 = -1e30f;
                    if (col > r0g + 8) v1 = -1e30f;
                }
                sacc[nt][c] = v0;
                sacc[nt][2 + c] = v1;
            }
        }

        // ---- online softmax ----
        float mx0 = -1e30f, mx1 = -1e30f;
#pragma unroll
        for (int nt = 0; nt < 8; ++nt) {
            mx0 = fmaxf(mx0, fmaxf(sacc[nt][0], sacc[nt][1]));
            mx1 = fmaxf(mx1, fmaxf(sacc[nt][2], sacc[nt][3]));
        }
        mx0 = fmaxf(mx0, __shfl_xor_sync(0xffffffffu, mx0, 1));
        mx0 = fmaxf(mx0, __shfl_xor_sync(0xffffffffu, mx0, 2));
        mx1 = fmaxf(mx1, __shfl_xor_sync(0xffffffffu, mx1, 1));
        mx1 = fmaxf(mx1, __shfl_xor_sync(0xffffffffu, mx1, 2));
        const float mn0 = fmaxf(m0, mx0), mn1 = fmaxf(m1, mx1);
        const float al0 = __expf(m0 - mn0), al1 = __expf(m1 - mn1);
        m0 = mn0; m1 = mn1;

        float rs0 = 0.0f, rs1 = 0.0f;
#pragma unroll
        for (int nt = 0; nt < 8; ++nt) {
            float p0 = __expf(sacc[nt][0] - mn0);
            float p1 = __expf(sacc[nt][1] - mn0);
            float p2 = __expf(sacc[nt][2] - mn1);
            float p3 = __expf(sacc[nt][3] - mn1);
            sacc[nt][0] = p0; sacc[nt][1] = p1; sacc[nt][2] = p2; sacc[nt][3] = p3;
            rs0 += p0 + p1; rs1 += p2 + p3;
        }
        rs0 += __shfl_xor_sync(0xffffffffu, rs0, 1);
        rs0 += __shfl_xor_sync(0xffffffffu, rs0, 2);
        rs1 += __shfl_xor_sync(0xffffffffu, rs1, 1);
        rs1 += __shfl_xor_sync(0xffffffffu, rs1, 2);
        l0 = l0 * al0 + rs0;
        l1 = l1 * al1 + rs1;

#pragma unroll
        for (int nt = 0; nt < 16; ++nt) {
            O[nt][0] *= al0; O[nt][1] *= al0;
            O[nt][2] *= al1; O[nt][3] *= al1;
        }

        // ---- P fragments (hi/lo bf16), A-operand layout ----
        uint32_t pah[4][4], pal[4][4];
#pragma unroll
        for (int kk = 0; kk < 4; ++kk) {
            const int t0 = 2 * kk, t1 = 2 * kk + 1;
            split_pack(sacc[t0][0], sacc[t0][1], pah[kk][0], pal[kk][0]);
            split_pack(sacc[t0][2], sacc[t0][3], pah[kk][1], pal[kk][1]);
            split_pack(sacc[t1][0], sacc[t1][1], pah[kk][2], pal[kk][2]);
            split_pack(sacc[t1][2], sacc[t1][3], pah[kk][3], pal[kk][3]);
        }

        // ---- O += P V (3 terms) ----
#pragma unroll
        for (int kk = 0; kk < 4; ++kk) {
            const int rowl = kk * 16 + v_row_l;
            const uint32_t rbase = stg + 32768u + (uint32_t)(rowl * 128);
            const uint32_t rxor = (uint32_t)((rowl << 4) & 0x70);
#pragma unroll
            for (int j = 0; j < 8; ++j) {
                const uint32_t colb = (uint32_t)((j & 3) * 32) + v_cb;
                const uint32_t ad = rbase + (uint32_t)(j >> 2) * 8192u + (colb ^ rxor);
                uint32_t vh4[4], vl4[4];
                ldsm_x4_t(vh4, ad);
                ldsm_x4_t(vl4, ad + 16384u);
                mma_bf16(O[2 * j],     pah[kk], vh4);
                mma_bf16(O[2 * j],     pah[kk], vl4);
                mma_bf16(O[2 * j],     pal[kk], vh4);
                mma_bf16(O[2 * j + 1], pah[kk], vh4 + 2);
                mma_bf16(O[2 * j + 1], pah[kk], vl4 + 2);
                mma_bf16(O[2 * j + 1], pal[kk], vh4 + 2);
            }
        }
        if (++sidx == 3) sidx = 0;
    }

    // ---- epilogue: normalize, split hi/lo, write bf16 ----
    const float inv0 = 1.0f / l0, inv1 = 1.0f / l1;
    const size_t tok0 = (size_t)(b * T_ + qt * 128 + wid * 16 + (lane >> 2));
    const int colb = h * HD_ + (lane & 3) * 2;
#pragma unroll
    for (int nt = 0; nt < 16; ++nt) {
        uint32_t hi, lo;
        const size_t idx0 = tok0 * DQ + colb + nt * 8;
        split_pack(O[nt][0] * inv0, O[nt][1] * inv0, hi, lo);
        *(uint32_t*)(Yh + idx0) = hi;
        *(uint32_t*)(Yl + idx0) = lo;
        const size_t idx1 = idx0 + (size_t)8 * DQ;
        split_pack(O[nt][2] * inv1, O[nt][3] * inv1, hi, lo);
        *(uint32_t*)(Yh + idx1) = hi;
        *(uint32_t*)(Yl + idx1) = lo;
    }
}

// ---------------------------------------------------------------------------
// Launch
// ---------------------------------------------------------------------------
extern "C" void kernel_launch(void* const* d_in, const int* in_sizes, int n_in,
                              void* d_out, int out_size)
{
    const float* x     = (const float*)d_in[0];
    const float* Wq    = (const float*)d_in[1];
    const float* Wk    = (const float*)d_in[2];
    const float* Wv    = (const float*)d_in[3];
    const float* Wproj = (const float*)d_in[4];
    const float* qgain = (const float*)d_in[5];
    float* out = (float*)d_out;

    float *Qb, *Kb;
    cudaGetSymbolAddress((void**)&Qb, g_Q);
    cudaGetSymbolAddress((void**)&Kb, g_K);
    __nv_bfloat16 *xh, *xl, *yh, *yl, *wqh, *wql, *wkh, *wkl, *wvh, *wvl, *wph, *wpl;
    __nv_bfloat16 *aqh, *aql, *akh, *akl, *avh, *avl;
    cudaGetSymbolAddress((void**)&xh,  g_xh);
    cudaGetSymbolAddress((void**)&xl,  g_xl);
    cudaGetSymbolAddress((void**)&yh,  g_yh);
    cudaGetSymbolAddress((void**)&yl,  g_yl);
    cudaGetSymbolAddress((void**)&wqh, g_wqh);
    cudaGetSymbolAddress((void**)&wql, g_wql);
    cudaGetSymbolAddress((void**)&wkh, g_wkh);
    cudaGetSymbolAddress((void**)&wkl, g_wkl);
    cudaGetSymbolAddress((void**)&wvh, g_wvh);
    cudaGetSymbolAddress((void**)&wvl, g_wvl);
    cudaGetSymbolAddress((void**)&wph, g_wph);
    cudaGetSymbolAddress((void**)&wpl, g_wpl);
    cudaGetSymbolAddress((void**)&aqh, g_aqh);
    cudaGetSymbolAddress((void**)&aql, g_aql);
    cudaGetSymbolAddress((void**)&akh, g_akh);
    cudaGetSymbolAddress((void**)&akl, g_akl);
    cudaGetSymbolAddress((void**)&avh, g_avh);
    cudaGetSymbolAddress((void**)&avl, g_avl);

    cudaFuncSetAttribute(gemm_mma3_kernel<0>,
                         cudaFuncAttributeMaxDynamicSharedMemorySize, GSMEM_SIZE);
    cudaFuncSetAttribute(gemm_mma3_kernel<1>,
                         cudaFuncAttributeMaxDynamicSharedMemorySize, GSMEM_SIZE);
    cudaFuncSetAttribute(flash_attn_mma_kernel,
                         cudaFuncAttributeMaxDynamicSharedMemorySize, FA_SMEM);

    // Convert inputs to bf16 hi/lo
    cvt_hilo_kernel<<<(MROWS * DQ / 4 + 255) / 256, 256>>>(x, xh, xl, MROWS * DQ / 4);
    cvt_hilo_kernel<<<(DQ * DQ / 4 + 255) / 256, 256>>>(Wq, wqh, wql, DQ * DQ / 4);
    cvt_hilo_kernel<<<(DKV * DQ / 4 + 255) / 256, 256>>>(Wk, wkh, wkl, DKV * DQ / 4);
    cvt_hilo_kernel<<<(DKV * DQ / 4 + 255) / 256, 256>>>(Wv, wvh, wvl, DKV * DQ / 4);
    cvt_hilo_kernel<<<(DQ * DQ / 4 + 255) / 256, 256>>>(Wproj, wph, wpl, DQ * DQ / 4);

    // QKV projections on HMMA tensor cores (3xBF16)
    gemm_mma3_kernel<0><<<dim3(DQ / 128,  MROWS / 128), 256, GSMEM_SIZE>>>(
        xh, xl, wqh, wql, Qb, nullptr, nullptr, MROWS, DQ, DQ);
    gemm_mma3_kernel<0><<<dim3(DKV / 128, MROWS / 128), 256, GSMEM_SIZE>>>(
        xh, xl, wkh, wkl, Kb, nullptr, nullptr, MROWS, DKV, DQ);
    // V projection writes bf16 hi/lo directly (no fp32 round-trip)
    gemm_mma3_kernel<1><<<dim3(DKV / 128, MROWS / 128), 256, GSMEM_SIZE>>>(
        xh, xl, wvh, wvl, nullptr, avh, avl, MROWS, DKV, DQ);

    // RMSNorm + RoPE (+gain on Q) -> bf16 hi/lo
    rms_rope_split_kernel<<<(MROWS * NH) / 8, 256>>>(Qb, NH, qgain, aqh, aql);
    rms_rope_split_kernel<<<(MROWS * NKV) / 8, 256>>>(Kb, NKV, nullptr, akh, akl);

    // Flash attention (HMMA 3xBF16) -> yh/yl bf16
    flash_attn_mma_kernel<<<dim3(T_ / 128, NH, B_), 256, FA_SMEM>>>(
        aqh, aql, akh, akl, avh, avl, yh, yl);

    // Output projection
    gemm_mma3_kernel<0><<<dim3(DQ / 128, MROWS / 128), 256, GSMEM_SIZE>>>(
        yh, yl, wph, wpl, out, nullptr, nullptr, MROWS, DQ, DQ);
}

// round 14
// speedup vs baseline: 1.0114x; 1.0097x over previous
#include <cuda_runtime.h>
#include <cuda_bf16.h>
#include <math.h>
#include <cstdint>

// Problem constants
#define B_   4
#define T_   2048
#define NH   16
#define NKV  4
#define HD_  128
#define DQ   (NH * HD_)    // 2048
#define DKV  (NKV * HD_)   // 512
#define MROWS (B_ * T_)    // 8192

// ---------------------------------------------------------------------------
// Scratch (device globals; allocations banned)
// ---------------------------------------------------------------------------
__device__ float g_Q[(size_t)MROWS * DQ];    // fp32 Q projection
__device__ float g_K[(size_t)MROWS * DKV];   // fp32 K projection

__device__ __nv_bfloat16 g_xh[(size_t)MROWS * DQ];
__device__ __nv_bfloat16 g_xl[(size_t)MROWS * DQ];
__device__ __nv_bfloat16 g_yh[(size_t)MROWS * DQ];
__device__ __nv_bfloat16 g_yl[(size_t)MROWS * DQ];
__device__ __nv_bfloat16 g_wqh[(size_t)DQ * DQ];
__device__ __nv_bfloat16 g_wql[(size_t)DQ * DQ];
__device__ __nv_bfloat16 g_wkh[(size_t)DKV * DQ];
__device__ __nv_bfloat16 g_wkl[(size_t)DKV * DQ];
__device__ __nv_bfloat16 g_wvh[(size_t)DKV * DQ];
__device__ __nv_bfloat16 g_wvl[(size_t)DKV * DQ];
__device__ __nv_bfloat16 g_wph[(size_t)DQ * DQ];
__device__ __nv_bfloat16 g_wpl[(size_t)DQ * DQ];

// attention operands (hi/lo bf16)
__device__ __nv_bfloat16 g_aqh[(size_t)MROWS * DQ];
__device__ __nv_bfloat16 g_aql[(size_t)MROWS * DQ];
__device__ __nv_bfloat16 g_akh[(size_t)MROWS * DKV];
__device__ __nv_bfloat16 g_akl[(size_t)MROWS * DKV];
__device__ __nv_bfloat16 g_avh[(size_t)MROWS * DKV];
__device__ __nv_bfloat16 g_avl[(size_t)MROWS * DKV];

// ---------------------------------------------------------------------------
// Warp-level MMA helpers
// ---------------------------------------------------------------------------
__device__ __forceinline__ uint32_t smem_to_u32(const void* smem_ptr) {
    uint32_t addr;
    asm("{ .reg .u64 tmp; cvta.to.shared.u64 tmp, %1; cvt.u32.u64 %0, tmp; }"
        : "=r"(addr) : "l"(smem_ptr));
    return addr;
}

__device__ __forceinline__ void ldsm_x4(uint32_t* r, uint32_t addr) {
    asm volatile("ldmatrix.sync.aligned.m8n8.x4.shared.b16 {%0,%1,%2,%3}, [%4];"
        : "=r"(r[0]), "=r"(r[1]), "=r"(r[2]), "=r"(r[3]) : "r"(addr));
}

__device__ __forceinline__ void ldsm_x4_t(uint32_t* r, uint32_t addr) {
    asm volatile("ldmatrix.sync.aligned.m8n8.x4.trans.shared.b16 {%0,%1,%2,%3}, [%4];"
        : "=r"(r[0]), "=r"(r[1]), "=r"(r[2]), "=r"(r[3]) : "r"(addr));
}

// NOTE: not volatile — register-only op, deps carried by constraints, so
// ptxas is free to software-pipeline/interleave independent MMAs.
__device__ __forceinline__ void mma_bf16(float* d, const uint32_t* a, const uint32_t* b) {
    asm("mma.sync.aligned.m16n8k16.row.col.f32.bf16.bf16.f32 "
        "{%0,%1,%2,%3}, {%4,%5,%6,%7}, {%8,%9}, {%0,%1,%2,%3};"
        : "+f"(d[0]), "+f"(d[1]), "+f"(d[2]), "+f"(d[3])
        : "r"(a[0]), "r"(a[1]), "r"(a[2]), "r"(a[3]), "r"(b[0]), "r"(b[1]));
}

__device__ __forceinline__ void cp_async16(uint32_t dst, const void* src) {
    asm volatile("cp.async.cg.shared.global [%0], [%1], 16;"
                 :: "r"(dst), "l"(src) : "memory");
}

// split x,y into packed bf16 hi + lo pairs
__device__ __forceinline__ void split_pack(float x, float y, uint32_t& hi, uint32_t& lo) {
    __nv_bfloat16 hx = __float2bfloat16(x);
    __nv_bfloat16 hy = __float2bfloat16(y);
    __nv_bfloat16 lx = __float2bfloat16(x - __bfloat162float(hx));
    __nv_bfloat16 ly = __float2bfloat16(y - __bfloat162float(hy));
    __nv_bfloat162 h2 = __halves2bfloat162(hx, hy);
    __nv_bfloat162 l2 = __halves2bfloat162(lx, ly);
    hi = *(uint32_t*)&h2; lo = *(uint32_t*)&l2;
}

// ---------------------------------------------------------------------------
// fp32 -> bf16 hi/lo split
// ---------------------------------------------------------------------------
__global__ void __launch_bounds__(256) cvt_hilo_kernel(
    const float* __restrict__ x,
    __nv_bfloat16* __restrict__ hi, __nv_bfloat16* __restrict__ lo, int n4)
{
    int i = blockIdx.x * 256 + threadIdx.x;
    if (i >= n4) return;
    float4 v = ((const float4*)x)[i];
    __nv_bfloat16 h[4], l[4];
    h[0] = __float2bfloat16(v.x); l[0] = __float2bfloat16(v.x - __bfloat162float(h[0]));
    h[1] = __float2bfloat16(v.y); l[1] = __float2bfloat16(v.y - __bfloat162float(h[1]));
    h[2] = __float2bfloat16(v.z); l[2] = __float2bfloat16(v.z - __bfloat162float(h[2]));
    h[3] = __float2bfloat16(v.w); l[3] = __float2bfloat16(v.w - __bfloat162float(h[3]));
    *(uint2*)(hi + 4 * (size_t)i) = *(uint2*)h;
    *(uint2*)(lo + 4 * (size_t)i) = *(uint2*)l;
}

// ---------------------------------------------------------------------------
// HMMA 3xBF16 GEMM (NT): C[M,N] = A[M,K] * B[N,K]^T, fp32 accumulate.
// BM=128, BN=128, BK=64. 8 warps (2x4). 3-stage cp.async pipeline.
// MMA issue is TERM-MAJOR: all 16 (mi,ni) accumulators per term, so the
// same-accumulator reuse distance is 16 MMAs (no RAW stalls).
// ---------------------------------------------------------------------------
#define GTILE_BYTES  16384
#define GSTAGE_BYTES (4 * GTILE_BYTES)      // 65536
#define GSMEM_SIZE   (3 * GSTAGE_BYTES)     // 196608

template<int OUT_MODE>
__global__ void __launch_bounds__(256, 1)
gemm_mma3_kernel(const __nv_bfloat16* __restrict__ Ah,
                 const __nv_bfloat16* __restrict__ Al,
                 const __nv_bfloat16* __restrict__ Bh,
                 const __nv_bfloat16* __restrict__ Bl,
                 float* __restrict__ C,
                 __nv_bfloat16* __restrict__ Ch, __nv_bfloat16* __restrict__ Cl,
                 int M, int N, int Kd)
{
    extern __shared__ char smem[];
    const uint32_t sbase = smem_to_u32(smem);
    const int tid = threadIdx.x;
    const int wid = tid >> 5, lane = tid & 31;
    const int wm = wid >> 2, wn = wid & 3;
    const int m0 = blockIdx.y * 128, n0 = blockIdx.x * 128;
    const int nchunk = Kd >> 6;

    const char* gsrc[16];
    uint32_t    soff[16];
#pragma unroll
    for (int i = 0; i < 16; ++i) {
        int gid  = tid + i * 256;
        int tile = gid >> 10;
        int rem  = gid & 1023;
        int row  = rem >> 3;
        int seg  = rem & 7;
        uint32_t off = (uint32_t)(row * 128 + seg * 16);
        soff[i] = (uint32_t)tile * GTILE_BYTES + (off ^ ((off >> 3) & 0x70));
        const char* base =
            (tile == 0) ? (const char*)Ah :
            (tile == 1) ? (const char*)Al :
            (tile == 2) ? (const char*)Bh : (const char*)Bl;
        int r0 = (tile < 2) ? m0 : n0;
        gsrc[i] = base + ((size_t)(r0 + row) * Kd + (size_t)seg * 8) * 2;
    }

    // Prologue: chunks 0 and 1 into stages 0, 1
#pragma unroll
    for (int i = 0; i < 16; ++i) cp_async16(sbase + soff[i], gsrc[i]);
    asm volatile("cp.async.commit_group;" ::: "memory");
#pragma unroll
    for (int i = 0; i < 16; ++i)
        cp_async16(sbase + GSTAGE_BYTES + soff[i], gsrc[i] + 128);
    asm volatile("cp.async.commit_group;" ::: "memory");

    const int a_row_l = (lane & 15);
    const uint32_t a_cb = (uint32_t)((lane >> 4) * 16);
    const int b_row_l = ((lane >> 4) << 3) + (lane & 7);
    const uint32_t b_cb = (uint32_t)(((lane >> 3) & 1) * 16);

    uint32_t aRow[4], aXor[4];
#pragma unroll
    for (int mi = 0; mi < 4; ++mi) {
        int r = wm * 64 + mi * 16 + a_row_l;
        aRow[mi] = (uint32_t)(r * 128);
        aXor[mi] = (uint32_t)((r << 4) & 0x70);
    }
    uint32_t bRow[2], bXor[2];
#pragma unroll
    for (int p = 0; p < 2; ++p) {
        int r = wn * 32 + p * 16 + b_row_l;
        bRow[p] = (uint32_t)(r * 128);
        bXor[p] = (uint32_t)((r << 4) & 0x70);
    }

    float acc[4][4][4];
#pragma unroll
    for (int mi = 0; mi < 4; ++mi)
#pragma unroll
        for (int ni = 0; ni < 4; ++ni)
#pragma unroll
            for (int q = 0; q < 4; ++q) acc[mi][ni][q] = 0.0f;

    int sidx = 0;                 // stage of chunk c
    for (int c = 0; c < nchunk; ++c) {
        if (c + 1 < nchunk) {
            asm volatile("cp.async.wait_group 1;" ::: "memory");
        } else {
            asm volatile("cp.async.wait_group 0;" ::: "memory");
        }
        __syncthreads();

        if (c + 2 < nchunk) {
            int pidx = sidx + 2; if (pidx >= 3) pidx -= 3;
            const uint32_t stn = sbase + (uint32_t)pidx * GSTAGE_BYTES;
            const size_t kb = (size_t)(c + 2) * 128;
#pragma unroll
            for (int i = 0; i < 16; ++i) cp_async16(stn + soff[i], gsrc[i] + kb);
            asm volatile("cp.async.commit_group;" ::: "memory");
        }

        const uint32_t st = sbase + (uint32_t)sidx * GSTAGE_BYTES;
#pragma unroll
        for (int ks = 0; ks < 4; ++ks) {
            const uint32_t kcb = (uint32_t)(ks * 32);
            uint32_t ah[4][4], al[4][4], bh[2][4], bl[2][4];
#pragma unroll
            for (int mi = 0; mi < 4; ++mi) {
                uint32_t col = (kcb + a_cb);
                uint32_t addr = st + aRow[mi] + (col ^ aXor[mi]);
                ldsm_x4(ah[mi], addr);
                ldsm_x4(al[mi], addr + GTILE_BYTES);
            }
#pragma unroll
            for (int p = 0; p < 2; ++p) {
                uint32_t col = (kcb + b_cb);
                uint32_t addr = st + 2 * GTILE_BYTES + bRow[p] + (col ^ bXor[p]);
                ldsm_x4(bh[p], addr);
                ldsm_x4(bl[p], addr + GTILE_BYTES);
            }
            // term-major: 16 independent accumulators between reuses
#pragma unroll
            for (int mi = 0; mi < 4; ++mi)
#pragma unroll
                for (int ni = 0; ni < 4; ++ni)
                    mma_bf16(acc[mi][ni], ah[mi], &bh[ni >> 1][(ni & 1) * 2]);
#pragma unroll
            for (int mi = 0; mi < 4; ++mi)
#pragma unroll
                for (int ni = 0; ni < 4; ++ni)
                    mma_bf16(acc[mi][ni], ah[mi], &bl[ni >> 1][(ni & 1) * 2]);
#pragma unroll
            for (int mi = 0; mi < 4; ++mi)
#pragma unroll
                for (int ni = 0; ni < 4; ++ni)
                    mma_bf16(acc[mi][ni], al[mi], &bh[ni >> 1][(ni & 1) * 2]);
        }
        if (++sidx == 3) sidx = 0;
    }

#pragma unroll
    for (int mi = 0; mi < 4; ++mi) {
        const int gm = m0 + wm * 64 + mi * 16 + (lane >> 2);
#pragma unroll
        for (int ni = 0; ni < 4; ++ni) {
            const int gn = n0 + wn * 32 + ni * 8 + (lane & 3) * 2;
            if (OUT_MODE == 0) {
                float2 v0 = make_float2(acc[mi][ni][0], acc[mi][ni][1]);
                float2 v1 = make_float2(acc[mi][ni][2], acc[mi][ni][3]);
                *(float2*)(C + (size_t)gm * N + gn) = v0;
                *(float2*)(C + (size_t)(gm + 8) * N + gn) = v1;
            } else {
                uint32_t hi, lo;
                split_pack(acc[mi][ni][0], acc[mi][ni][1], hi, lo);
                *(uint32_t*)(Ch + (size_t)gm * N + gn) = hi;
                *(uint32_t*)(Cl + (size_t)gm * N + gn) = lo;
                split_pack(acc[mi][ni][2], acc[mi][ni][3], hi, lo);
                *(uint32_t*)(Ch + (size_t)(gm + 8) * N + gn) = hi;
                *(uint32_t*)(Cl + (size_t)(gm + 8) * N + gn) = lo;
            }
        }
    }
}

// ---------------------------------------------------------------------------
// Fused QK RMSNorm + RoPE (+gain) -> bf16 hi/lo outputs.
// ---------------------------------------------------------------------------
__global__ void __launch_bounds__(256) rms_rope_split_kernel(
    const float* __restrict__ X, int nheads, const float* __restrict__ gain,
    __nv_bfloat16* __restrict__ H, __nv_bfloat16* __restrict__ L)
{
    const int wid = threadIdx.x >> 5, lane = threadIdx.x & 31;
    const long long gid = (long long)blockIdx.x * 8 + wid;
    const int h = (int)(gid % nheads);
    const long long bt = gid / nheads;
    const int t = (int)(bt % T_);

    const long long base = bt * (long long)(nheads * HD_) + (long long)h * HD_;
    const float* p = X + base;
    float x0 = p[lane], x1 = p[lane + 32], x2 = p[lane + 64], x3 = p[lane + 96];

    float ss = x0 * x0 + x1 * x1 + x2 * x2 + x3 * x3;
#pragma unroll
    for (int o = 16; o; o >>= 1) ss += __shfl_xor_sync(0xffffffffu, ss, o);
    const float r = rsqrtf(ss * (1.0f / 128.0f) + 1.1920928955078125e-07f);
    x0 *= r; x1 *= r; x2 *= r; x3 *= r;

    const float Lc = 13.287712379549449f / 64.0f;
    const float tf = (float)t;
    const float a0 = tf * exp2f(-(float)lane * Lc);
    const float a1 = tf * exp2f(-(float)(lane + 32) * Lc);
    const float c0 = cosf(a0), s0 = sinf(a0);
    const float c1 = cosf(a1), s1 = sinf(a1);
    const float g = gain ? gain[h] : 1.0f;

    float y0 = (x0 * c0 - x2 * s0) * g;
    float y2 = (x2 * c0 + x0 * s0) * g;
    float y1 = (x1 * c1 - x3 * s1) * g;
    float y3 = (x3 * c1 + x1 * s1) * g;

    __nv_bfloat16 h0 = __float2bfloat16(y0), h1 = __float2bfloat16(y1);
    __nv_bfloat16 h2 = __float2bfloat16(y2), h3 = __float2bfloat16(y3);
    H[base + lane]      = h0;  L[base + lane]      = __float2bfloat16(y0 - __bfloat162float(h0));
    H[base + lane + 32] = h1;  L[base + lane + 32] = __float2bfloat16(y1 - __bfloat162float(h1));
    H[base + lane + 64] = h2;  L[base + lane + 64] = __float2bfloat16(y2 - __bfloat162float(h2));
    H[base + lane + 96] = h3;  L[base + lane + 96] = __float2bfloat16(y3 - __bfloat162float(h3));
}

// ---------------------------------------------------------------------------
// Flash attention, HMMA 3xBF16, causal, GQA group=4.
// Br=128, Bc=64, 8 warps. 3-stage KV cp.async pipeline; Q in registers.
// MMA issue is TERM-MAJOR inside each k-step / kk-step so the same-
// accumulator reuse distance is 8 MMAs.
// ---------------------------------------------------------------------------
#define FA_STSZ 65536u
#define FA_SMEM (3 * 65536)   // 196608

__global__ void __launch_bounds__(256, 1) flash_attn_mma_kernel(
    const __nv_bfloat16* __restrict__ Qh, const __nv_bfloat16* __restrict__ Ql,
    const __nv_bfloat16* __restrict__ Kh, const __nv_bfloat16* __restrict__ Kl,
    const __nv_bfloat16* __restrict__ Vh, const __nv_bfloat16* __restrict__ Vl,
    __nv_bfloat16* __restrict__ Yh, __nv_bfloat16* __restrict__ Yl)
{
    extern __shared__ char smem[];
    const uint32_t sb = smem_to_u32(smem);
    const int qt = blockIdx.x, h = blockIdx.y, b = blockIdx.z;
    const int kvh = h >> 2;
    const int tid = threadIdx.x, wid = tid >> 5, lane = tid & 31;

    // ---- Q tile via stage 0 (Qh at +0, Ql at +32768), 16 x 16B per thread ----
#pragma unroll
    for (int i = 0; i < 16; ++i) {
        int gid = tid + i * 256;
        int tensor = gid >> 11;
        int rem = gid & 2047;
        int row = rem >> 4;
        int seg = rem & 15;
        int panel = seg >> 3, segp = seg & 7;
        uint32_t off = (uint32_t)(row * 128 + segp * 16);
        uint32_t dst = sb + (uint32_t)tensor * 32768u + (uint32_t)panel * 16384u
                     + (off ^ ((off >> 3) & 0x70));
        const __nv_bfloat16* g = (tensor ? Ql : Qh)
            + ((size_t)(b * T_ + qt * 128 + row) * DQ + h * HD_ + seg * 8);
        cp_async16(dst, g);
    }
    asm volatile("cp.async.commit_group;" ::: "memory");
    asm volatile("cp.async.wait_group 0;" ::: "memory");
    __syncthreads();

    // lane addressing constants
    const int a_row_l = lane & 15;
    const uint32_t a_cb = (uint32_t)((lane >> 4) * 16);
    const int b_row_l = ((lane >> 4) << 3) + (lane & 7);
    const uint32_t b_cb = (uint32_t)(((lane >> 3) & 1) * 16);
    const int v_row_l = lane & 15;
    const uint32_t v_cb = (uint32_t)((lane >> 4) * 16);

    // ---- extract Q fragments (A operand) for 8 k-steps, hi+lo ----
    uint32_t qhf[8][4], qlf[8][4];
    {
        const int arow = wid * 16 + a_row_l;
        const uint32_t axor = (uint32_t)((arow << 4) & 0x70);
        const uint32_t abase = sb + (uint32_t)(arow * 128);
#pragma unroll
        for (int ks = 0; ks < 8; ++ks) {
            uint32_t colb = (uint32_t)((ks & 3) * 32) + a_cb;
            uint32_t ad = abase + (uint32_t)(ks >> 2) * 16384u + (colb ^ axor);
            ldsm_x4(qhf[ks], ad);
            ldsm_x4(qlf[ks], ad + 32768u);
        }
    }
    __syncthreads();   // everyone done reading Q from stage 0

    // ---- KV stage loader ----
    auto issue_kv = [&](int kt, uint32_t stagebase) {
#pragma unroll
        for (int i = 0; i < 16; ++i) {
            int gid = tid + i * 256;
            int tensor = gid >> 10;
            int rem = gid & 1023;
            int row = rem >> 4;
            int seg = rem & 15;
            int panel = seg >> 3, segp = seg & 7;
            uint32_t off = (uint32_t)(row * 128 + segp * 16);
            uint32_t dst = stagebase + (uint32_t)tensor * 16384u + (uint32_t)panel * 8192u
                         + (off ^ ((off >> 3) & 0x70));
            const __nv_bfloat16* base =
                (tensor == 0) ? Kh : (tensor == 1) ? Kl : (tensor == 2) ? Vh : Vl;
            const __nv_bfloat16* g = base
                + ((size_t)(b * T_ + kt * 64 + row) * DKV + kvh * HD_ + seg * 8);
            cp_async16(dst, g);
        }
        asm volatile("cp.async.commit_group;" ::: "memory");
    };

    const int ktmax = 2 * qt + 1;
    issue_kv(0, sb);
    issue_kv(1, sb + FA_STSZ);

    float m0 = -1e30f, m1 = -1e30f, l0 = 0.0f, l1 = 0.0f;
    float O[16][4];
#pragma unroll
    for (int nt = 0; nt < 16; ++nt)
#pragma unroll
        for (int q = 0; q < 4; ++q) O[nt][q] = 0.0f;

    const int r0g = qt * 128 + wid * 16 + (lane >> 2);
    const float scale = 0.08838834764831845f;

    int sidx = 0;
    for (int kt = 0; kt <= ktmax; ++kt) {
        if (kt + 1 <= ktmax) {
            asm volatile("cp.async.wait_group 1;" ::: "memory");
        } else {
            asm volatile("cp.async.wait_group 0;" ::: "memory");
        }
        __syncthreads();

        if (kt + 2 <= ktmax) {
            int pidx = sidx + 2; if (pidx >= 3) pidx -= 3;
            issue_kv(kt + 2, sb + (uint32_t)pidx * FA_STSZ);
        }

        const uint32_t stg = sb + (uint32_t)sidx * FA_STSZ;

        // ---- S = Q K^T (3 terms, term-major per k-step) ----
        float sacc[8][4];
#pragma unroll
        for (int nt = 0; nt < 8; ++nt)
#pragma unroll
            for (int q = 0; q < 4; ++q) sacc[nt][q] = 0.0f;

#pragma unroll
        for (int ks = 0; ks < 8; ++ks) {
            const uint32_t pbase = stg + (uint32_t)(ks >> 2) * 8192u;
            const uint32_t colb = (uint32_t)((ks & 3) * 32) + b_cb;
            uint32_t kh4[4][4], kl4[4][4];
#pragma unroll
            for (int p = 0; p < 4; ++p) {
                const int row = p * 16 + b_row_l;
                const uint32_t ad = pbase + (uint32_t)(row * 128)
                                  + (colb ^ (uint32_t)((row << 4) & 0x70));
                ldsm_x4(kh4[p], ad);
                ldsm_x4(kl4[p], ad + 16384u);
            }
            // term hh: 8 independent accumulators
#pragma unroll
            for (int p = 0; p < 4; ++p) {
                mma_bf16(sacc[2 * p],     qhf[ks], kh4[p]);
                mma_bf16(sacc[2 * p + 1], qhf[ks], kh4[p] + 2);
            }
            // term hl
#pragma unroll
            for (int p = 0; p < 4; ++p) {
                mma_bf16(sacc[2 * p],     qhf[ks], kl4[p]);
                mma_bf16(sacc[2 * p + 1], qhf[ks], kl4[p] + 2);
            }
            // term lh
#pragma unroll
            for (int p = 0; p < 4; ++p) {
                mma_bf16(sacc[2 * p],     qlf[ks], kh4[p]);
                mma_bf16(sacc[2 * p + 1], qlf[ks], kh4[p] + 2);
            }
        }

        // ---- scale + causal mask ----
        const int cbase = kt * 64 + (lane & 3) * 2;
        const bool need_mask = (kt >= 2 * qt);
#pragma unroll
        for (int nt = 0; nt < 8; ++nt) {
#pragma unroll
            for (int c = 0; c < 2; ++c) {
                const int col = cbase + nt * 8 + c;
                float v0 = sacc[nt][c] * scale;
                float v1 = sacc[nt][2 + c] * scale;
                if (need_mask) {
                    if (col > r0g)     v0 = -1e30f;
                    if (col > r0g + 8) v1 = -1e30f;
                }
                sacc[nt][c] = v0;
                sacc[nt][2 + c] = v1;
            }
        }

        // ---- online softmax ----
        float mx0 = -1e30f, mx1 = -1e30f;
#pragma unroll
        for (int nt = 0; nt < 8; ++nt) {
            mx0 = fmaxf(mx0, fmaxf(sacc[nt][0], sacc[nt][1]));
            mx1 = fmaxf(mx1, fmaxf(sacc[nt][2], sacc[nt][3]));
        }
        mx0 = fmaxf(mx0, __shfl_xor_sync(0xffffffffu, mx0, 1));
        mx0 = fmaxf(mx0, __shfl_xor_sync(0xffffffffu, mx0, 2));
        mx1 = fmaxf(mx1, __shfl_xor_sync(0xffffffffu, mx1, 1));
        mx1 = fmaxf(mx1, __shfl_xor_sync(0xffffffffu, mx1, 2));
        const float mn0 = fmaxf(m0, mx0), mn1 = fmaxf(m1, mx1);
        const float al0 = __expf(m0 - mn0), al1 = __expf(m1 - mn1);
        m0 = mn0; m1 = mn1;

        float rs0 = 0.0f, rs1 = 0.0f;
#pragma unroll
        for (int nt = 0; nt < 8; ++nt) {
            float p0 = __expf(sacc[nt][0] - mn0);
            float p1 = __expf(sacc[nt][1] - mn0);
            float p2 = __expf(sacc[nt][2] - mn1);
            float p3 = __expf(sacc[nt][3] - mn1);
            sacc[nt][0] = p0; sacc[nt][1] = p1; sacc[nt][2] = p2; sacc[nt][3] = p3;
            rs0 += p0 + p1; rs1 += p2 + p3;
        }
        rs0 += __shfl_xor_sync(0xffffffffu, rs0, 1);
        rs0 += __shfl_xor_sync(0xffffffffu, rs0, 2);
        rs1 += __shfl_xor_sync(0xffffffffu, rs1, 1);
        rs1 += __shfl_xor_sync(0xffffffffu, rs1, 2);
        l0 = l0 * al0 + rs0;
        l1 = l1 * al1 + rs1;

#pragma unroll
        for (int nt = 0; nt < 16; ++nt) {
            O[nt][0] *= al0; O[nt][1] *= al0;
            O[nt][2] *= al1; O[nt][3] *= al1;
        }

        // ---- P fragments (hi/lo bf16), A-operand layout ----
        uint32_t pah[4][4], pal[4][4];
#pragma unroll
        for (int kk = 0; kk < 4; ++kk) {
            const int t0 = 2 * kk, t1 = 2 * kk + 1;
            split_pack(sacc[t0][0], sacc[t0][1], pah[kk][0], pal[kk][0]);
            split_pack(sacc[t0][2], sacc[t0][3], pah[kk][1], pal[kk][1]);
            split_pack(sacc[t1][0], sacc[t1][1], pah[kk][2], pal[kk][2]);
            split_pack(sacc[t1][2], sacc[t1][3], pah[kk][3], pal[kk][3]);
        }

        // ---- O += P V (3 terms, term-major per half-panel) ----
#pragma unroll
        for (int kk = 0; kk < 4; ++kk) {
            const int rowl = kk * 16 + v_row_l;
            const uint32_t rbase = stg + 32768u + (uint32_t)(rowl * 128);
            const uint32_t rxor = (uint32_t)((rowl << 4) & 0x70);
#pragma unroll
            for (int half = 0; half < 2; ++half) {
                uint32_t vh4[4][4], vl4[4][4];
#pragma unroll
                for (int j4 = 0; j4 < 4; ++j4) {
                    const uint32_t colb = (uint32_t)(j4 * 32) + v_cb;
                    const uint32_t ad = rbase + (uint32_t)half * 8192u + (colb ^ rxor);
                    ldsm_x4_t(vh4[j4], ad);
                    ldsm_x4_t(vl4[j4], ad + 16384u);
                }
                // term hh: 8 independent accumulators
#pragma unroll
                for (int j4 = 0; j4 < 4; ++j4) {
                    const int j = half * 4 + j4;
                    mma_bf16(O[2 * j],     pah[kk], vh4[j4]);
                    mma_bf16(O[2 * j + 1], pah[kk], vh4[j4] + 2);
                }
                // term hl
#pragma unroll
                for (int j4 = 0; j4 < 4; ++j4) {
                    const int j = half * 4 + j4;
                    mma_bf16(O[2 * j],     pah[kk], vl4[j4]);
                    mma_bf16(O[2 * j + 1], pah[kk], vl4[j4] + 2);
                }
                // term lh
#pragma unroll
                for (int j4 = 0; j4 < 4; ++j4) {
                    const int j = half * 4 + j4;
                    mma_bf16(O[2 * j],     pal[kk], vh4[j4]);
                    mma_bf16(O[2 * j + 1], pal[kk], vh4[j4] + 2);
                }
            }
        }
        if (++sidx == 3) sidx = 0;
    }

    // ---- epilogue: normalize, split hi/lo, write bf16 ----
    const float inv0 = 1.0f / l0, inv1 = 1.0f / l1;
    const size_t tok0 = (size_t)(b * T_ + qt * 128 + wid * 16 + (lane >> 2));
    const int colb = h * HD_ + (lane & 3) * 2;
#pragma unroll
    for (int nt = 0; nt < 16; ++nt) {
        uint32_t hi, lo;
        const size_t idx0 = tok0 * DQ + colb + nt * 8;
        split_pack(O[nt][0] * inv0, O[nt][1] * inv0, hi, lo);
        *(uint32_t*)(Yh + idx0) = hi;
        *(uint32_t*)(Yl + idx0) = lo;
        const size_t idx1 = idx0 + (size_t)8 * DQ;
        split_pack(O[nt][2] * inv1, O[nt][3] * inv1, hi, lo);
        *(uint32_t*)(Yh + idx1) = hi;
        *(uint32_t*)(Yl + idx1) = lo;
    }
}

// ---------------------------------------------------------------------------
// Launch
// ---------------------------------------------------------------------------
extern "C" void kernel_launch(void* const* d_in, const int* in_sizes, int n_in,
                              void* d_out, int out_size)
{
    const float* x     = (const float*)d_in[0];
    const float* Wq    = (const float*)d_in[1];
    const float* Wk    = (const float*)d_in[2];
    const float* Wv    = (const float*)d_in[3];
    const float* Wproj = (const float*)d_in[4];
    const float* qgain = (const float*)d_in[5];
    float* out = (float*)d_out;

    float *Qb, *Kb;
    cudaGetSymbolAddress((void**)&Qb, g_Q);
    cudaGetSymbolAddress((void**)&Kb, g_K);
    __nv_bfloat16 *xh, *xl, *yh, *yl, *wqh, *wql, *wkh, *wkl, *wvh, *wvl, *wph, *wpl;
    __nv_bfloat16 *aqh, *aql, *akh, *akl, *avh, *avl;
    cudaGetSymbolAddress((void**)&xh,  g_xh);
    cudaGetSymbolAddress((void**)&xl,  g_xl);
    cudaGetSymbolAddress((void**)&yh,  g_yh);
    cudaGetSymbolAddress((void**)&yl,  g_yl);
    cudaGetSymbolAddress((void**)&wqh, g_wqh);
    cudaGetSymbolAddress((void**)&wql, g_wql);
    cudaGetSymbolAddress((void**)&wkh, g_wkh);
    cudaGetSymbolAddress((void**)&wkl, g_wkl);
    cudaGetSymbolAddress((void**)&wvh, g_wvh);
    cudaGetSymbolAddress((void**)&wvl, g_wvl);
    cudaGetSymbolAddress((void**)&wph, g_wph);
    cudaGetSymbolAddress((void**)&wpl, g_wpl);
    cudaGetSymbolAddress((void**)&aqh, g_aqh);
    cudaGetSymbolAddress((void**)&aql, g_aql);
    cudaGetSymbolAddress((void**)&akh, g_akh);
    cudaGetSymbolAddress((void**)&akl, g_akl);
    cudaGetSymbolAddress((void**)&avh, g_avh);
    cudaGetSymbolAddress((void**)&avl, g_avl);

    cudaFuncSetAttribute(gemm_mma3_kernel<0>,
                         cudaFuncAttributeMaxDynamicSharedMemorySize, GSMEM_SIZE);
    cudaFuncSetAttribute(gemm_mma3_kernel<1>,
                         cudaFuncAttributeMaxDynamicSharedMemorySize, GSMEM_SIZE);
    cudaFuncSetAttribute(flash_attn_mma_kernel,
                         cudaFuncAttributeMaxDynamicSharedMemorySize, FA_SMEM);

    // Convert inputs to bf16 hi/lo
    cvt_hilo_kernel<<<(MROWS * DQ / 4 + 255) / 256, 256>>>(x, xh, xl, MROWS * DQ / 4);
    cvt_hilo_kernel<<<(DQ * DQ / 4 + 255) / 256, 256>>>(Wq, wqh, wql, DQ * DQ / 4);
    cvt_hilo_kernel<<<(DKV * DQ / 4 + 255) / 256, 256>>>(Wk, wkh, wkl, DKV * DQ / 4);
    cvt_hilo_kernel<<<(DKV * DQ / 4 + 255) / 256, 256>>>(Wv, wvh, wvl, DKV * DQ / 4);
    cvt_hilo_kernel<<<(DQ * DQ / 4 + 255) / 256, 256>>>(Wproj, wph, wpl, DQ * DQ / 4);

    // QKV projections on HMMA tensor cores (3xBF16)
    gemm_mma3_kernel<0><<<dim3(DQ / 128,  MROWS / 128), 256, GSMEM_SIZE>>>(
        xh, xl, wqh, wql, Qb, nullptr, nullptr, MROWS, DQ, DQ);
    gemm_mma3_kernel<0><<<dim3(DKV / 128, MROWS / 128), 256, GSMEM_SIZE>>>(
        xh, xl, wkh, wkl, Kb, nullptr, nullptr, MROWS, DKV, DQ);
    // V projection writes bf16 hi/lo directly (no fp32 round-trip)
    gemm_mma3_kernel<1><<<dim3(DKV / 128, MROWS / 128), 256, GSMEM_SIZE>>>(
        xh, xl, wvh, wvl, nullptr, avh, avl, MROWS, DKV, DQ);

    // RMSNorm + RoPE (+gain on Q) -> bf16 hi/lo
    rms_rope_split_kernel<<<(MROWS * NH) / 8, 256>>>(Qb, NH, qgain, aqh, aql);
    rms_rope_split_kernel<<<(MROWS * NKV) / 8, 256>>>(Kb, NKV, nullptr, akh, akl);

    // Flash attention (HMMA 3xBF16) -> yh/yl bf16
    flash_attn_mma_kernel<<<dim3(T_ / 128, NH, B_), 256, FA_SMEM>>>(
        aqh, aql, akh, akl, avh, avl, yh, yl);

    // Output projection
    gemm_mma3_kernel<0><<<dim3(DQ / 128, MROWS / 128), 256, GSMEM_SIZE>>>(
        yh, yl, wph, wpl, out, nullptr, nullptr, MROWS, DQ, DQ);
}

// round 15
// speedup vs baseline: 1.0134x; 1.0019x over previous
#include <cuda_runtime.h>
#include <cuda_bf16.h>
#include <math.h>
#include <cstdint>

// Problem constants
#define B_   4
#define T_   2048
#define NH   16
#define NKV  4
#define HD_  128
#define DQ   (NH * HD_)    // 2048
#define DKV  (NKV * HD_)   // 512
#define MROWS (B_ * T_)    // 8192

// ---------------------------------------------------------------------------
// Scratch (device globals; allocations banned)
// ---------------------------------------------------------------------------
__device__ float g_Q[(size_t)MROWS * DQ];    // fp32 Q projection
__device__ float g_K[(size_t)MROWS * DKV];   // fp32 K projection

__device__ __nv_bfloat16 g_xh[(size_t)MROWS * DQ];
__device__ __nv_bfloat16 g_xl[(size_t)MROWS * DQ];
__device__ __nv_bfloat16 g_yh[(size_t)MROWS * DQ];
__device__ __nv_bfloat16 g_yl[(size_t)MROWS * DQ];
__device__ __nv_bfloat16 g_wqh[(size_t)DQ * DQ];
__device__ __nv_bfloat16 g_wql[(size_t)DQ * DQ];
__device__ __nv_bfloat16 g_wkh[(size_t)DKV * DQ];
__device__ __nv_bfloat16 g_wkl[(size_t)DKV * DQ];
__device__ __nv_bfloat16 g_wvh[(size_t)DKV * DQ];
__device__ __nv_bfloat16 g_wvl[(size_t)DKV * DQ];
__device__ __nv_bfloat16 g_wph[(size_t)DQ * DQ];
__device__ __nv_bfloat16 g_wpl[(size_t)DQ * DQ];

// attention operands (hi/lo bf16)
__device__ __nv_bfloat16 g_aqh[(size_t)MROWS * DQ];
__device__ __nv_bfloat16 g_aql[(size_t)MROWS * DQ];
__device__ __nv_bfloat16 g_akh[(size_t)MROWS * DKV];
__device__ __nv_bfloat16 g_akl[(size_t)MROWS * DKV];
__device__ __nv_bfloat16 g_avh[(size_t)MROWS * DKV];
__device__ __nv_bfloat16 g_avl[(size_t)MROWS * DKV];

// ---------------------------------------------------------------------------
// Warp-level MMA helpers
// ---------------------------------------------------------------------------
__device__ __forceinline__ uint32_t smem_to_u32(const void* smem_ptr) {
    uint32_t addr;
    asm("{ .reg .u64 tmp; cvta.to.shared.u64 tmp, %1; cvt.u32.u64 %0, tmp; }"
        : "=r"(addr) : "l"(smem_ptr));
    return addr;
}

__device__ __forceinline__ void ldsm_x4(uint32_t* r, uint32_t addr) {
    asm volatile("ldmatrix.sync.aligned.m8n8.x4.shared.b16 {%0,%1,%2,%3}, [%4];"
        : "=r"(r[0]), "=r"(r[1]), "=r"(r[2]), "=r"(r[3]) : "r"(addr));
}

__device__ __forceinline__ void ldsm_x4_t(uint32_t* r, uint32_t addr) {
    asm volatile("ldmatrix.sync.aligned.m8n8.x4.trans.shared.b16 {%0,%1,%2,%3}, [%4];"
        : "=r"(r[0]), "=r"(r[1]), "=r"(r[2]), "=r"(r[3]) : "r"(addr));
}

// NOTE: not volatile — register-only op, deps carried by constraints, so
// ptxas is free to software-pipeline/interleave independent MMAs.
__device__ __forceinline__ void mma_bf16(float* d, const uint32_t* a, const uint32_t* b) {
    asm("mma.sync.aligned.m16n8k16.row.col.f32.bf16.bf16.f32 "
        "{%0,%1,%2,%3}, {%4,%5,%6,%7}, {%8,%9}, {%0,%1,%2,%3};"
        : "+f"(d[0]), "+f"(d[1]), "+f"(d[2]), "+f"(d[3])
        : "r"(a[0]), "r"(a[1]), "r"(a[2]), "r"(a[3]), "r"(b[0]), "r"(b[1]));
}

__device__ __forceinline__ void cp_async16(uint32_t dst, const void* src) {
    asm volatile("cp.async.cg.shared.global [%0], [%1], 16;"
                 :: "r"(dst), "l"(src) : "memory");
}

// split x,y into packed bf16 hi + lo pairs
__device__ __forceinline__ void split_pack(float x, float y, uint32_t& hi, uint32_t& lo) {
    __nv_bfloat16 hx = __float2bfloat16(x);
    __nv_bfloat16 hy = __float2bfloat16(y);
    __nv_bfloat16 lx = __float2bfloat16(x - __bfloat162float(hx));
    __nv_bfloat16 ly = __float2bfloat16(y - __bfloat162float(hy));
    __nv_bfloat162 h2 = __halves2bfloat162(hx, hy);
    __nv_bfloat162 l2 = __halves2bfloat162(lx, ly);
    hi = *(uint32_t*)&h2; lo = *(uint32_t*)&l2;
}

// ---------------------------------------------------------------------------
// fp32 -> bf16 hi/lo split
// ---------------------------------------------------------------------------
__global__ void __launch_bounds__(256) cvt_hilo_kernel(
    const float* __restrict__ x,
    __nv_bfloat16* __restrict__ hi, __nv_bfloat16* __restrict__ lo, int n4)
{
    int i = blockIdx.x * 256 + threadIdx.x;
    if (i >= n4) return;
    float4 v = ((const float4*)x)[i];
    __nv_bfloat16 h[4], l[4];
    h[0] = __float2bfloat16(v.x); l[0] = __float2bfloat16(v.x - __bfloat162float(h[0]));
    h[1] = __float2bfloat16(v.y); l[1] = __float2bfloat16(v.y - __bfloat162float(h[1]));
    h[2] = __float2bfloat16(v.z); l[2] = __float2bfloat16(v.z - __bfloat162float(h[2]));
    h[3] = __float2bfloat16(v.w); l[3] = __float2bfloat16(v.w - __bfloat162float(h[3]));
    *(uint2*)(hi + 4 * (size_t)i) = *(uint2*)h;
    *(uint2*)(lo + 4 * (size_t)i) = *(uint2*)l;
}

// ---------------------------------------------------------------------------
// HMMA 3xBF16 GEMM (NT): C[M,N] = A[M,K] * B[N,K]^T, fp32 accumulate.
// BM=128, BN=128, BK=64. 8 warps (2x4). 3-stage cp.async pipeline.
// MMA issue is TERM-MAJOR: all 16 (mi,ni) accumulators per term, so the
// same-accumulator reuse distance is 16 MMAs (no RAW stalls).
// ---------------------------------------------------------------------------
#define GTILE_BYTES  16384
#define GSTAGE_BYTES (4 * GTILE_BYTES)      // 65536
#define GSMEM_SIZE   (3 * GSTAGE_BYTES)     // 196608

template<int OUT_MODE>
__global__ void __launch_bounds__(256, 1)
gemm_mma3_kernel(const __nv_bfloat16* __restrict__ Ah,
                 const __nv_bfloat16* __restrict__ Al,
                 const __nv_bfloat16* __restrict__ Bh,
                 const __nv_bfloat16* __restrict__ Bl,
                 float* __restrict__ C,
                 __nv_bfloat16* __restrict__ Ch, __nv_bfloat16* __restrict__ Cl,
                 int M, int N, int Kd)
{
    extern __shared__ char smem[];
    const uint32_t sbase = smem_to_u32(smem);
    const int tid = threadIdx.x;
    const int wid = tid >> 5, lane = tid & 31;
    const int wm = wid >> 2, wn = wid & 3;
    const int m0 = blockIdx.y * 128, n0 = blockIdx.x * 128;
    const int nchunk = Kd >> 6;

    const char* gsrc[16];
    uint32_t    soff[16];
#pragma unroll
    for (int i = 0; i < 16; ++i) {
        int gid  = tid + i * 256;
        int tile = gid >> 10;
        int rem  = gid & 1023;
        int row  = rem >> 3;
        int seg  = rem & 7;
        uint32_t off = (uint32_t)(row * 128 + seg * 16);
        soff[i] = (uint32_t)tile * GTILE_BYTES + (off ^ ((off >> 3) & 0x70));
        const char* base =
            (tile == 0) ? (const char*)Ah :
            (tile == 1) ? (const char*)Al :
            (tile == 2) ? (const char*)Bh : (const char*)Bl;
        int r0 = (tile < 2) ? m0 : n0;
        gsrc[i] = base + ((size_t)(r0 + row) * Kd + (size_t)seg * 8) * 2;
    }

    // Prologue: chunks 0 and 1 into stages 0, 1
#pragma unroll
    for (int i = 0; i < 16; ++i) cp_async16(sbase + soff[i], gsrc[i]);
    asm volatile("cp.async.commit_group;" ::: "memory");
#pragma unroll
    for (int i = 0; i < 16; ++i)
        cp_async16(sbase + GSTAGE_BYTES + soff[i], gsrc[i] + 128);
    asm volatile("cp.async.commit_group;" ::: "memory");

    const int a_row_l = (lane & 15);
    const uint32_t a_cb = (uint32_t)((lane >> 4) * 16);
    const int b_row_l = ((lane >> 4) << 3) + (lane & 7);
    const uint32_t b_cb = (uint32_t)(((lane >> 3) & 1) * 16);

    uint32_t aRow[4], aXor[4];
#pragma unroll
    for (int mi = 0; mi < 4; ++mi) {
        int r = wm * 64 + mi * 16 + a_row_l;
        aRow[mi] = (uint32_t)(r * 128);
        aXor[mi] = (uint32_t)((r << 4) & 0x70);
    }
    uint32_t bRow[2], bXor[2];
#pragma unroll
    for (int p = 0; p < 2; ++p) {
        int r = wn * 32 + p * 16 + b_row_l;
        bRow[p] = (uint32_t)(r * 128);
        bXor[p] = (uint32_t)((r << 4) & 0x70);
    }

    float acc[4][4][4];
#pragma unroll
    for (int mi = 0; mi < 4; ++mi)
#pragma unroll
        for (int ni = 0; ni < 4; ++ni)
#pragma unroll
            for (int q = 0; q < 4; ++q) acc[mi][ni][q] = 0.0f;

    int sidx = 0;                 // stage of chunk c
    for (int c = 0; c < nchunk; ++c) {
        if (c + 1 < nchunk) {
            asm volatile("cp.async.wait_group 1;" ::: "memory");
        } else {
            asm volatile("cp.async.wait_group 0;" ::: "memory");
        }
        __syncthreads();

        if (c + 2 < nchunk) {
            int pidx = sidx + 2; if (pidx >= 3) pidx -= 3;
            const uint32_t stn = sbase + (uint32_t)pidx * GSTAGE_BYTES;
            const size_t kb = (size_t)(c + 2) * 128;
#pragma unroll
            for (int i = 0; i < 16; ++i) cp_async16(stn + soff[i], gsrc[i] + kb);
            asm volatile("cp.async.commit_group;" ::: "memory");
        }

        const uint32_t st = sbase + (uint32_t)sidx * GSTAGE_BYTES;
#pragma unroll
        for (int ks = 0; ks < 4; ++ks) {
            const uint32_t kcb = (uint32_t)(ks * 32);
            uint32_t ah[4][4], al[4][4], bh[2][4], bl[2][4];
#pragma unroll
            for (int mi = 0; mi < 4; ++mi) {
                uint32_t col = (kcb + a_cb);
                uint32_t addr = st + aRow[mi] + (col ^ aXor[mi]);
                ldsm_x4(ah[mi], addr);
                ldsm_x4(al[mi], addr + GTILE_BYTES);
            }
#pragma unroll
            for (int p = 0; p < 2; ++p) {
                uint32_t col = (kcb + b_cb);
                uint32_t addr = st + 2 * GTILE_BYTES + bRow[p] + (col ^ bXor[p]);
                ldsm_x4(bh[p], addr);
                ldsm_x4(bl[p], addr + GTILE_BYTES);
            }
            // term-major: 16 independent accumulators between reuses
#pragma unroll
            for (int mi = 0; mi < 4; ++mi)
#pragma unroll
                for (int ni = 0; ni < 4; ++ni)
                    mma_bf16(acc[mi][ni], ah[mi], &bh[ni >> 1][(ni & 1) * 2]);
#pragma unroll
            for (int mi = 0; mi < 4; ++mi)
#pragma unroll
                for (int ni = 0; ni < 4; ++ni)
                    mma_bf16(acc[mi][ni], ah[mi], &bl[ni >> 1][(ni & 1) * 2]);
#pragma unroll
            for (int mi = 0; mi < 4; ++mi)
#pragma unroll
                for (int ni = 0; ni < 4; ++ni)
                    mma_bf16(acc[mi][ni], al[mi], &bh[ni >> 1][(ni & 1) * 2]);
        }
        if (++sidx == 3) sidx = 0;
    }

#pragma unroll
    for (int mi = 0; mi < 4; ++mi) {
        const int gm = m0 + wm * 64 + mi * 16 + (lane >> 2);
#pragma unroll
        for (int ni = 0; ni < 4; ++ni) {
            const int gn = n0 + wn * 32 + ni * 8 + (lane & 3) * 2;
            if (OUT_MODE == 0) {
                float2 v0 = make_float2(acc[mi][ni][0], acc[mi][ni][1]);
                float2 v1 = make_float2(acc[mi][ni][2], acc[mi][ni][3]);
                *(float2*)(C + (size_t)gm * N + gn) = v0;
                *(float2*)(C + (size_t)(gm + 8) * N + gn) = v1;
            } else {
                uint32_t hi, lo;
                split_pack(acc[mi][ni][0], acc[mi][ni][1], hi, lo);
                *(uint32_t*)(Ch + (size_t)gm * N + gn) = hi;
                *(uint32_t*)(Cl + (size_t)gm * N + gn) = lo;
                split_pack(acc[mi][ni][2], acc[mi][ni][3], hi, lo);
                *(uint32_t*)(Ch + (size_t)(gm + 8) * N + gn) = hi;
                *(uint32_t*)(Cl + (size_t)(gm + 8) * N + gn) = lo;
            }
        }
    }
}

// ---------------------------------------------------------------------------
// Fused QK RMSNorm + RoPE (+gain) -> bf16 hi/lo outputs.
// ---------------------------------------------------------------------------
__global__ void __launch_bounds__(256) rms_rope_split_kernel(
    const float* __restrict__ X, int nheads, const float* __restrict__ gain,
    __nv_bfloat16* __restrict__ H, __nv_bfloat16* __restrict__ L)
{
    const int wid = threadIdx.x >> 5, lane = threadIdx.x & 31;
    const long long gid = (long long)blockIdx.x * 8 + wid;
    const int h = (int)(gid % nheads);
    const long long bt = gid / nheads;
    const int t = (int)(bt % T_);

    const long long base = bt * (long long)(nheads * HD_) + (long long)h * HD_;
    const float* p = X + base;
    float x0 = p[lane], x1 = p[lane + 32], x2 = p[lane + 64], x3 = p[lane + 96];

    float ss = x0 * x0 + x1 * x1 + x2 * x2 + x3 * x3;
#pragma unroll
    for (int o = 16; o; o >>= 1) ss += __shfl_xor_sync(0xffffffffu, ss, o);
    const float r = rsqrtf(ss * (1.0f / 128.0f) + 1.1920928955078125e-07f);
    x0 *= r; x1 *= r; x2 *= r; x3 *= r;

    const float Lc = 13.287712379549449f / 64.0f;
    const float tf = (float)t;
    const float a0 = tf * exp2f(-(float)lane * Lc);
    const float a1 = tf * exp2f(-(float)(lane + 32) * Lc);
    const float c0 = cosf(a0), s0 = sinf(a0);
    const float c1 = cosf(a1), s1 = sinf(a1);
    const float g = gain ? gain[h] : 1.0f;

    float y0 = (x0 * c0 - x2 * s0) * g;
    float y2 = (x2 * c0 + x0 * s0) * g;
    float y1 = (x1 * c1 - x3 * s1) * g;
    float y3 = (x3 * c1 + x1 * s1) * g;

    __nv_bfloat16 h0 = __float2bfloat16(y0), h1 = __float2bfloat16(y1);
    __nv_bfloat16 h2 = __float2bfloat16(y2), h3 = __float2bfloat16(y3);
    H[base + lane]      = h0;  L[base + lane]      = __float2bfloat16(y0 - __bfloat162float(h0));
    H[base + lane + 32] = h1;  L[base + lane + 32] = __float2bfloat16(y1 - __bfloat162float(h1));
    H[base + lane + 64] = h2;  L[base + lane + 64] = __float2bfloat16(y2 - __bfloat162float(h2));
    H[base + lane + 96] = h3;  L[base + lane + 96] = __float2bfloat16(y3 - __bfloat162float(h3));
}

// ---------------------------------------------------------------------------
// Flash attention, HMMA 3xBF16, causal, GQA group=4.
// Br=128, Bc=64, 8 warps. 3-stage KV cp.async pipeline; Q in registers.
// MMA issue is TERM-MAJOR inside each k-step / kk-step so the same-
// accumulator reuse distance is 8 MMAs.
// ---------------------------------------------------------------------------
#define FA_STSZ 65536u
#define FA_SMEM (3 * 65536)   // 196608

__global__ void __launch_bounds__(256, 1) flash_attn_mma_kernel(
    const __nv_bfloat16* __restrict__ Qh, const __nv_bfloat16* __restrict__ Ql,
    const __nv_bfloat16* __restrict__ Kh, const __nv_bfloat16* __restrict__ Kl,
    const __nv_bfloat16* __restrict__ Vh, const __nv_bfloat16* __restrict__ Vl,
    __nv_bfloat16* __restrict__ Yh, __nv_bfloat16* __restrict__ Yl)
{
    extern __shared__ char smem[];
    const uint32_t sb = smem_to_u32(smem);
    const int qt = blockIdx.x, h = blockIdx.y, b = blockIdx.z;
    const int kvh = h >> 2;
    const int tid = threadIdx.x, wid = tid >> 5, lane = tid & 31;

    // ---- Q tile via stage 0 (Qh at +0, Ql at +32768), 16 x 16B per thread ----
#pragma unroll
    for (int i = 0; i < 16; ++i) {
        int gid = tid + i * 256;
        int tensor = gid >> 11;
        int rem = gid & 2047;
        int row = rem >> 4;
        int seg = rem & 15;
        int panel = seg >> 3, segp = seg & 7;
        uint32_t off = (uint32_t)(row * 128 + segp * 16);
        uint32_t dst = sb + (uint32_t)tensor * 32768u + (uint32_t)panel * 16384u
                     + (off ^ ((off >> 3) & 0x70));
        const __nv_bfloat16* g = (tensor ? Ql : Qh)
            + ((size_t)(b * T_ + qt * 128 + row) * DQ + h * HD_ + seg * 8);
        cp_async16(dst, g);
    }
    asm volatile("cp.async.commit_group;" ::: "memory");
    asm volatile("cp.async.wait_group 0;" ::: "memory");
    __syncthreads();

    // lane addressing constants
    const int a_row_l = lane & 15;
    const uint32_t a_cb = (uint32_t)((lane >> 4) * 16);
    const int b_row_l = ((lane >> 4) << 3) + (lane & 7);
    const uint32_t b_cb = (uint32_t)(((lane >> 3) & 1) * 16);
    const int v_row_l = lane & 15;
    const uint32_t v_cb = (uint32_t)((lane >> 4) * 16);

    // ---- extract Q fragments (A operand) for 8 k-steps, hi+lo ----
    uint32_t qhf[8][4], qlf[8][4];
    {
        const int arow = wid * 16 + a_row_l;
        const uint32_t axor = (uint32_t)((arow << 4) & 0x70);
        const uint32_t abase = sb + (uint32_t)(arow * 128);
#pragma unroll
        for (int ks = 0; ks < 8; ++ks) {
            uint32_t colb = (uint32_t)((ks & 3) * 32) + a_cb;
            uint32_t ad = abase + (uint32_t)(ks >> 2) * 16384u + (colb ^ axor);
            ldsm_x4(qhf[ks], ad);
            ldsm_x4(qlf[ks], ad + 32768u);
        }
    }
    __syncthreads();   // everyone done reading Q from stage 0

    // ---- KV stage loader ----
    auto issue_kv = [&](int kt, uint32_t stagebase) {
#pragma unroll
        for (int i = 0; i < 16; ++i) {
            int gid = tid + i * 256;
            int tensor = gid >> 10;
            int rem = gid & 1023;
            int row = rem >> 4;
            int seg = rem & 15;
            int panel = seg >> 3, segp = seg & 7;
            uint32_t off = (uint32_t)(row * 128 + segp * 16);
            uint32_t dst = stagebase + (uint32_t)tensor * 16384u + (uint32_t)panel * 8192u
                         + (off ^ ((off >> 3) & 0x70));
            const __nv_bfloat16* base =
                (tensor == 0) ? Kh : (tensor == 1) ? Kl : (tensor == 2) ? Vh : Vl;
            const __nv_bfloat16* g = base
                + ((size_t)(b * T_ + kt * 64 + row) * DKV + kvh * HD_ + seg * 8);
            cp_async16(dst, g);
        }
        asm volatile("cp.async.commit_group;" ::: "memory");
    };

    const int ktmax = 2 * qt + 1;
    issue_kv(0, sb);
    issue_kv(1, sb + FA_STSZ);

    float m0 = -1e30f, m1 = -1e30f, l0 = 0.0f, l1 = 0.0f;
    float O[16][4];
#pragma unroll
    for (int nt = 0; nt < 16; ++nt)
#pragma unroll
        for (int q = 0; q < 4; ++q) O[nt][q] = 0.0f;

    const int r0g = qt * 128 + wid * 16 + (lane >> 2);
    const float scale = 0.08838834764831845f;

    int sidx = 0;
    for (int kt = 0; kt <= ktmax; ++kt) {
        if (kt + 1 <= ktmax) {
            asm volatile("cp.async.wait_group 1;" ::: "memory");
        } else {
            asm volatile("cp.async.wait_group 0;" ::: "memory");
        }
        __syncthreads();

        if (kt + 2 <= ktmax) {
            int pidx = sidx + 2; if (pidx >= 3) pidx -= 3;
            issue_kv(kt + 2, sb + (uint32_t)pidx * FA_STSZ);
        }

        const uint32_t stg = sb + (uint32_t)sidx * FA_STSZ;

        // ---- S = Q K^T (3 terms, term-major per k-step) ----
        float sacc[8][4];
#pragma unroll
        for (int nt = 0; nt < 8; ++nt)
#pragma unroll
            for (int q = 0; q < 4; ++q) sacc[nt][q] = 0.0f;

#pragma unroll
        for (int ks = 0; ks < 8; ++ks) {
            const uint32_t pbase = stg + (uint32_t)(ks >> 2) * 8192u;
            const uint32_t colb = (uint32_t)((ks & 3) * 32) + b_cb;
            uint32_t kh4[4][4], kl4[4][4];
#pragma unroll
            for (int p = 0; p < 4; ++p) {
                const int row = p * 16 + b_row_l;
                const uint32_t ad = pbase + (uint32_t)(row * 128)
                                  + (colb ^ (uint32_t)((row << 4) & 0x70));
                ldsm_x4(kh4[p], ad);
                ldsm_x4(kl4[p], ad + 16384u);
            }
            // term hh: 8 independent accumulators
#pragma unroll
            for (int p = 0; p < 4; ++p) {
                mma_bf16(sacc[2 * p],     qhf[ks], kh4[p]);
                mma_bf16(sacc[2 * p + 1], qhf[ks], kh4[p] + 2);
            }
            // term hl
#pragma unroll
            for (int p = 0; p < 4; ++p) {
                mma_bf16(sacc[2 * p],     qhf[ks], kl4[p]);
                mma_bf16(sacc[2 * p + 1], qhf[ks], kl4[p] + 2);
            }
            // term lh
#pragma unroll
            for (int p = 0; p < 4; ++p) {
                mma_bf16(sacc[2 * p],     qlf[ks], kh4[p]);
                mma_bf16(sacc[2 * p + 1], qlf[ks], kh4[p] + 2);
            }
        }

        // ---- scale + causal mask ----
        const int cbase = kt * 64 + (lane & 3) * 2;
        const bool need_mask = (kt >= 2 * qt);
#pragma unroll
        for (int nt = 0; nt < 8; ++nt) {
#pragma unroll
            for (int c = 0; c < 2; ++c) {
                const int col = cbase + nt * 8 + c;
                float v0 = sacc[nt][c] * scale;
                float v1 = sacc[nt][2 + c] * scale;
                if (need_mask) {
                    if (col > r0g)     v0 = -1e30f;
                    if (col > r0g + 8) v1 = -1e30f;
                }
                sacc[nt][c] = v0;
                sacc[nt][2 + c] = v1;
            }
        }

        // ---- online softmax ----
        float mx0 = -1e30f, mx1 = -1e30f;
#pragma unroll
        for (int nt = 0; nt < 8; ++nt) {
            mx0 = fmaxf(mx0, fmaxf(sacc[nt][0], sacc[nt][1]));
            mx1 = fmaxf(mx1, fmaxf(sacc[nt][2], sacc[nt][3]));
        }
        mx0 = fmaxf(mx0, __shfl_xor_sync(0xffffffffu, mx0, 1));
        mx0 = fmaxf(mx0, __shfl_xor_sync(0xffffffffu, mx0, 2));
        mx1 = fmaxf(mx1, __shfl_xor_sync(0xffffffffu, mx1, 1));
        mx1 = fmaxf(mx1, __shfl_xor_sync(0xffffffffu, mx1, 2));
        const float mn0 = fmaxf(m0, mx0), mn1 = fmaxf(m1, mx1);
        const float al0 = __expf(m0 - mn0), al1 = __expf(m1 - mn1);
        m0 = mn0; m1 = mn1;

        float rs0 = 0.0f, rs1 = 0.0f;
#pragma unroll
        for (int nt = 0; nt < 8; ++nt) {
            float p0 = __expf(sacc[nt][0] - mn0);
            float p1 = __expf(sacc[nt][1] - mn0);
            float p2 = __expf(sacc[nt][2] - mn1);
            float p3 = __expf(sacc[nt][3] - mn1);
            sacc[nt][0] = p0; sacc[nt][1] = p1; sacc[nt][2] = p2; sacc[nt][3] = p3;
            rs0 += p0 + p1; rs1 += p2 + p3;
        }
        rs0 += __shfl_xor_sync(0xffffffffu, rs0, 1);
        rs0 += __shfl_xor_sync(0xffffffffu, rs0, 2);
        rs1 += __shfl_xor_sync(0xffffffffu, rs1, 1);
        rs1 += __shfl_xor_sync(0xffffffffu, rs1, 2);
        l0 = l0 * al0 + rs0;
        l1 = l1 * al1 + rs1;

#pragma unroll
        for (int nt = 0; nt < 16; ++nt) {
            O[nt][0] *= al0; O[nt][1] *= al0;
            O[nt][2] *= al1; O[nt][3] *= al1;
        }

        // ---- P fragments (hi/lo bf16), A-operand layout ----
        uint32_t pah[4][4], pal[4][4];
#pragma unroll
        for (int kk = 0; kk < 4; ++kk) {
            const int t0 = 2 * kk, t1 = 2 * kk + 1;
            split_pack(sacc[t0][0], sacc[t0][1], pah[kk][0], pal[kk][0]);
            split_pack(sacc[t0][2], sacc[t0][3], pah[kk][1], pal[kk][1]);
            split_pack(sacc[t1][0], sacc[t1][1], pah[kk][2], pal[kk][2]);
            split_pack(sacc[t1][2], sacc[t1][3], pah[kk][3], pal[kk][3]);
        }

        // ---- O += P V (3 terms, term-major per half-panel) ----
#pragma unroll
        for (int kk = 0; kk < 4; ++kk) {
            const int rowl = kk * 16 + v_row_l;
            const uint32_t rbase = stg + 32768u + (uint32_t)(rowl * 128);
            const uint32_t rxor = (uint32_t)((rowl << 4) & 0x70);
#pragma unroll
            for (int half = 0; half < 2; ++half) {
                uint32_t vh4[4][4], vl4[4][4];
#pragma unroll
                for (int j4 = 0; j4 < 4; ++j4) {
                    const uint32_t colb = (uint32_t)(j4 * 32) + v_cb;
                    const uint32_t ad = rbase + (uint32_t)half * 8192u + (colb ^ rxor);
                    ldsm_x4_t(vh4[j4], ad);
                    ldsm_x4_t(vl4[j4], ad + 16384u);
                }
                // term hh: 8 independent accumulators
#pragma unroll
                for (int j4 = 0; j4 < 4; ++j4) {
                    const int j = half * 4 + j4;
                    mma_bf16(O[2 * j],     pah[kk], vh4[j4]);
                    mma_bf16(O[2 * j + 1], pah[kk], vh4[j4] + 2);
                }
                // term hl
#pragma unroll
                for (int j4 = 0; j4 < 4; ++j4) {
                    const int j = half * 4 + j4;
                    mma_bf16(O[2 * j],     pah[kk], vl4[j4]);
                    mma_bf16(O[2 * j + 1], pah[kk], vl4[j4] + 2);
                }
                // term lh
#pragma unroll
                for (int j4 = 0; j4 < 4; ++j4) {
                    const int j = half * 4 + j4;
                    mma_bf16(O[2 * j],     pal[kk], vh4[j4]);
                    mma_bf16(O[2 * j + 1], pal[kk], vh4[j4] + 2);
                }
            }
        }
        if (++sidx == 3) sidx = 0;
    }

    // ---- epilogue: normalize, split hi/lo, write bf16 ----
    const float inv0 = 1.0f / l0, inv1 = 1.0f / l1;
    const size_t tok0 = (size_t)(b * T_ + qt * 128 + wid * 16 + (lane >> 2));
    const int colb = h * HD_ + (lane & 3) * 2;
#pragma unroll
    for (int nt = 0; nt < 16; ++nt) {
        uint32_t hi, lo;
        const size_t idx0 = tok0 * DQ + colb + nt * 8;
        split_pack(O[nt][0] * inv0, O[nt][1] * inv0, hi, lo);
        *(uint32_t*)(Yh + idx0) = hi;
        *(uint32_t*)(Yl + idx0) = lo;
        const size_t idx1 = idx0 + (size_t)8 * DQ;
        split_pack(O[nt][2] * inv1, O[nt][3] * inv1, hi, lo);
        *(uint32_t*)(Yh + idx1) = hi;
        *(uint32_t*)(Yl + idx1) = lo;
    }
}

// ---------------------------------------------------------------------------
// Launch
// ---------------------------------------------------------------------------
extern "C" void kernel_launch(void* const* d_in, const int* in_sizes, int n_in,
                              void* d_out, int out_size)
{
    const float* x     = (const float*)d_in[0];
    const float* Wq    = (const float*)d_in[1];
    const float* Wk    = (const float*)d_in[2];
    const float* Wv    = (const float*)d_in[3];
    const float* Wproj = (const float*)d_in[4];
    const float* qgain = (const float*)d_in[5];
    float* out = (float*)d_out;

    float *Qb, *Kb;
    cudaGetSymbolAddress((void**)&Qb, g_Q);
    cudaGetSymbolAddress((void**)&Kb, g_K);
    __nv_bfloat16 *xh, *xl, *yh, *yl, *wqh, *wql, *wkh, *wkl, *wvh, *wvl, *wph, *wpl;
    __nv_bfloat16 *aqh, *aql, *akh, *akl, *avh, *avl;
    cudaGetSymbolAddress((void**)&xh,  g_xh);
    cudaGetSymbolAddress((void**)&xl,  g_xl);
    cudaGetSymbolAddress((void**)&yh,  g_yh);
    cudaGetSymbolAddress((void**)&yl,  g_yl);
    cudaGetSymbolAddress((void**)&wqh, g_wqh);
    cudaGetSymbolAddress((void**)&wql, g_wql);
    cudaGetSymbolAddress((void**)&wkh, g_wkh);
    cudaGetSymbolAddress((void**)&wkl, g_wkl);
    cudaGetSymbolAddress((void**)&wvh, g_wvh);
    cudaGetSymbolAddress((void**)&wvl, g_wvl);
    cudaGetSymbolAddress((void**)&wph, g_wph);
    cudaGetSymbolAddress((void**)&wpl, g_wpl);
    cudaGetSymbolAddress((void**)&aqh, g_aqh);
    cudaGetSymbolAddress((void**)&aql, g_aql);
    cudaGetSymbolAddress((void**)&akh, g_akh);
    cudaGetSymbolAddress((void**)&akl, g_akl);
    cudaGetSymbolAddress((void**)&avh, g_avh);
    cudaGetSymbolAddress((void**)&avl, g_avl);

    cudaFuncSetAttribute(gemm_mma3_kernel<0>,
                         cudaFuncAttributeMaxDynamicSharedMemorySize, GSMEM_SIZE);
    cudaFuncSetAttribute(gemm_mma3_kernel<1>,
                         cudaFuncAttributeMaxDynamicSharedMemorySize, GSMEM_SIZE);
    cudaFuncSetAttribute(flash_attn_mma_kernel,
                         cudaFuncAttributeMaxDynamicSharedMemorySize, FA_SMEM);

    // Convert inputs to bf16 hi/lo
    cvt_hilo_kernel<<<(MROWS * DQ / 4 + 255) / 256, 256>>>(x, xh, xl, MROWS * DQ / 4);
    cvt_hilo_kernel<<<(DQ * DQ / 4 + 255) / 256, 256>>>(Wq, wqh, wql, DQ * DQ / 4);
    cvt_hilo_kernel<<<(DKV * DQ / 4 + 255) / 256, 256>>>(Wk, wkh, wkl, DKV * DQ / 4);
    cvt_hilo_kernel<<<(DKV * DQ / 4 + 255) / 256, 256>>>(Wv, wvh, wvl, DKV * DQ / 4);
    cvt_hilo_kernel<<<(DQ * DQ / 4 + 255) / 256, 256>>>(Wproj, wph, wpl, DQ * DQ / 4);

    // QKV projections on HMMA tensor cores (3xBF16)
    gemm_mma3_kernel<0><<<dim3(DQ / 128,  MROWS / 128), 256, GSMEM_SIZE>>>(
        xh, xl, wqh, wql, Qb, nullptr, nullptr, MROWS, DQ, DQ);
    gemm_mma3_kernel<0><<<dim3(DKV / 128, MROWS / 128), 256, GSMEM_SIZE>>>(
        xh, xl, wkh, wkl, Kb, nullptr, nullptr, MROWS, DKV, DQ);
    // V projection writes bf16 hi/lo directly (no fp32 round-trip)
    gemm_mma3_kernel<1><<<dim3(DKV / 128, MROWS / 128), 256, GSMEM_SIZE>>>(
        xh, xl, wvh, wvl, nullptr, avh, avl, MROWS, DKV, DQ);

    // RMSNorm + RoPE (+gain on Q) -> bf16 hi/lo
    rms_rope_split_kernel<<<(MROWS * NH) / 8, 256>>>(Qb, NH, qgain, aqh, aql);
    rms_rope_split_kernel<<<(MROWS * NKV) / 8, 256>>>(Kb, NKV, nullptr, akh, akl);

    // Flash attention (HMMA 3xBF16) -> yh/yl bf16
    flash_attn_mma_kernel<<<dim3(T_ / 128, NH, B_), 256, FA_SMEM>>>(
        aqh, aql, akh, akl, avh, avl, yh, yl);

    // Output projection
    gemm_mma3_kernel<0><<<dim3(DQ / 128, MROWS / 128), 256, GSMEM_SIZE>>>(
        yh, yl, wph, wpl, out, nullptr, nullptr, MROWS, DQ, DQ);
}